// round 1
// baseline (speedup 1.0000x reference)
#include <cuda_runtime.h>
#include <math.h>
#include <stdint.h>

#define H 256
#define BM 128
#define BN 128
#define BK 16
#define NTHREADS 256

#define N_MAX 10240
#define E_MAX 163840

// ---------------- scratch (device globals; no allocation allowed) ----------
__device__ float    g_P1[N_MAX * H];      // h @ a_w1[0:256]
__device__ float    g_P2[N_MAX * H];      // h @ a_w1[256:512]
__device__ float    g_eps[N_MAX];         // per-node epsilon
__device__ float    g_ae[E_MAX];          // per-edge attention score
__device__ unsigned g_amax[N_MAX];        // segment max (ordered-int encoded)
__device__ float    g_denom[N_MAX];       // segment sum of exp
__device__ float    g_hv[N_MAX * H];      // unnormalized message sums

// ---------------- fused GEMM ------------------------------------------------
// Computes T = A[M,K] @ B[K,256] for the block tile [BM x BN].
// mode 0: C[row,:] = T + bias (opt) with optional relu  (plain GEMM)
// mode 1: outScalar[row] += sum_j relu(T + bias + P1[src[row]] + P2[dst[row]])_j * w2_j
//         (per-row scalar, partial over this column tile, atomicAdd)
__global__ void __launch_bounds__(NTHREADS, 2)
gemm_fused(const float* __restrict__ A, int M, int K,
           const float* __restrict__ B,        // [K,256] row-major
           const float* __restrict__ bias,     // [256] or null
           float* __restrict__ C,              // mode 0 output [M,256]
           int relu_flag, int mode,
           const float* __restrict__ P1, const float* __restrict__ P2,
           const int* __restrict__ src, const int* __restrict__ dst,
           const float* __restrict__ w2,       // [256]
           float* __restrict__ outScalar)      // [M]
{
    __shared__ float As[BK][BM + 4];
    __shared__ float Bs[BK][BN];

    const int m0 = blockIdx.x * BM;
    const int n0 = blockIdx.y * BN;
    const int tid = threadIdx.x;
    const int tx = tid & 15;       // 0..15 -> column group
    const int ty = tid >> 4;       // 0..15 -> row group

    float acc[8][8];
#pragma unroll
    for (int i = 0; i < 8; i++)
#pragma unroll
        for (int j = 0; j < 8; j++) acc[i][j] = 0.f;

    // A-tile load mapping: thread loads rows (ar, ar+64), 4 consecutive k at ac
    const int ar = tid >> 2;            // 0..63
    const int ac = (tid & 3) * 4;       // 0,4,8,12
    // B-tile load mapping: row br, 8 consecutive n at bc
    const int br = tid >> 4;            // 0..15
    const int bc = (tid & 15) * 8;      // 0..120

    for (int k0 = 0; k0 < K; k0 += BK) {
#pragma unroll
        for (int rr = 0; rr < 2; rr++) {
            const int row = m0 + ar + rr * 64;
            float4 v = make_float4(0.f, 0.f, 0.f, 0.f);
            if (row < M)
                v = *(const float4*)(A + (size_t)row * K + k0 + ac);
            As[ac + 0][ar + rr * 64] = v.x;
            As[ac + 1][ar + rr * 64] = v.y;
            As[ac + 2][ar + rr * 64] = v.z;
            As[ac + 3][ar + rr * 64] = v.w;
        }
#pragma unroll
        for (int cc = 0; cc < 2; cc++) {
            float4 v = *(const float4*)(B + (size_t)(k0 + br) * 256 + n0 + bc + cc * 4);
            *(float4*)&Bs[br][bc + cc * 4] = v;
        }
        __syncthreads();

#pragma unroll
        for (int k = 0; k < BK; k++) {
            float a[8], b[8];
            *(float4*)&a[0] = *(const float4*)&As[k][ty * 8];
            *(float4*)&a[4] = *(const float4*)&As[k][ty * 8 + 4];
            *(float4*)&b[0] = *(const float4*)&Bs[k][tx * 8];
            *(float4*)&b[4] = *(const float4*)&Bs[k][tx * 8 + 4];
#pragma unroll
            for (int i = 0; i < 8; i++)
#pragma unroll
                for (int j = 0; j < 8; j++)
                    acc[i][j] = fmaf(a[i], b[j], acc[i][j]);
        }
        __syncthreads();
    }

    const int nc = n0 + tx * 8;

    if (mode == 0) {
        float bv[8];
#pragma unroll
        for (int j = 0; j < 8; j++) bv[j] = bias ? bias[nc + j] : 0.f;
#pragma unroll
        for (int i = 0; i < 8; i++) {
            const int row = m0 + ty * 8 + i;
            if (row < M) {
#pragma unroll
                for (int jj = 0; jj < 2; jj++) {
                    float4 o;
                    o.x = acc[i][jj * 4 + 0] + bv[jj * 4 + 0];
                    o.y = acc[i][jj * 4 + 1] + bv[jj * 4 + 1];
                    o.z = acc[i][jj * 4 + 2] + bv[jj * 4 + 2];
                    o.w = acc[i][jj * 4 + 3] + bv[jj * 4 + 3];
                    if (relu_flag) {
                        o.x = fmaxf(o.x, 0.f); o.y = fmaxf(o.y, 0.f);
                        o.z = fmaxf(o.z, 0.f); o.w = fmaxf(o.w, 0.f);
                    }
                    *(float4*)(C + (size_t)row * 256 + nc + jj * 4) = o;
                }
            }
        }
    } else {
        float bv[8], wv[8];
#pragma unroll
        for (int j = 0; j < 8; j++) { bv[j] = bias[nc + j]; wv[j] = w2[nc + j]; }
#pragma unroll
        for (int i = 0; i < 8; i++) {
            const int row = m0 + ty * 8 + i;
            float partial = 0.f;
            if (row < M) {
                float p1v[8] = {0, 0, 0, 0, 0, 0, 0, 0};
                float p2v[8] = {0, 0, 0, 0, 0, 0, 0, 0};
                if (P1) {
                    const float* p = P1 + (size_t)src[row] * 256 + nc;
                    *(float4*)&p1v[0] = *(const float4*)(p);
                    *(float4*)&p1v[4] = *(const float4*)(p + 4);
                }
                if (P2) {
                    const float* p = P2 + (size_t)dst[row] * 256 + nc;
                    *(float4*)&p2v[0] = *(const float4*)(p);
                    *(float4*)&p2v[4] = *(const float4*)(p + 4);
                }
#pragma unroll
                for (int j = 0; j < 8; j++) {
                    float v = acc[i][j] + bv[j] + p1v[j] + p2v[j];
                    v = fmaxf(v, 0.f);
                    partial = fmaf(v, wv[j], partial);
                }
            }
            // reduce across the 16 tx lanes (half-warp)
            partial += __shfl_xor_sync(0xffffffffu, partial, 1);
            partial += __shfl_xor_sync(0xffffffffu, partial, 2);
            partial += __shfl_xor_sync(0xffffffffu, partial, 4);
            partial += __shfl_xor_sync(0xffffffffu, partial, 8);
            if (tx == 0 && row < M) atomicAdd(outScalar + row, partial);
        }
    }
}

// ---------------- per-layer init -------------------------------------------
__global__ void init_layer(float* __restrict__ ae, int E, const float* __restrict__ ab2,
                           float* __restrict__ epsv, int N, const float* __restrict__ eb2,
                           unsigned* __restrict__ amax, float* __restrict__ denom,
                           float* __restrict__ hv)
{
    const int i = blockIdx.x * blockDim.x + threadIdx.x;
    if (i < N * H) hv[i] = 0.f;
    if (i < E) ae[i] = ab2[0];
    if (i < N) { epsv[i] = eb2[0]; amax[i] = 0u; denom[i] = 0.f; }
}

// ---------------- segment max via ordered-int atomicMax --------------------
__device__ __forceinline__ unsigned f2key(float f) {
    unsigned b = __float_as_uint(f);
    return (b & 0x80000000u) ? ~b : (b | 0x80000000u);
}
__device__ __forceinline__ float key2f(unsigned k) {
    unsigned b = (k & 0x80000000u) ? (k & 0x7fffffffu) : ~k;
    return __uint_as_float(b);
}

__global__ void edge_max(const float* __restrict__ ae, const int* __restrict__ dst,
                         unsigned* __restrict__ amax, int E)
{
    const int e = blockIdx.x * blockDim.x + threadIdx.x;
    if (e < E) atomicMax(&amax[dst[e]], f2key(ae[e]));
}

// ---------------- exp + message scatter (warp per edge) --------------------
__global__ void edge_msg(const float* __restrict__ ae, const int* __restrict__ src,
                         const int* __restrict__ dst, const float* __restrict__ h,
                         const float* __restrict__ gh, const unsigned* __restrict__ amax,
                         float* __restrict__ denom, float* __restrict__ hv, int E)
{
    const int e = (blockIdx.x * blockDim.x + threadIdx.x) >> 5;
    const int lane = threadIdx.x & 31;
    if (e >= E) return;
    const int s = src[e];
    const int d = dst[e];
    const float mx = key2f(amax[d]);
    const float ea = expf(ae[e] - mx);
    if (lane == 0) atomicAdd(denom + d, ea);

    const float4* g4 = (const float4*)(gh + (size_t)e * H);
    const float4* h4 = (const float4*)(h + (size_t)s * H);
    float* hvp = hv + (size_t)d * H;
#pragma unroll
    for (int it = 0; it < 2; it++) {
        const int j = lane + it * 32;          // float4 index 0..63
        float4 g = g4[j];
        float4 hh = h4[j];
        float4 m;
        m.x = ea * g.x * hh.x;
        m.y = ea * g.y * hh.y;
        m.z = ea * g.z * hh.z;
        m.w = ea * g.w * hh.w;
        asm volatile("red.global.add.v4.f32 [%0], {%1, %2, %3, %4};"
                     :: "l"(hvp + j * 4), "f"(m.x), "f"(m.y), "f"(m.z), "f"(m.w)
                     : "memory");
    }
}

// ---------------- GIN-style node update -------------------------------------
__global__ void node_update(const float* __restrict__ hv, const float* __restrict__ denom,
                            const float* __restrict__ epsv, const float* __restrict__ h_old,
                            float* __restrict__ h_new, int N)
{
    const int i = blockIdx.x * blockDim.x + threadIdx.x;   // float4 index
    if (i >= N * (H / 4)) return;
    const int n = i >> 6;
    const float dn = denom[n];
    const float inv = dn > 0.f ? 1.f / dn : 0.f;
    const float scale = (1.f + epsv[n]) * inv;
    float4 v = ((const float4*)hv)[i];
    float4 ho = ((const float4*)h_old)[i];
    float4 r;
    r.x = fmaf(v.x, scale, ho.x);
    r.y = fmaf(v.y, scale, ho.y);
    r.z = fmaf(v.z, scale, ho.z);
    r.w = fmaf(v.w, scale, ho.w);
    ((float4*)h_new)[i] = r;
}

// ---------------- launch -----------------------------------------------------
extern "C" void kernel_launch(void* const* d_in, const int* in_sizes, int n_in,
                              void* d_out, int out_size)
{
    (void)n_in; (void)out_size;
    const float* node_feats = (const float*)d_in[0];
    const float* gh         = (const float*)d_in[1];
    const int*   src        = (const int*)d_in[2];
    const int*   dst        = (const int*)d_in[3];
    const float* Wn_w       = (const float*)d_in[4];
    const float* Wn_b       = (const float*)d_in[5];
    const float* eps_w1     = (const float*)d_in[6];
    const float* eps_b1     = (const float*)d_in[7];
    const float* eps_w2     = (const float*)d_in[8];
    const float* eps_b2     = (const float*)d_in[9];
    const float* a_w1       = (const float*)d_in[10];
    const float* a_b1       = (const float*)d_in[11];
    const float* a_w2       = (const float*)d_in[12];
    const float* a_b2       = (const float*)d_in[13];

    const int D_IN = 128;
    const int N = in_sizes[0] / D_IN;
    const int E = in_sizes[2];
    const int L = in_sizes[6] / (H * H);

    float* out = (float*)d_out;

    float *P1, *P2, *epsv, *ae, *denom, *hv;
    unsigned* amaxp;
    cudaGetSymbolAddress((void**)&P1,    g_P1);
    cudaGetSymbolAddress((void**)&P2,    g_P2);
    cudaGetSymbolAddress((void**)&epsv,  g_eps);
    cudaGetSymbolAddress((void**)&ae,    g_ae);
    cudaGetSymbolAddress((void**)&amaxp, g_amax);
    cudaGetSymbolAddress((void**)&denom, g_denom);
    cudaGetSymbolAddress((void**)&hv,    g_hv);

    // input projection: out[0:N*H] = node_feats @ W_n + b
    {
        dim3 grid((N + BM - 1) / BM, 256 / BN);
        gemm_fused<<<grid, NTHREADS>>>(node_feats, N, D_IN, Wn_w, Wn_b, out,
                                       0, 0, nullptr, nullptr, nullptr, nullptr,
                                       nullptr, nullptr);
    }

    for (int l = 0; l < L; l++) {
        const float* hcur = out + (size_t)l * N * H;
        float*       hnext = out + (size_t)(l + 1) * N * H;
        const float* aw1 = a_w1 + (size_t)l * 3 * H * H;

        const int tot = N * H;   // >= E here
        init_layer<<<(tot + 255) / 256, 256>>>(ae, E, a_b2 + l,
                                               epsv, N, eps_b2 + l,
                                               amaxp, denom, hv);

        dim3 gridN((N + BM - 1) / BM, 256 / BN);
        // P1 = h @ a_w1[:H], P2 = h @ a_w1[H:2H]
        gemm_fused<<<gridN, NTHREADS>>>(hcur, N, H, aw1, nullptr, P1,
                                        0, 0, nullptr, nullptr, nullptr, nullptr,
                                        nullptr, nullptr);
        gemm_fused<<<gridN, NTHREADS>>>(hcur, N, H, aw1 + (size_t)H * H, nullptr, P2,
                                        0, 0, nullptr, nullptr, nullptr, nullptr,
                                        nullptr, nullptr);
        // eps = relu(h @ eps_w1 + eps_b1) @ eps_w2 + eps_b2  (scalar per node)
        gemm_fused<<<gridN, NTHREADS>>>(hcur, N, H, eps_w1 + (size_t)l * H * H,
                                        eps_b1 + (size_t)l * H, nullptr,
                                        0, 1, nullptr, nullptr, nullptr, nullptr,
                                        eps_w2 + (size_t)l * H, epsv);
        // edge scores: a[e] = relu(gh@W_c + P1[src] + P2[dst] + a_b1) @ a_w2 + a_b2
        dim3 gridE((E + BM - 1) / BM, 256 / BN);
        gemm_fused<<<gridE, NTHREADS>>>(gh, E, H, aw1 + (size_t)2 * H * H,
                                        a_b1 + (size_t)l * H, nullptr,
                                        0, 1, P1, P2, src, dst,
                                        a_w2 + (size_t)l * H, ae);

        edge_max<<<(E + 255) / 256, 256>>>(ae, dst, amaxp, E);
        edge_msg<<<(E + 7) / 8, 256>>>(ae, src, dst, hcur, gh, amaxp, denom, hv, E);
        node_update<<<(N * (H / 4) + 255) / 256, 256>>>(hv, denom, epsv, hcur, hnext, N);
    }
}

// round 3
// speedup vs baseline: 2.0069x; 2.0069x over previous
#include <cuda_runtime.h>
#include <cuda_bf16.h>
#include <math.h>
#include <stdint.h>

#define H 256
#define N_MAX 10240
#define E_MAX 163840
#define L_MAX 3

#define BM 128
#define BN 128
#define BK 32
#define NTH 256

// smem stage layout (bytes)
#define A_H_OFF 0
#define A_L_OFF 8192
#define B_H_OFF 16384
#define B_L_OFF 24576
#define STAGE_BYTES 32768
#define SMEM_TOTAL (2 * STAGE_BYTES)

// ---------------- scratch (device globals; no allocation allowed) ----------
__device__ __nv_bfloat16 g_ghh[E_MAX * H];
__device__ __nv_bfloat16 g_ghl[E_MAX * H];
__device__ __nv_bfloat16 g_nfh[N_MAX * 128];
__device__ __nv_bfloat16 g_nfl[N_MAX * 128];
__device__ __nv_bfloat16 g_hh[N_MAX * H];
__device__ __nv_bfloat16 g_hl[N_MAX * H];
// combined per-layer node/edge weights: rows 0-255 P1W, 256-511 P2W,
// 512-767 epsW, 768-1023 edgeW   (each [256(k),256(n)] row-major)
__device__ __nv_bfloat16 g_Wh[L_MAX * 1024 * 256];
__device__ __nv_bfloat16 g_Wl[L_MAX * 1024 * 256];
__device__ __nv_bfloat16 g_wnh[128 * 256];
__device__ __nv_bfloat16 g_wnl[128 * 256];
__device__ float    g_P[2 * N_MAX * H];
__device__ float    g_eps[N_MAX];
__device__ float    g_ae[E_MAX];
__device__ unsigned g_amax[N_MAX];
__device__ float    g_denom[N_MAX];
__device__ float    g_hv[N_MAX * H];

// ---------------- small helpers --------------------------------------------
__device__ __forceinline__ uint32_t smem_u32(const void* p) {
    uint32_t a;
    asm("{ .reg .u64 t; cvta.to.shared.u64 t, %1; cvt.u32.u64 %0, t; }" : "=r"(a) : "l"(p));
    return a;
}
__device__ __forceinline__ void cp16(uint32_t dst, const void* src) {
    asm volatile("cp.async.cg.shared.global [%0], [%1], 16;" :: "r"(dst), "l"(src));
}
__device__ __forceinline__ void ldsm4(uint32_t* r, uint32_t addr) {
    asm volatile("ldmatrix.sync.aligned.m8n8.x4.shared.b16 {%0,%1,%2,%3}, [%4];"
                 : "=r"(r[0]), "=r"(r[1]), "=r"(r[2]), "=r"(r[3]) : "r"(addr));
}
__device__ __forceinline__ void ldsm4t(uint32_t* r, uint32_t addr) {
    asm volatile("ldmatrix.sync.aligned.m8n8.x4.trans.shared.b16 {%0,%1,%2,%3}, [%4];"
                 : "=r"(r[0]), "=r"(r[1]), "=r"(r[2]), "=r"(r[3]) : "r"(addr));
}
__device__ __forceinline__ void mma16816(float* c, const uint32_t* a, const uint32_t* b) {
    asm volatile("mma.sync.aligned.m16n8k16.row.col.f32.bf16.bf16.f32 "
                 "{%0,%1,%2,%3}, {%4,%5,%6,%7}, {%8,%9}, {%0,%1,%2,%3};"
                 : "+f"(c[0]), "+f"(c[1]), "+f"(c[2]), "+f"(c[3])
                 : "r"(a[0]), "r"(a[1]), "r"(a[2]), "r"(a[3]), "r"(b[0]), "r"(b[1]));
}

// ---------------- conversion: fp32 -> bf16 hi/lo ----------------------------
__global__ void cvt_split(const float* __restrict__ x, __nv_bfloat16* __restrict__ hi,
                          __nv_bfloat16* __restrict__ lo, int n4)
{
    int i = blockIdx.x * blockDim.x + threadIdx.x;
    if (i >= n4) return;
    float4 v = ((const float4*)x)[i];
    __nv_bfloat16 h0 = __float2bfloat16(v.x), h1 = __float2bfloat16(v.y);
    __nv_bfloat16 h2 = __float2bfloat16(v.z), h3 = __float2bfloat16(v.w);
    __nv_bfloat16 l0 = __float2bfloat16(v.x - __bfloat162float(h0));
    __nv_bfloat16 l1 = __float2bfloat16(v.y - __bfloat162float(h1));
    __nv_bfloat16 l2 = __float2bfloat16(v.z - __bfloat162float(h2));
    __nv_bfloat16 l3 = __float2bfloat16(v.w - __bfloat162float(h3));
    __nv_bfloat162 hh0(h0, h1), hh1(h2, h3), ll0(l0, l1), ll1(l2, l3);
    ((__nv_bfloat162*)hi)[i * 2 + 0] = hh0;
    ((__nv_bfloat162*)hi)[i * 2 + 1] = hh1;
    ((__nv_bfloat162*)lo)[i * 2 + 0] = ll0;
    ((__nv_bfloat162*)lo)[i * 2 + 1] = ll1;
}

// ---------------- weight prep: combine + split -------------------------------
__global__ void prep_w(const float* __restrict__ a_w1, const float* __restrict__ eps_w1,
                       const float* __restrict__ Wn_w, int L)
{
    const int totW = L * 1024 * 256;
    const int total = totW + 128 * 256;
    int idx = blockIdx.x * blockDim.x + threadIdx.x;
    if (idx >= total) return;
    float v;
    __nv_bfloat16 *dh, *dl;
    int di;
    if (idx < totW) {
        int l = idx / (1024 * 256);
        int r = (idx / 256) % 1024;
        int n = idx % 256;
        if (r < 512)        v = a_w1[((size_t)l * 768 + r) * 256 + n];
        else if (r < 768)   v = eps_w1[((size_t)l * 256 + (r - 512)) * 256 + n];
        else                v = a_w1[((size_t)l * 768 + 512 + (r - 768)) * 256 + n];
        dh = g_Wh; dl = g_Wl; di = idx;
    } else {
        int i2 = idx - totW;
        v = Wn_w[i2];
        dh = g_wnh; dl = g_wnl; di = i2;
    }
    __nv_bfloat16 h = __float2bfloat16(v);
    dh[di] = h;
    dl[di] = __float2bfloat16(v - __bfloat162float(h));
}

// ---------------- bf16-split tensor-core GEMM -------------------------------
// D[BM,BN] tile of A[M,K] @ B[K,256]; B selected by blockIdx.z (zstrB elems),
// col tile by blockIdx.y.
//   z <  scalar_z : C[z*zstrC + row*256 + col] = D (+bias)
//   z >= scalar_z : sout[row] += sum_col relu(D + sbias + P1[src]+P2[dst]) * w2
__global__ void __launch_bounds__(NTH, 1)
mma_gemm(const __nv_bfloat16* __restrict__ Ah, const __nv_bfloat16* __restrict__ Al,
         int M, int K,
         const __nv_bfloat16* __restrict__ Bh, const __nv_bfloat16* __restrict__ Bl,
         float* __restrict__ C, size_t zstrC, size_t zstrB,
         const float* __restrict__ bias, int scalar_z,
         const float* __restrict__ sbias, const float* __restrict__ w2,
         float* __restrict__ sout,
         const float* __restrict__ P1, const float* __restrict__ P2,
         const int* __restrict__ src, const int* __restrict__ dst)
{
    extern __shared__ char smem[];
    const uint32_t sb = smem_u32(smem);
    const int tid = threadIdx.x;
    const int lane = tid & 31;
    const int wid = tid >> 5;
    const int wm = wid & 3;
    const int wn = wid >> 2;
    const int m0 = blockIdx.x * BM;
    const int n0 = blockIdx.y * BN;
    const int z = blockIdx.z;
    const int nchunks = K / BK;

    const __nv_bfloat16* Bhz = Bh + zstrB * z;
    const __nv_bfloat16* Blz = Bl + zstrB * z;

    float acc[2][8][4];
#pragma unroll
    for (int mi = 0; mi < 2; mi++)
#pragma unroll
        for (int nj = 0; nj < 8; nj++)
#pragma unroll
            for (int q = 0; q < 4; q++) acc[mi][nj][q] = 0.f;

    // ---- stage loader ----
    auto load_stage = [&](int s, int k0) {
        const uint32_t base = sb + s * STAGE_BYTES;
        // A: 512 16B chunks per buf (128 rows x 64B)
#pragma unroll
        for (int i = 0; i < 2; i++) {
            int cid = tid + i * NTH;          // 0..511
            int row = cid >> 2;
            int cb = (cid & 3) * 16;          // byte in 64B row
            int grow = m0 + row;
            if (grow >= M) grow = M - 1;
            size_t gb = ((size_t)grow * K + k0) * 2 + cb;
            uint32_t d = base + row * 64 + (cb ^ ((row & 3) << 4));
            cp16(d + A_H_OFF, (const char*)Ah + gb);
            cp16(d + A_L_OFF, (const char*)Al + gb);
        }
        // B: 512 16B chunks per buf (32 rows x 256B)
#pragma unroll
        for (int i = 0; i < 2; i++) {
            int cid = tid + i * NTH;
            int k = cid >> 4;
            int cb = (cid & 15) * 16;         // byte in 256B tile row
            size_t gb = ((size_t)(k0 + k) * 256 + n0) * 2 + cb;
            uint32_t d = base + k * 256 + (cb ^ ((k & 7) << 4));
            cp16(d + B_H_OFF, (const char*)Bhz + gb);
            cp16(d + B_L_OFF, (const char*)Blz + gb);
        }
        asm volatile("cp.async.commit_group;" ::: "memory");
    };

    auto compute_stage = [&](int s) {
        const uint32_t base = sb + s * STAGE_BYTES;
#pragma unroll
        for (int kk = 0; kk < 2; kk++) {     // two k16 halves
            uint32_t ah[2][4], al[2][4];
#pragma unroll
            for (int mi = 0; mi < 2; mi++) {
                int row = wm * 32 + mi * 16 + (lane & 15);
                uint32_t cb = kk * 32 + ((lane >> 4) << 4);
                uint32_t ad = base + row * 64 + (cb ^ ((row & 3) << 4));
                ldsm4(ah[mi], ad + A_H_OFF);
                ldsm4(al[mi], ad + A_L_OFF);
            }
            uint32_t bh[4][4], bl[4][4];
#pragma unroll
            for (int nj2 = 0; nj2 < 4; nj2++) {
                int k = kk * 16 + (lane & 15);
                uint32_t cb = wn * 128 + nj2 * 32 + ((lane >> 4) << 4);
                uint32_t bd = base + k * 256 + (cb ^ ((k & 7) << 4));
                ldsm4t(bh[nj2], bd + B_H_OFF);
                ldsm4t(bl[nj2], bd + B_L_OFF);
            }
#pragma unroll
            for (int mi = 0; mi < 2; mi++)
#pragma unroll
                for (int nj = 0; nj < 8; nj++) {
                    const uint32_t* b2h = &bh[nj >> 1][(nj & 1) * 2];
                    const uint32_t* b2l = &bl[nj >> 1][(nj & 1) * 2];
                    mma16816(acc[mi][nj], ah[mi], b2h);
                    mma16816(acc[mi][nj], al[mi], b2h);
                    mma16816(acc[mi][nj], ah[mi], b2l);
                }
        }
    };

    load_stage(0, 0);
    for (int c = 0; c < nchunks; c++) {
        if (c + 1 < nchunks) {
            load_stage((c + 1) & 1, (c + 1) * BK);
            asm volatile("cp.async.wait_group 1;" ::: "memory");
        } else {
            asm volatile("cp.async.wait_group 0;" ::: "memory");
        }
        __syncthreads();
        compute_stage(c & 1);
        __syncthreads();
    }

    // ---- epilogue ----
    if (z < scalar_z) {
        float* Cz = C + zstrC * z;
        const float* bp = bias;
#pragma unroll
        for (int mi = 0; mi < 2; mi++) {
#pragma unroll
            for (int half = 0; half < 2; half++) {
                int row = m0 + wm * 32 + mi * 16 + half * 8 + (lane >> 2);
                if (row >= M) continue;
                float* cr = Cz + (size_t)row * 256;
#pragma unroll
                for (int nj = 0; nj < 8; nj++) {
                    int col = n0 + wn * 64 + nj * 8 + (lane & 3) * 2;
                    float2 v;
                    v.x = acc[mi][nj][half * 2 + 0];
                    v.y = acc[mi][nj][half * 2 + 1];
                    if (bp) { v.x += bp[col]; v.y += bp[col + 1]; }
                    *(float2*)(cr + col) = v;
                }
            }
        }
    } else {
#pragma unroll
        for (int mi = 0; mi < 2; mi++) {
#pragma unroll
            for (int half = 0; half < 2; half++) {
                int row = m0 + wm * 32 + mi * 16 + half * 8 + (lane >> 2);
                int cl = (row < M) ? row : (M - 1);
                const float* p1 = P1 ? (P1 + (size_t)src[cl] * 256) : nullptr;
                const float* p2 = P2 ? (P2 + (size_t)dst[cl] * 256) : nullptr;
                float part = 0.f;
#pragma unroll
                for (int nj = 0; nj < 8; nj++) {
                    int col = n0 + wn * 64 + nj * 8 + (lane & 3) * 2;
                    float2 bv = *(const float2*)(sbias + col);
                    float2 wv = *(const float2*)(w2 + col);
                    float2 p1v = make_float2(0.f, 0.f), p2v = make_float2(0.f, 0.f);
                    if (p1) p1v = *(const float2*)(p1 + col);
                    if (p2) p2v = *(const float2*)(p2 + col);
                    float v0 = fmaxf(acc[mi][nj][half * 2 + 0] + bv.x + p1v.x + p2v.x, 0.f);
                    float v1 = fmaxf(acc[mi][nj][half * 2 + 1] + bv.y + p1v.y + p2v.y, 0.f);
                    part = fmaf(v0, wv.x, part);
                    part = fmaf(v1, wv.y, part);
                }
                part += __shfl_xor_sync(0xffffffffu, part, 1);
                part += __shfl_xor_sync(0xffffffffu, part, 2);
                if ((lane & 3) == 0 && row < M) atomicAdd(sout + row, part);
            }
        }
    }
}

// ---------------- per-layer init --------------------------------------------
__global__ void init_layer(float* __restrict__ ae, int E, const float* __restrict__ ab2,
                           float* __restrict__ epsv, int N, const float* __restrict__ eb2,
                           unsigned* __restrict__ amax, float* __restrict__ denom,
                           float* __restrict__ hv)
{
    const int i = blockIdx.x * blockDim.x + threadIdx.x;
    if (i < N * H) hv[i] = 0.f;
    if (i < E) ae[i] = ab2[0];
    if (i < N) { epsv[i] = eb2[0]; amax[i] = 0u; denom[i] = 0.f; }
}

// ---------------- segment max via ordered-int atomicMax --------------------
__device__ __forceinline__ unsigned f2key(float f) {
    unsigned b = __float_as_uint(f);
    return (b & 0x80000000u) ? ~b : (b | 0x80000000u);
}
__device__ __forceinline__ float key2f(unsigned k) {
    unsigned b = (k & 0x80000000u) ? (k & 0x7fffffffu) : ~k;
    return __uint_as_float(b);
}

__global__ void edge_max(const float* __restrict__ ae, const int* __restrict__ dst,
                         unsigned* __restrict__ amax, int E)
{
    const int e = blockIdx.x * blockDim.x + threadIdx.x;
    if (e < E) atomicMax(&amax[dst[e]], f2key(ae[e]));
}

// ---------------- exp + message scatter (warp per edge) --------------------
__global__ void edge_msg(const float* __restrict__ ae, const int* __restrict__ src,
                         const int* __restrict__ dst, const float* __restrict__ h,
                         const float* __restrict__ gh, const unsigned* __restrict__ amax,
                         float* __restrict__ denom, float* __restrict__ hv, int E)
{
    const int e = (blockIdx.x * blockDim.x + threadIdx.x) >> 5;
    const int lane = threadIdx.x & 31;
    if (e >= E) return;
    const int s = src[e];
    const int d = dst[e];
    const float mx = key2f(amax[d]);
    const float ea = expf(ae[e] - mx);
    if (lane == 0) atomicAdd(denom + d, ea);

    const float4* g4 = (const float4*)(gh + (size_t)e * H);
    const float4* h4 = (const float4*)(h + (size_t)s * H);
    float* hvp = hv + (size_t)d * H;
#pragma unroll
    for (int it = 0; it < 2; it++) {
        const int j = lane + it * 32;
        float4 g = g4[j];
        float4 hh = h4[j];
        float4 m;
        m.x = ea * g.x * hh.x;
        m.y = ea * g.y * hh.y;
        m.z = ea * g.z * hh.z;
        m.w = ea * g.w * hh.w;
        asm volatile("red.global.add.v4.f32 [%0], {%1, %2, %3, %4};"
                     :: "l"(hvp + j * 4), "f"(m.x), "f"(m.y), "f"(m.z), "f"(m.w)
                     : "memory");
    }
}

// ---------------- GIN-style node update -------------------------------------
__global__ void node_update(const float* __restrict__ hv, const float* __restrict__ denom,
                            const float* __restrict__ epsv, const float* __restrict__ h_old,
                            float* __restrict__ h_new, int N)
{
    const int i = blockIdx.x * blockDim.x + threadIdx.x;
    if (i >= N * (H / 4)) return;
    const int n = i >> 6;
    const float dn = denom[n];
    const float inv = dn > 0.f ? 1.f / dn : 0.f;
    const float scale = (1.f + epsv[n]) * inv;
    float4 v = ((const float4*)hv)[i];
    float4 ho = ((const float4*)h_old)[i];
    float4 r;
    r.x = fmaf(v.x, scale, ho.x);
    r.y = fmaf(v.y, scale, ho.y);
    r.z = fmaf(v.z, scale, ho.z);
    r.w = fmaf(v.w, scale, ho.w);
    ((float4*)h_new)[i] = r;
}

// ---------------- launch -----------------------------------------------------
extern "C" void kernel_launch(void* const* d_in, const int* in_sizes, int n_in,
                              void* d_out, int out_size)
{
    (void)n_in; (void)out_size;
    const float* node_feats = (const float*)d_in[0];
    const float* gh         = (const float*)d_in[1];
    const int*   src        = (const int*)d_in[2];
    const int*   dst        = (const int*)d_in[3];
    const float* Wn_w       = (const float*)d_in[4];
    const float* Wn_b       = (const float*)d_in[5];
    const float* eps_w1     = (const float*)d_in[6];
    const float* eps_b1     = (const float*)d_in[7];
    const float* eps_w2     = (const float*)d_in[8];
    const float* eps_b2     = (const float*)d_in[9];
    const float* a_w1       = (const float*)d_in[10];
    const float* a_b1       = (const float*)d_in[11];
    const float* a_w2       = (const float*)d_in[12];
    const float* a_b2       = (const float*)d_in[13];

    const int D_IN = 128;
    const int N = in_sizes[0] / D_IN;
    const int E = in_sizes[2];
    const int L = in_sizes[6] / (H * H);

    float* out = (float*)d_out;

    __nv_bfloat16 *ghh, *ghl, *nfh, *nfl, *hh, *hl, *Wh, *Wl, *wnh, *wnl;
    float *gP, *epsv, *ae, *denom, *hv;
    unsigned* amaxp;
    cudaGetSymbolAddress((void**)&ghh, g_ghh);
    cudaGetSymbolAddress((void**)&ghl, g_ghl);
    cudaGetSymbolAddress((void**)&nfh, g_nfh);
    cudaGetSymbolAddress((void**)&nfl, g_nfl);
    cudaGetSymbolAddress((void**)&hh,  g_hh);
    cudaGetSymbolAddress((void**)&hl,  g_hl);
    cudaGetSymbolAddress((void**)&Wh,  g_Wh);
    cudaGetSymbolAddress((void**)&Wl,  g_Wl);
    cudaGetSymbolAddress((void**)&wnh, g_wnh);
    cudaGetSymbolAddress((void**)&wnl, g_wnl);
    cudaGetSymbolAddress((void**)&gP,    g_P);
    cudaGetSymbolAddress((void**)&epsv,  g_eps);
    cudaGetSymbolAddress((void**)&ae,    g_ae);
    cudaGetSymbolAddress((void**)&amaxp, g_amax);
    cudaGetSymbolAddress((void**)&denom, g_denom);
    cudaGetSymbolAddress((void**)&hv,    g_hv);

    cudaFuncSetAttribute(mma_gemm, cudaFuncAttributeMaxDynamicSharedMemorySize, SMEM_TOTAL);

    // conversions + weight prep
    {
        int n4 = (E * H) / 4;
        cvt_split<<<(n4 + 255) / 256, 256>>>(gh, ghh, ghl, n4);
        n4 = (N * D_IN) / 4;
        cvt_split<<<(n4 + 255) / 256, 256>>>(node_feats, nfh, nfl, n4);
        int totw = L * 1024 * 256 + 128 * 256;
        prep_w<<<(totw + 255) / 256, 256>>>(a_w1, eps_w1, Wn_w, L);
    }

    const int nblkN = (N + BM - 1) / BM;
    const int nblkE = (E + BM - 1) / BM;
    const size_t nsec = (size_t)N * H;

    // input projection -> out[0:N*H]
    mma_gemm<<<dim3(nblkN, 2, 1), NTH, SMEM_TOTAL>>>(
        nfh, nfl, N, D_IN, wnh, wnl,
        out, 0, 0, Wn_b, 99,
        nullptr, nullptr, nullptr, nullptr, nullptr, nullptr, nullptr);
    cvt_split<<<((N * H) / 4 + 255) / 256, 256>>>(out, hh, hl, (N * H) / 4);

    for (int l = 0; l < L; l++) {
        const float* hcur = out + (size_t)l * N * H;
        float*       hnext = out + (size_t)(l + 1) * N * H;
        const __nv_bfloat16* WhL = Wh + (size_t)l * 1024 * 256;
        const __nv_bfloat16* WlL = Wl + (size_t)l * 1024 * 256;

        init_layer<<<((N * H) + 255) / 256, 256>>>(ae, E, a_b2 + l,
                                                   epsv, N, eps_b2 + l,
                                                   amaxp, denom, hv);

        // node GEMMs: z=0 -> P1, z=1 -> P2, z=2 -> eps scalar (rows 512-767)
        mma_gemm<<<dim3(nblkN, 2, 3), NTH, SMEM_TOTAL>>>(
            hh, hl, N, H, WhL, WlL,
            gP, nsec, (size_t)256 * 256, nullptr, 2,
            eps_b1 + (size_t)l * H, eps_w2 + (size_t)l * H, epsv,
            nullptr, nullptr, nullptr, nullptr);

        // edge scores (rows 768-1023 of combined W)
        mma_gemm<<<dim3(nblkE, 2, 1), NTH, SMEM_TOTAL>>>(
            ghh, ghl, E, H, WhL + (size_t)768 * 256, WlL + (size_t)768 * 256,
            nullptr, 0, 0, nullptr, 0,
            a_b1 + (size_t)l * H, a_w2 + (size_t)l * H, ae,
            gP, gP + nsec, src, dst);

        edge_max<<<(E + 255) / 256, 256>>>(ae, dst, amaxp, E);
        edge_msg<<<(E + 7) / 8, 256>>>(ae, src, dst, hcur, gh, amaxp, denom, hv, E);
        node_update<<<(N * (H / 4) + 255) / 256, 256>>>(hv, denom, epsv, hcur, hnext, N);
        if (l + 1 < L)
            cvt_split<<<((N * H) / 4 + 255) / 256, 256>>>(hnext, hh, hl, (N * H) / 4);
    }
}

// round 4
// speedup vs baseline: 2.1131x; 1.0529x over previous
#include <cuda_runtime.h>
#include <cuda_bf16.h>
#include <math.h>
#include <stdint.h>

#define H 256
#define N_MAX 10240
#define E_MAX 163840
#define L_MAX 3

#define BM 128
#define BN 256
#define BK 32
#define NTH 256

// stage layout (bytes)
#define A_H 0
#define A_L 8192
#define B_HO 16384
#define B_LO 32768
#define ST_BYTES 49152
#define NSTAGE 3
#define SMEM_TOTAL (NSTAGE * ST_BYTES)

// ---------------- scratch (device globals) ---------------------------------
__device__ __nv_bfloat16 g_ghh[E_MAX * H];
__device__ __nv_bfloat16 g_ghl[E_MAX * H];
__device__ __nv_bfloat16 g_nfh[N_MAX * 128];
__device__ __nv_bfloat16 g_nfl[N_MAX * 128];
__device__ __nv_bfloat16 g_hh[N_MAX * H];
__device__ __nv_bfloat16 g_hl[N_MAX * H];
// combined per-layer weights: rows 0-255 P1W, 256-511 P2W, 512-767 epsW,
// 768-1023 edgeW (each [256k,256n] row-major)
__device__ __nv_bfloat16 g_Wh[L_MAX * 1024 * 256];
__device__ __nv_bfloat16 g_Wl[L_MAX * 1024 * 256];
__device__ __nv_bfloat16 g_wnh[128 * 256];
__device__ __nv_bfloat16 g_wnl[128 * 256];
__device__ float g_P[2 * N_MAX * H];
__device__ float g_eps[N_MAX];
__device__ float g_ae[E_MAX];
// CSR by dst
__device__ int g_cnt[N_MAX];
__device__ int g_off[N_MAX + 1];
__device__ int g_cur[N_MAX];
__device__ int g_perm[E_MAX];

// ---------------- helpers ----------------------------------------------------
__device__ __forceinline__ uint32_t smem_u32(const void* p) {
    uint32_t a;
    asm("{ .reg .u64 t; cvta.to.shared.u64 t, %1; cvt.u32.u64 %0, t; }" : "=r"(a) : "l"(p));
    return a;
}
__device__ __forceinline__ void cp16(uint32_t dst, const void* src) {
    asm volatile("cp.async.cg.shared.global [%0], [%1], 16;" :: "r"(dst), "l"(src));
}
__device__ __forceinline__ void ldsm4(uint32_t* r, uint32_t addr) {
    asm volatile("ldmatrix.sync.aligned.m8n8.x4.shared.b16 {%0,%1,%2,%3}, [%4];"
                 : "=r"(r[0]), "=r"(r[1]), "=r"(r[2]), "=r"(r[3]) : "r"(addr));
}
__device__ __forceinline__ void ldsm4t(uint32_t* r, uint32_t addr) {
    asm volatile("ldmatrix.sync.aligned.m8n8.x4.trans.shared.b16 {%0,%1,%2,%3}, [%4];"
                 : "=r"(r[0]), "=r"(r[1]), "=r"(r[2]), "=r"(r[3]) : "r"(addr));
}
__device__ __forceinline__ void mma16816(float* c, const uint32_t* a, const uint32_t* b) {
    asm volatile("mma.sync.aligned.m16n8k16.row.col.f32.bf16.bf16.f32 "
                 "{%0,%1,%2,%3}, {%4,%5,%6,%7}, {%8,%9}, {%0,%1,%2,%3};"
                 : "+f"(c[0]), "+f"(c[1]), "+f"(c[2]), "+f"(c[3])
                 : "r"(a[0]), "r"(a[1]), "r"(a[2]), "r"(a[3]), "r"(b[0]), "r"(b[1]));
}

// ---------------- fp32 -> bf16 hi/lo split ----------------------------------
__global__ void cvt_split(const float* __restrict__ x, __nv_bfloat16* __restrict__ hi,
                          __nv_bfloat16* __restrict__ lo, int n4)
{
    int i = blockIdx.x * blockDim.x + threadIdx.x;
    if (i >= n4) return;
    float4 v = ((const float4*)x)[i];
    __nv_bfloat16 h0 = __float2bfloat16(v.x), h1 = __float2bfloat16(v.y);
    __nv_bfloat16 h2 = __float2bfloat16(v.z), h3 = __float2bfloat16(v.w);
    __nv_bfloat16 l0 = __float2bfloat16(v.x - __bfloat162float(h0));
    __nv_bfloat16 l1 = __float2bfloat16(v.y - __bfloat162float(h1));
    __nv_bfloat16 l2 = __float2bfloat16(v.z - __bfloat162float(h2));
    __nv_bfloat16 l3 = __float2bfloat16(v.w - __bfloat162float(h3));
    __nv_bfloat162 hh0(h0, h1), hh1(h2, h3), ll0(l0, l1), ll1(l2, l3);
    ((__nv_bfloat162*)hi)[i * 2 + 0] = hh0;
    ((__nv_bfloat162*)hi)[i * 2 + 1] = hh1;
    ((__nv_bfloat162*)lo)[i * 2 + 0] = ll0;
    ((__nv_bfloat162*)lo)[i * 2 + 1] = ll1;
}

// ---------------- weight prep ------------------------------------------------
__global__ void prep_w(const float* __restrict__ a_w1, const float* __restrict__ eps_w1,
                       const float* __restrict__ Wn_w, int L)
{
    const int totW = L * 1024 * 256;
    const int total = totW + 128 * 256;
    int idx = blockIdx.x * blockDim.x + threadIdx.x;
    if (idx >= total) return;
    float v;
    __nv_bfloat16 *dh, *dl;
    int di;
    if (idx < totW) {
        int l = idx / (1024 * 256);
        int r = (idx / 256) % 1024;
        int n = idx % 256;
        if (r < 512)      v = a_w1[((size_t)l * 768 + r) * 256 + n];
        else if (r < 768) v = eps_w1[((size_t)l * 256 + (r - 512)) * 256 + n];
        else              v = a_w1[((size_t)l * 768 + 512 + (r - 768)) * 256 + n];
        dh = g_Wh; dl = g_Wl; di = idx;
    } else {
        int i2 = idx - totW;
        v = Wn_w[i2];
        dh = g_wnh; dl = g_wnl; di = i2;
    }
    __nv_bfloat16 h = __float2bfloat16(v);
    dh[di] = h;
    dl[di] = __float2bfloat16(v - __bfloat162float(h));
}

// ---------------- CSR build ---------------------------------------------------
__global__ void csr_clear(int N) {
    int i = blockIdx.x * blockDim.x + threadIdx.x;
    if (i < N) g_cnt[i] = 0;
}
__global__ void csr_hist(const int* __restrict__ dst, int E) {
    int e = blockIdx.x * blockDim.x + threadIdx.x;
    if (e < E) atomicAdd(&g_cnt[dst[e]], 1);
}
__global__ void csr_scan(int N, int E) {
    __shared__ int sums[256];
    const int tid = threadIdx.x;
    const int chunk = (N + 255) / 256;
    const int base = tid * chunk;
    int s = 0;
    for (int i = 0; i < chunk; i++) {
        int idx = base + i;
        if (idx < N) s += g_cnt[idx];
    }
    sums[tid] = s;
    __syncthreads();
    for (int d = 1; d < 256; d <<= 1) {
        int v = (tid >= d) ? sums[tid - d] : 0;
        __syncthreads();
        sums[tid] += v;
        __syncthreads();
    }
    int run = sums[tid] - s;
    for (int i = 0; i < chunk; i++) {
        int idx = base + i;
        if (idx < N) { g_off[idx] = run; g_cur[idx] = run; run += g_cnt[idx]; }
    }
    if (tid == 255) g_off[N] = E;
}
__global__ void csr_scatter(const int* __restrict__ dst, int E) {
    int e = blockIdx.x * blockDim.x + threadIdx.x;
    if (e < E) {
        int pos = atomicAdd(&g_cur[dst[e]], 1);
        g_perm[pos] = e;
    }
}

// ---------------- bf16-split tensor-core GEMM (BM=128, BN=256) ---------------
// z < scalar_z : C[z*zstrC + row*256 + col] = D (+bias); optional bf16 split out
// z >= scalar_z: sout[m0+row] = sum_col relu(D + sbias + P1[src]+P2[dst])*w2 + b2
__global__ void __launch_bounds__(NTH, 1)
mma_gemm(const __nv_bfloat16* __restrict__ Ah, const __nv_bfloat16* __restrict__ Al,
         int M, int K,
         const __nv_bfloat16* __restrict__ Bh, const __nv_bfloat16* __restrict__ Bl,
         float* __restrict__ C, size_t zstrC, size_t zstrB,
         const float* __restrict__ bias, int scalar_z,
         const float* __restrict__ sbias, const float* __restrict__ w2,
         const float* __restrict__ b2, float* __restrict__ sout,
         const float* __restrict__ P1, const float* __restrict__ P2,
         const int* __restrict__ src, const int* __restrict__ dst,
         __nv_bfloat16* __restrict__ bfh, __nv_bfloat16* __restrict__ bfl)
{
    extern __shared__ char smem[];
    const uint32_t sb = smem_u32(smem);
    const int tid = threadIdx.x;
    const int lane = tid & 31;
    const int wid = tid >> 5;
    const int wm = wid & 3;
    const int wn = wid >> 2;
    const int m0 = blockIdx.x * BM;
    const int z = blockIdx.z;
    const int nchunks = K / BK;

    const __nv_bfloat16* Bhz = Bh + zstrB * z;
    const __nv_bfloat16* Blz = Bl + zstrB * z;

    float acc[2][16][4];
#pragma unroll
    for (int mi = 0; mi < 2; mi++)
#pragma unroll
        for (int nj = 0; nj < 16; nj++)
#pragma unroll
            for (int q = 0; q < 4; q++) acc[mi][nj][q] = 0.f;

    auto load_stage = [&](int s, int k0) {
        const uint32_t base = sb + s * ST_BYTES;
        // A: 512 chunks of 16B per buf
#pragma unroll
        for (int i = 0; i < 2; i++) {
            int cid = tid + i * NTH;
            int row = cid >> 2;
            int cb = (cid & 3) * 16;
            int grow = m0 + row;
            if (grow >= M) grow = M - 1;
            size_t gb = ((size_t)grow * K + k0) * 2 + cb;
            uint32_t d = base + row * 64 + (cb ^ ((row & 3) << 4));
            cp16(d + A_H, (const char*)Ah + gb);
            cp16(d + A_L, (const char*)Al + gb);
        }
        // B: 1024 chunks of 16B per buf (32 k-rows x 512B)
#pragma unroll
        for (int i = 0; i < 4; i++) {
            int cid = tid + i * NTH;
            int k = cid >> 5;
            int cb = (cid & 31) * 16;
            size_t gb = (size_t)(k0 + k) * 512 + cb;
            uint32_t d = base + k * 512 + (cb ^ ((k & 7) << 4));
            cp16(d + B_HO, (const char*)Bhz + gb);
            cp16(d + B_LO, (const char*)Blz + gb);
        }
        asm volatile("cp.async.commit_group;" ::: "memory");
    };

    auto compute_stage = [&](int s) {
        const uint32_t base = sb + s * ST_BYTES;
#pragma unroll
        for (int kk = 0; kk < 2; kk++) {
            uint32_t ah[2][4], al[2][4];
#pragma unroll
            for (int mi = 0; mi < 2; mi++) {
                int row = wm * 32 + mi * 16 + (lane & 15);
                uint32_t cb = kk * 32 + ((lane >> 4) << 4);
                uint32_t ad = base + row * 64 + (cb ^ ((row & 3) << 4));
                ldsm4(ah[mi], ad + A_H);
                ldsm4(al[mi], ad + A_L);
            }
#pragma unroll
            for (int nj2 = 0; nj2 < 8; nj2++) {
                int k = kk * 16 + (lane & 15);
                uint32_t cb = wn * 256 + nj2 * 32 + ((lane >> 4) << 4);
                uint32_t bd = base + k * 512 + (cb ^ ((k & 7) << 4));
                uint32_t bh4[4], bl4[4];
                ldsm4t(bh4, bd + B_HO);
                ldsm4t(bl4, bd + B_LO);
#pragma unroll
                for (int mi = 0; mi < 2; mi++)
#pragma unroll
                    for (int sub = 0; sub < 2; sub++) {
                        int nj = nj2 * 2 + sub;
                        mma16816(acc[mi][nj], ah[mi], &bh4[sub * 2]);
                        mma16816(acc[mi][nj], al[mi], &bh4[sub * 2]);
                        mma16816(acc[mi][nj], ah[mi], &bl4[sub * 2]);
                    }
            }
        }
    };

    load_stage(0, 0);
    load_stage(1, BK);
    for (int c = 0; c < nchunks; c++) {
        if (c + 2 < nchunks) load_stage((c + 2) % 3, (c + 2) * BK);
        else asm volatile("cp.async.commit_group;" ::: "memory");
        asm volatile("cp.async.wait_group 2;" ::: "memory");
        __syncthreads();
        compute_stage(c % 3);
        __syncthreads();
    }

    if (z < scalar_z) {
        float* Cz = C + zstrC * z;
#pragma unroll
        for (int mi = 0; mi < 2; mi++) {
#pragma unroll
            for (int half = 0; half < 2; half++) {
                int row = m0 + wm * 32 + mi * 16 + half * 8 + (lane >> 2);
                if (row >= M) continue;
                float* cr = Cz + (size_t)row * 256;
#pragma unroll
                for (int nj = 0; nj < 16; nj++) {
                    int col = wn * 128 + nj * 8 + (lane & 3) * 2;
                    float2 v;
                    v.x = acc[mi][nj][half * 2 + 0];
                    v.y = acc[mi][nj][half * 2 + 1];
                    if (bias) { v.x += bias[col]; v.y += bias[col + 1]; }
                    *(float2*)(cr + col) = v;
                    if (bfh) {
                        __nv_bfloat16 b0 = __float2bfloat16(v.x);
                        __nv_bfloat16 b1 = __float2bfloat16(v.y);
                        __nv_bfloat162 hp(b0, b1);
                        __nv_bfloat162 lp(__float2bfloat16(v.x - __bfloat162float(b0)),
                                          __float2bfloat16(v.y - __bfloat162float(b1)));
                        *(__nv_bfloat162*)(bfh + (size_t)row * 256 + col) = hp;
                        *(__nv_bfloat162*)(bfl + (size_t)row * 256 + col) = lp;
                    }
                }
            }
        }
    } else {
        float* sred = (float*)smem;   // [128][2]
#pragma unroll
        for (int mi = 0; mi < 2; mi++) {
#pragma unroll
            for (int half = 0; half < 2; half++) {
                int rowl = wm * 32 + mi * 16 + half * 8 + (lane >> 2);
                int row = m0 + rowl;
                int cl = (row < M) ? row : (M - 1);
                const float* p1 = P1 ? (P1 + (size_t)src[cl] * 256) : nullptr;
                const float* p2 = P2 ? (P2 + (size_t)dst[cl] * 256) : nullptr;
                float part = 0.f;
#pragma unroll
                for (int nj = 0; nj < 16; nj++) {
                    int col = wn * 128 + nj * 8 + (lane & 3) * 2;
                    float2 bv = *(const float2*)(sbias + col);
                    float2 wv = *(const float2*)(w2 + col);
                    float2 p1v = make_float2(0.f, 0.f), p2v = make_float2(0.f, 0.f);
                    if (p1) p1v = *(const float2*)(p1 + col);
                    if (p2) p2v = *(const float2*)(p2 + col);
                    float v0 = fmaxf(acc[mi][nj][half * 2 + 0] + bv.x + p1v.x + p2v.x, 0.f);
                    float v1 = fmaxf(acc[mi][nj][half * 2 + 1] + bv.y + p1v.y + p2v.y, 0.f);
                    part = fmaf(v0, wv.x, part);
                    part = fmaf(v1, wv.y, part);
                }
                part += __shfl_xor_sync(0xffffffffu, part, 1);
                part += __shfl_xor_sync(0xffffffffu, part, 2);
                if ((lane & 3) == 0) sred[rowl * 2 + wn] = part;
            }
        }
        __syncthreads();
        if (tid < 128) {
            int row = m0 + tid;
            if (row < M) sout[row] = sred[tid * 2] + sred[tid * 2 + 1] + b2[0];
        }
    }
}

// ---------------- fused message + softmax + update (warp per node) -----------
__global__ void msg_update(const float* __restrict__ ae, const int* __restrict__ src,
                           const float* __restrict__ gh, const float* __restrict__ h_old,
                           const float* __restrict__ epsv,
                           float* __restrict__ h_new,
                           __nv_bfloat16* __restrict__ hh, __nv_bfloat16* __restrict__ hl,
                           int N)
{
    const int w = (blockIdx.x * blockDim.x + threadIdx.x) >> 5;
    const int lane = threadIdx.x & 31;
    if (w >= N) return;
    const int lo = g_off[w], hi = g_off[w + 1];

    float m = -INFINITY, s = 0.f;
    float4 a0 = make_float4(0.f, 0.f, 0.f, 0.f);
    float4 a1 = make_float4(0.f, 0.f, 0.f, 0.f);

    for (int i = lo; i < hi; i++) {
        const int e = g_perm[i];
        const float a = ae[e];
        if (a > m) {
            float sc = expf(m - a);
            a0.x *= sc; a0.y *= sc; a0.z *= sc; a0.w *= sc;
            a1.x *= sc; a1.y *= sc; a1.z *= sc; a1.w *= sc;
            s *= sc;
            m = a;
        }
        const float ea = expf(a - m);
        s += ea;
        const float4* g4 = (const float4*)(gh + (size_t)e * H);
        const float4* h4 = (const float4*)(h_old + (size_t)src[e] * H);
        float4 g = g4[lane], hv = h4[lane];
        a0.x = fmaf(ea * g.x, hv.x, a0.x);
        a0.y = fmaf(ea * g.y, hv.y, a0.y);
        a0.z = fmaf(ea * g.z, hv.z, a0.z);
        a0.w = fmaf(ea * g.w, hv.w, a0.w);
        g = g4[lane + 32]; hv = h4[lane + 32];
        a1.x = fmaf(ea * g.x, hv.x, a1.x);
        a1.y = fmaf(ea * g.y, hv.y, a1.y);
        a1.z = fmaf(ea * g.z, hv.z, a1.z);
        a1.w = fmaf(ea * g.w, hv.w, a1.w);
    }
    const float inv = (s > 0.f) ? (1.f / s) : 0.f;
    const float scale = (1.f + epsv[w]) * inv;

    const float4* hrow = (const float4*)(h_old + (size_t)w * H);
    float4 o0 = hrow[lane], o1 = hrow[lane + 32];
    float4 r0, r1;
    r0.x = fmaf(a0.x, scale, o0.x); r0.y = fmaf(a0.y, scale, o0.y);
    r0.z = fmaf(a0.z, scale, o0.z); r0.w = fmaf(a0.w, scale, o0.w);
    r1.x = fmaf(a1.x, scale, o1.x); r1.y = fmaf(a1.y, scale, o1.y);
    r1.z = fmaf(a1.z, scale, o1.z); r1.w = fmaf(a1.w, scale, o1.w);
    ((float4*)(h_new + (size_t)w * H))[lane] = r0;
    ((float4*)(h_new + (size_t)w * H))[lane + 32] = r1;

    // bf16 hi/lo split for next layer's GEMMs
    auto wr = [&](float4 v, int c) {
        __nv_bfloat16 b0 = __float2bfloat16(v.x), b1 = __float2bfloat16(v.y);
        __nv_bfloat16 b2 = __float2bfloat16(v.z), b3 = __float2bfloat16(v.w);
        __nv_bfloat162 hp0(b0, b1), hp1(b2, b3);
        __nv_bfloat162 lp0(__float2bfloat16(v.x - __bfloat162float(b0)),
                           __float2bfloat16(v.y - __bfloat162float(b1)));
        __nv_bfloat162 lp1(__float2bfloat16(v.z - __bfloat162float(b2)),
                           __float2bfloat16(v.w - __bfloat162float(b3)));
        *(__nv_bfloat162*)(hh + (size_t)w * H + c) = hp0;
        *(__nv_bfloat162*)(hh + (size_t)w * H + c + 2) = hp1;
        *(__nv_bfloat162*)(hl + (size_t)w * H + c) = lp0;
        *(__nv_bfloat162*)(hl + (size_t)w * H + c + 2) = lp1;
    };
    wr(r0, lane * 4);
    wr(r1, 128 + lane * 4);
}

// ---------------- launch -------------------------------------------------------
extern "C" void kernel_launch(void* const* d_in, const int* in_sizes, int n_in,
                              void* d_out, int out_size)
{
    (void)n_in; (void)out_size;
    const float* node_feats = (const float*)d_in[0];
    const float* gh         = (const float*)d_in[1];
    const int*   src        = (const int*)d_in[2];
    const int*   dst        = (const int*)d_in[3];
    const float* Wn_w       = (const float*)d_in[4];
    const float* Wn_b       = (const float*)d_in[5];
    const float* eps_w1     = (const float*)d_in[6];
    const float* eps_b1     = (const float*)d_in[7];
    const float* eps_w2     = (const float*)d_in[8];
    const float* eps_b2     = (const float*)d_in[9];
    const float* a_w1       = (const float*)d_in[10];
    const float* a_b1       = (const float*)d_in[11];
    const float* a_w2       = (const float*)d_in[12];
    const float* a_b2       = (const float*)d_in[13];

    const int D_IN = 128;
    const int N = in_sizes[0] / D_IN;
    const int E = in_sizes[2];
    const int L = in_sizes[6] / (H * H);

    float* out = (float*)d_out;

    __nv_bfloat16 *ghh, *ghl, *nfh, *nfl, *hh, *hl, *Wh, *Wl, *wnh, *wnl;
    float *gP, *epsv, *ae;
    cudaGetSymbolAddress((void**)&ghh, g_ghh);
    cudaGetSymbolAddress((void**)&ghl, g_ghl);
    cudaGetSymbolAddress((void**)&nfh, g_nfh);
    cudaGetSymbolAddress((void**)&nfl, g_nfl);
    cudaGetSymbolAddress((void**)&hh,  g_hh);
    cudaGetSymbolAddress((void**)&hl,  g_hl);
    cudaGetSymbolAddress((void**)&Wh,  g_Wh);
    cudaGetSymbolAddress((void**)&Wl,  g_Wl);
    cudaGetSymbolAddress((void**)&wnh, g_wnh);
    cudaGetSymbolAddress((void**)&wnl, g_wnl);
    cudaGetSymbolAddress((void**)&gP,   g_P);
    cudaGetSymbolAddress((void**)&epsv, g_eps);
    cudaGetSymbolAddress((void**)&ae,   g_ae);

    cudaFuncSetAttribute(mma_gemm, cudaFuncAttributeMaxDynamicSharedMemorySize, SMEM_TOTAL);

    // one-time prep
    {
        int n4 = (E * H) / 4;
        cvt_split<<<(n4 + 255) / 256, 256>>>(gh, ghh, ghl, n4);
        n4 = (N * D_IN) / 4;
        cvt_split<<<(n4 + 255) / 256, 256>>>(node_feats, nfh, nfl, n4);
        int totw = L * 1024 * 256 + 128 * 256;
        prep_w<<<(totw + 255) / 256, 256>>>(a_w1, eps_w1, Wn_w, L);
        csr_clear<<<(N + 255) / 256, 256>>>(N);
        csr_hist<<<(E + 255) / 256, 256>>>(dst, E);
        csr_scan<<<1, 256>>>(N, E);
        csr_scatter<<<(E + 255) / 256, 256>>>(dst, E);
    }

    const int nblkN = (N + BM - 1) / BM;
    const int nblkE = (E + BM - 1) / BM;
    const size_t nsec = (size_t)N * H;

    // input projection -> out[0:N*H] (+ bf16 split)
    mma_gemm<<<dim3(nblkN, 1, 1), NTH, SMEM_TOTAL>>>(
        nfh, nfl, N, D_IN, wnh, wnl,
        out, 0, 0, Wn_b, 99,
        nullptr, nullptr, nullptr, nullptr,
        nullptr, nullptr, nullptr, nullptr, hh, hl);

    for (int l = 0; l < L; l++) {
        const float* hcur = out + (size_t)l * N * H;
        float*       hnext = out + (size_t)(l + 1) * N * H;
        const __nv_bfloat16* WhL = Wh + (size_t)l * 1024 * 256;
        const __nv_bfloat16* WlL = Wl + (size_t)l * 1024 * 256;

        // node GEMMs: z=0 -> P1, z=1 -> P2, z=2 -> eps scalar
        mma_gemm<<<dim3(nblkN, 1, 3), NTH, SMEM_TOTAL>>>(
            hh, hl, N, H, WhL, WlL,
            gP, nsec, (size_t)256 * 256, nullptr, 2,
            eps_b1 + (size_t)l * H, eps_w2 + (size_t)l * H, eps_b2 + l, epsv,
            nullptr, nullptr, nullptr, nullptr, nullptr, nullptr);

        // edge scores -> ae
        mma_gemm<<<dim3(nblkE, 1, 1), NTH, SMEM_TOTAL>>>(
            ghh, ghl, E, H, WhL + (size_t)768 * 256, WlL + (size_t)768 * 256,
            nullptr, 0, 0, nullptr, 0,
            a_b1 + (size_t)l * H, a_w2 + (size_t)l * H, a_b2 + l, ae,
            gP, gP + nsec, src, dst, nullptr, nullptr);

        // fused message + softmax + GIN update (+ bf16 split of h_next)
        msg_update<<<(N * 32 + 255) / 256, 256>>>(
            ae, src, gh, hcur, epsv, hnext, hh, hl, N);
    }
}

// round 5
// speedup vs baseline: 2.1995x; 1.0409x over previous
#include <cuda_runtime.h>
#include <cuda_bf16.h>
#include <math.h>
#include <stdint.h>

#define H 256
#define N_MAX 10240
#define E_MAX 163840
#define L_MAX 3

#define BM 128
#define BN 256
#define BK 32
#define NTH 256

// stage layout (bytes)
#define A_H 0
#define A_L 8192
#define B_HO 16384
#define B_LO 32768
#define ST_BYTES 49152
#define NSTAGE 4
#define SMEM_TOTAL (NSTAGE * ST_BYTES)

// ---------------- scratch (device globals) ---------------------------------
__device__ __nv_bfloat16 g_ghh[E_MAX * H];
__device__ __nv_bfloat16 g_ghl[E_MAX * H];
__device__ __nv_bfloat16 g_nfh[N_MAX * 128];
__device__ __nv_bfloat16 g_nfl[N_MAX * 128];
__device__ __nv_bfloat16 g_hh[N_MAX * H];
__device__ __nv_bfloat16 g_hl[N_MAX * H];
// combined per-layer weights: rows 0-255 P1W, 256-511 P2W, 512-767 epsW,
// 768-1023 edgeW (each [256k,256n] row-major)
__device__ __nv_bfloat16 g_Wh[L_MAX * 1024 * 256];
__device__ __nv_bfloat16 g_Wl[L_MAX * 1024 * 256];
__device__ __nv_bfloat16 g_wnh[128 * 256];
__device__ __nv_bfloat16 g_wnl[128 * 256];
__device__ float g_P[2 * N_MAX * H];
__device__ float g_eps[N_MAX];
__device__ float g_ae[E_MAX];
// CSR by dst
__device__ int g_cnt[N_MAX];
__device__ int g_off[N_MAX + 1];
__device__ int g_cur[N_MAX];
__device__ int g_perm[E_MAX];

// ---------------- helpers ----------------------------------------------------
__device__ __forceinline__ uint32_t smem_u32(const void* p) {
    uint32_t a;
    asm("{ .reg .u64 t; cvta.to.shared.u64 t, %1; cvt.u32.u64 %0, t; }" : "=r"(a) : "l"(p));
    return a;
}
__device__ __forceinline__ void cp16(uint32_t dst, const void* src) {
    asm volatile("cp.async.cg.shared.global [%0], [%1], 16;" :: "r"(dst), "l"(src));
}
__device__ __forceinline__ void ldsm4(uint32_t* r, uint32_t addr) {
    asm volatile("ldmatrix.sync.aligned.m8n8.x4.shared.b16 {%0,%1,%2,%3}, [%4];"
                 : "=r"(r[0]), "=r"(r[1]), "=r"(r[2]), "=r"(r[3]) : "r"(addr));
}
__device__ __forceinline__ void ldsm4t(uint32_t* r, uint32_t addr) {
    asm volatile("ldmatrix.sync.aligned.m8n8.x4.trans.shared.b16 {%0,%1,%2,%3}, [%4];"
                 : "=r"(r[0]), "=r"(r[1]), "=r"(r[2]), "=r"(r[3]) : "r"(addr));
}
__device__ __forceinline__ void mma16816(float* c, const uint32_t* a, const uint32_t* b) {
    asm volatile("mma.sync.aligned.m16n8k16.row.col.f32.bf16.bf16.f32 "
                 "{%0,%1,%2,%3}, {%4,%5,%6,%7}, {%8,%9}, {%0,%1,%2,%3};"
                 : "+f"(c[0]), "+f"(c[1]), "+f"(c[2]), "+f"(c[3])
                 : "r"(a[0]), "r"(a[1]), "r"(a[2]), "r"(a[3]), "r"(b[0]), "r"(b[1]));
}

// ---------------- fp32 -> bf16 hi/lo split ----------------------------------
__global__ void cvt_split(const float* __restrict__ x, __nv_bfloat16* __restrict__ hi,
                          __nv_bfloat16* __restrict__ lo, int n4)
{
    int i = blockIdx.x * blockDim.x + threadIdx.x;
    if (i >= n4) return;
    float4 v = ((const float4*)x)[i];
    __nv_bfloat16 h0 = __float2bfloat16(v.x), h1 = __float2bfloat16(v.y);
    __nv_bfloat16 h2 = __float2bfloat16(v.z), h3 = __float2bfloat16(v.w);
    __nv_bfloat16 l0 = __float2bfloat16(v.x - __bfloat162float(h0));
    __nv_bfloat16 l1 = __float2bfloat16(v.y - __bfloat162float(h1));
    __nv_bfloat16 l2 = __float2bfloat16(v.z - __bfloat162float(h2));
    __nv_bfloat16 l3 = __float2bfloat16(v.w - __bfloat162float(h3));
    __nv_bfloat162 hh0(h0, h1), hh1(h2, h3), ll0(l0, l1), ll1(l2, l3);
    ((__nv_bfloat162*)hi)[i * 2 + 0] = hh0;
    ((__nv_bfloat162*)hi)[i * 2 + 1] = hh1;
    ((__nv_bfloat162*)lo)[i * 2 + 0] = ll0;
    ((__nv_bfloat162*)lo)[i * 2 + 1] = ll1;
}

// ---------------- weight prep ------------------------------------------------
__global__ void prep_w(const float* __restrict__ a_w1, const float* __restrict__ eps_w1,
                       const float* __restrict__ Wn_w, int L)
{
    const int totW = L * 1024 * 256;
    const int total = totW + 128 * 256;
    int idx = blockIdx.x * blockDim.x + threadIdx.x;
    if (idx >= total) return;
    float v;
    __nv_bfloat16 *dh, *dl;
    int di;
    if (idx < totW) {
        int l = idx / (1024 * 256);
        int r = (idx / 256) % 1024;
        int n = idx % 256;
        if (r < 512)      v = a_w1[((size_t)l * 768 + r) * 256 + n];
        else if (r < 768) v = eps_w1[((size_t)l * 256 + (r - 512)) * 256 + n];
        else              v = a_w1[((size_t)l * 768 + 512 + (r - 768)) * 256 + n];
        dh = g_Wh; dl = g_Wl; di = idx;
    } else {
        int i2 = idx - totW;
        v = Wn_w[i2];
        dh = g_wnh; dl = g_wnl; di = i2;
    }
    __nv_bfloat16 h = __float2bfloat16(v);
    dh[di] = h;
    dl[di] = __float2bfloat16(v - __bfloat162float(h));
}

// ---------------- CSR build ---------------------------------------------------
__global__ void csr_clear(int N) {
    int i = blockIdx.x * blockDim.x + threadIdx.x;
    if (i < N) g_cnt[i] = 0;
}
__global__ void csr_hist(const int* __restrict__ dst, int E) {
    int e = blockIdx.x * blockDim.x + threadIdx.x;
    if (e < E) atomicAdd(&g_cnt[dst[e]], 1);
}
__global__ void csr_scan(int N, int E) {
    __shared__ int sums[256];
    const int tid = threadIdx.x;
    const int chunk = (N + 255) / 256;
    const int base = tid * chunk;
    int s = 0;
    for (int i = 0; i < chunk; i++) {
        int idx = base + i;
        if (idx < N) s += g_cnt[idx];
    }
    sums[tid] = s;
    __syncthreads();
    for (int d = 1; d < 256; d <<= 1) {
        int v = (tid >= d) ? sums[tid - d] : 0;
        __syncthreads();
        sums[tid] += v;
        __syncthreads();
    }
    int run = sums[tid] - s;
    for (int i = 0; i < chunk; i++) {
        int idx = base + i;
        if (idx < N) { g_off[idx] = run; g_cur[idx] = run; run += g_cnt[idx]; }
    }
    if (tid == 255) g_off[N] = E;
}
__global__ void csr_scatter(const int* __restrict__ dst, int E) {
    int e = blockIdx.x * blockDim.x + threadIdx.x;
    if (e < E) {
        int pos = atomicAdd(&g_cur[dst[e]], 1);
        g_perm[pos] = e;
    }
}

// ---------------- bf16-split tensor-core GEMM (BM=128, BN=256) ---------------
__global__ void __launch_bounds__(NTH, 1)
mma_gemm(const __nv_bfloat16* __restrict__ Ah, const __nv_bfloat16* __restrict__ Al,
         int M, int K,
         const __nv_bfloat16* __restrict__ Bh, const __nv_bfloat16* __restrict__ Bl,
         float* __restrict__ C, size_t zstrC, size_t zstrB,
         const float* __restrict__ bias, int scalar_z,
         const float* __restrict__ sbias, const float* __restrict__ w2,
         const float* __restrict__ b2, float* __restrict__ sout,
         const float* __restrict__ P1, const float* __restrict__ P2,
         const int* __restrict__ src, const int* __restrict__ dst,
         __nv_bfloat16* __restrict__ bfh, __nv_bfloat16* __restrict__ bfl)
{
    extern __shared__ char smem[];
    const uint32_t sb = smem_u32(smem);
    const int tid = threadIdx.x;
    const int lane = tid & 31;
    const int wid = tid >> 5;
    const int wm = wid & 3;
    const int wn = wid >> 2;
    const int m0 = blockIdx.x * BM;
    const int z = blockIdx.z;
    const int nchunks = K / BK;

    const __nv_bfloat16* Bhz = Bh + zstrB * z;
    const __nv_bfloat16* Blz = Bl + zstrB * z;

    float acc[2][16][4];
#pragma unroll
    for (int mi = 0; mi < 2; mi++)
#pragma unroll
        for (int nj = 0; nj < 16; nj++)
#pragma unroll
            for (int q = 0; q < 4; q++) acc[mi][nj][q] = 0.f;

    auto load_stage = [&](int s, int k0) {
        const uint32_t base = sb + s * ST_BYTES;
#pragma unroll
        for (int i = 0; i < 2; i++) {
            int cid = tid + i * NTH;
            int row = cid >> 2;
            int cb = (cid & 3) * 16;
            int grow = m0 + row;
            if (grow >= M) grow = M - 1;
            size_t gb = ((size_t)grow * K + k0) * 2 + cb;
            uint32_t d = base + row * 64 + (cb ^ ((row & 3) << 4));
            cp16(d + A_H, (const char*)Ah + gb);
            cp16(d + A_L, (const char*)Al + gb);
        }
#pragma unroll
        for (int i = 0; i < 4; i++) {
            int cid = tid + i * NTH;
            int k = cid >> 5;
            int cb = (cid & 31) * 16;
            size_t gb = (size_t)(k0 + k) * 512 + cb;
            uint32_t d = base + k * 512 + (cb ^ ((k & 7) << 4));
            cp16(d + B_HO, (const char*)Bhz + gb);
            cp16(d + B_LO, (const char*)Blz + gb);
        }
        asm volatile("cp.async.commit_group;" ::: "memory");
    };

    auto compute_stage = [&](int s) {
        const uint32_t base = sb + s * ST_BYTES;
#pragma unroll
        for (int kk = 0; kk < 2; kk++) {
            uint32_t ah[2][4], al[2][4];
#pragma unroll
            for (int mi = 0; mi < 2; mi++) {
                int row = wm * 32 + mi * 16 + (lane & 15);
                uint32_t cb = kk * 32 + ((lane >> 4) << 4);
                uint32_t ad = base + row * 64 + (cb ^ ((row & 3) << 4));
                ldsm4(ah[mi], ad + A_H);
                ldsm4(al[mi], ad + A_L);
            }
            const int kr = kk * 16 + (lane & 15);
            const uint32_t hi16 = (lane >> 4) << 4;
            // software-pipelined B fragments (prefetch depth 1)
            uint32_t bhA[4], blA[4], bhB[4], blB[4];
            {
                uint32_t cb = wn * 256 + 0 * 32 + hi16;
                uint32_t bd = base + kr * 512 + (cb ^ ((kr & 7) << 4));
                ldsm4t(bhA, bd + B_HO);
                ldsm4t(blA, bd + B_LO);
            }
#pragma unroll
            for (int nj2 = 0; nj2 < 8; nj2++) {
                uint32_t* ch = (nj2 & 1) ? bhB : bhA;
                uint32_t* cl = (nj2 & 1) ? blB : blA;
                if (nj2 < 7) {
                    uint32_t* nh = (nj2 & 1) ? bhA : bhB;
                    uint32_t* nl = (nj2 & 1) ? blA : blB;
                    uint32_t cb = wn * 256 + (nj2 + 1) * 32 + hi16;
                    uint32_t bd = base + kr * 512 + (cb ^ ((kr & 7) << 4));
                    ldsm4t(nh, bd + B_HO);
                    ldsm4t(nl, bd + B_LO);
                }
#pragma unroll
                for (int mi = 0; mi < 2; mi++)
#pragma unroll
                    for (int sub = 0; sub < 2; sub++) {
                        int nj = nj2 * 2 + sub;
                        mma16816(acc[mi][nj], ah[mi], &ch[sub * 2]);
                        mma16816(acc[mi][nj], al[mi], &ch[sub * 2]);
                        mma16816(acc[mi][nj], ah[mi], &cl[sub * 2]);
                    }
            }
        }
    };

    // 4-stage pipeline
    for (int p = 0; p < 3 && p < nchunks; p++) load_stage(p, p * BK);
    for (int c = 0; c < nchunks; c++) {
        if (c + 3 < nchunks) load_stage((c + 3) & 3, (c + 3) * BK);
        else asm volatile("cp.async.commit_group;" ::: "memory");
        asm volatile("cp.async.wait_group 2;" ::: "memory");
        __syncthreads();
        compute_stage(c & 3);
        __syncthreads();
    }

    if (z < scalar_z) {
        float* Cz = C + zstrC * z;
#pragma unroll
        for (int mi = 0; mi < 2; mi++) {
#pragma unroll
            for (int half = 0; half < 2; half++) {
                int row = m0 + wm * 32 + mi * 16 + half * 8 + (lane >> 2);
                if (row >= M) continue;
                float* cr = Cz + (size_t)row * 256;
#pragma unroll
                for (int nj = 0; nj < 16; nj++) {
                    int col = wn * 128 + nj * 8 + (lane & 3) * 2;
                    float2 v;
                    v.x = acc[mi][nj][half * 2 + 0];
                    v.y = acc[mi][nj][half * 2 + 1];
                    if (bias) { v.x += bias[col]; v.y += bias[col + 1]; }
                    *(float2*)(cr + col) = v;
                    if (bfh) {
                        __nv_bfloat16 b0 = __float2bfloat16(v.x);
                        __nv_bfloat16 b1 = __float2bfloat16(v.y);
                        __nv_bfloat162 hp(b0, b1);
                        __nv_bfloat162 lp(__float2bfloat16(v.x - __bfloat162float(b0)),
                                          __float2bfloat16(v.y - __bfloat162float(b1)));
                        *(__nv_bfloat162*)(bfh + (size_t)row * 256 + col) = hp;
                        *(__nv_bfloat162*)(bfl + (size_t)row * 256 + col) = lp;
                    }
                }
            }
        }
    } else {
        float* sred = (float*)smem;   // [128][2]
#pragma unroll
        for (int mi = 0; mi < 2; mi++) {
#pragma unroll
            for (int half = 0; half < 2; half++) {
                int rowl = wm * 32 + mi * 16 + half * 8 + (lane >> 2);
                int row = m0 + rowl;
                int cl = (row < M) ? row : (M - 1);
                const float* p1 = P1 ? (P1 + (size_t)src[cl] * 256) : nullptr;
                const float* p2 = P2 ? (P2 + (size_t)dst[cl] * 256) : nullptr;
                float part = 0.f;
#pragma unroll
                for (int nj = 0; nj < 16; nj++) {
                    int col = wn * 128 + nj * 8 + (lane & 3) * 2;
                    float2 bv = *(const float2*)(sbias + col);
                    float2 wv = *(const float2*)(w2 + col);
                    float2 p1v = make_float2(0.f, 0.f), p2v = make_float2(0.f, 0.f);
                    if (p1) p1v = *(const float2*)(p1 + col);
                    if (p2) p2v = *(const float2*)(p2 + col);
                    float v0 = fmaxf(acc[mi][nj][half * 2 + 0] + bv.x + p1v.x + p2v.x, 0.f);
                    float v1 = fmaxf(acc[mi][nj][half * 2 + 1] + bv.y + p1v.y + p2v.y, 0.f);
                    part = fmaf(v0, wv.x, part);
                    part = fmaf(v1, wv.y, part);
                }
                part += __shfl_xor_sync(0xffffffffu, part, 1);
                part += __shfl_xor_sync(0xffffffffu, part, 2);
                if ((lane & 3) == 0) sred[rowl * 2 + wn] = part;
            }
        }
        __syncthreads();
        if (tid < 128) {
            int row = m0 + tid;
            if (row < M) sout[row] = sred[tid * 2] + sred[tid * 2 + 1] + b2[0];
        }
    }
}

// ---------------- fused message + softmax + update (warp per node) -----------
// two-phase: (1) lane-parallel max & denom, (2) dependency-free accumulation
__global__ void msg_update(const float* __restrict__ ae, const int* __restrict__ src,
                           const float* __restrict__ gh, const float* __restrict__ h_old,
                           const float* __restrict__ epsv,
                           float* __restrict__ h_new,
                           __nv_bfloat16* __restrict__ hh, __nv_bfloat16* __restrict__ hl,
                           int N)
{
    const int w = (blockIdx.x * blockDim.x + threadIdx.x) >> 5;
    const int lane = threadIdx.x & 31;
    if (w >= N) return;
    const int lo = g_off[w], hi = g_off[w + 1];

    float4 a0 = make_float4(0.f, 0.f, 0.f, 0.f);
    float4 a1 = make_float4(0.f, 0.f, 0.f, 0.f);
    float s = 0.f;

    if (hi > lo) {
        // phase 1: max
        float mym = -INFINITY;
        for (int j = lo + lane; j < hi; j += 32)
            mym = fmaxf(mym, ae[g_perm[j]]);
#pragma unroll
        for (int o = 16; o; o >>= 1)
            mym = fmaxf(mym, __shfl_xor_sync(0xffffffffu, mym, o));
        const float m = mym;
        // phase 2: denom + accumulation (no carried dependency)
        for (int base = lo; base < hi; base += 32) {
            const int j = base + lane;
            int e = 0, sr = 0;
            float c = 0.f;
            if (j < hi) {
                e = g_perm[j];
                c = __expf(ae[e] - m);
                sr = src[e];
            }
            s += c;
            const int cnt = min(32, hi - base);
            for (int i = 0; i < cnt; i++) {
                const float ci = __shfl_sync(0xffffffffu, c, i);
                const int ei = __shfl_sync(0xffffffffu, e, i);
                const int si = __shfl_sync(0xffffffffu, sr, i);
                const float4* g4 = (const float4*)(gh + (size_t)ei * H);
                const float4* h4 = (const float4*)(h_old + (size_t)si * H);
                float4 g = g4[lane], hv = h4[lane];
                a0.x = fmaf(ci * g.x, hv.x, a0.x);
                a0.y = fmaf(ci * g.y, hv.y, a0.y);
                a0.z = fmaf(ci * g.z, hv.z, a0.z);
                a0.w = fmaf(ci * g.w, hv.w, a0.w);
                g = g4[lane + 32]; hv = h4[lane + 32];
                a1.x = fmaf(ci * g.x, hv.x, a1.x);
                a1.y = fmaf(ci * g.y, hv.y, a1.y);
                a1.z = fmaf(ci * g.z, hv.z, a1.z);
                a1.w = fmaf(ci * g.w, hv.w, a1.w);
            }
        }
#pragma unroll
        for (int o = 16; o; o >>= 1)
            s += __shfl_xor_sync(0xffffffffu, s, o);
    }

    const float inv = (s > 0.f) ? (1.f / s) : 0.f;
    const float scale = (1.f + epsv[w]) * inv;

    const float4* hrow = (const float4*)(h_old + (size_t)w * H);
    float4 o0 = hrow[lane], o1 = hrow[lane + 32];
    float4 r0, r1;
    r0.x = fmaf(a0.x, scale, o0.x); r0.y = fmaf(a0.y, scale, o0.y);
    r0.z = fmaf(a0.z, scale, o0.z); r0.w = fmaf(a0.w, scale, o0.w);
    r1.x = fmaf(a1.x, scale, o1.x); r1.y = fmaf(a1.y, scale, o1.y);
    r1.z = fmaf(a1.z, scale, o1.z); r1.w = fmaf(a1.w, scale, o1.w);
    ((float4*)(h_new + (size_t)w * H))[lane] = r0;
    ((float4*)(h_new + (size_t)w * H))[lane + 32] = r1;

    auto wr = [&](float4 v, int c) {
        __nv_bfloat16 b0 = __float2bfloat16(v.x), b1 = __float2bfloat16(v.y);
        __nv_bfloat16 b2 = __float2bfloat16(v.z), b3 = __float2bfloat16(v.w);
        __nv_bfloat162 hp0(b0, b1), hp1(b2, b3);
        __nv_bfloat162 lp0(__float2bfloat16(v.x - __bfloat162float(b0)),
                           __float2bfloat16(v.y - __bfloat162float(b1)));
        __nv_bfloat162 lp1(__float2bfloat16(v.z - __bfloat162float(b2)),
                           __float2bfloat16(v.w - __bfloat162float(b3)));
        *(__nv_bfloat162*)(hh + (size_t)w * H + c) = hp0;
        *(__nv_bfloat162*)(hh + (size_t)w * H + c + 2) = hp1;
        *(__nv_bfloat162*)(hl + (size_t)w * H + c) = lp0;
        *(__nv_bfloat162*)(hl + (size_t)w * H + c + 2) = lp1;
    };
    wr(r0, lane * 4);
    wr(r1, 128 + lane * 4);
}

// ---------------- launch -------------------------------------------------------
extern "C" void kernel_launch(void* const* d_in, const int* in_sizes, int n_in,
                              void* d_out, int out_size)
{
    (void)n_in; (void)out_size;
    const float* node_feats = (const float*)d_in[0];
    const float* gh         = (const float*)d_in[1];
    const int*   src        = (const int*)d_in[2];
    const int*   dst        = (const int*)d_in[3];
    const float* Wn_w       = (const float*)d_in[4];
    const float* Wn_b       = (const float*)d_in[5];
    const float* eps_w1     = (const float*)d_in[6];
    const float* eps_b1     = (const float*)d_in[7];
    const float* eps_w2     = (const float*)d_in[8];
    const float* eps_b2     = (const float*)d_in[9];
    const float* a_w1       = (const float*)d_in[10];
    const float* a_b1       = (const float*)d_in[11];
    const float* a_w2       = (const float*)d_in[12];
    const float* a_b2       = (const float*)d_in[13];

    const int D_IN = 128;
    const int N = in_sizes[0] / D_IN;
    const int E = in_sizes[2];
    const int L = in_sizes[6] / (H * H);

    float* out = (float*)d_out;

    __nv_bfloat16 *ghh, *ghl, *nfh, *nfl, *hh, *hl, *Wh, *Wl, *wnh, *wnl;
    float *gP, *epsv, *ae;
    cudaGetSymbolAddress((void**)&ghh, g_ghh);
    cudaGetSymbolAddress((void**)&ghl, g_ghl);
    cudaGetSymbolAddress((void**)&nfh, g_nfh);
    cudaGetSymbolAddress((void**)&nfl, g_nfl);
    cudaGetSymbolAddress((void**)&hh,  g_hh);
    cudaGetSymbolAddress((void**)&hl,  g_hl);
    cudaGetSymbolAddress((void**)&Wh,  g_Wh);
    cudaGetSymbolAddress((void**)&Wl,  g_Wl);
    cudaGetSymbolAddress((void**)&wnh, g_wnh);
    cudaGetSymbolAddress((void**)&wnl, g_wnl);
    cudaGetSymbolAddress((void**)&gP,   g_P);
    cudaGetSymbolAddress((void**)&epsv, g_eps);
    cudaGetSymbolAddress((void**)&ae,   g_ae);

    cudaFuncSetAttribute(mma_gemm, cudaFuncAttributeMaxDynamicSharedMemorySize, SMEM_TOTAL);

    // one-time prep
    {
        int n4 = (E * H) / 4;
        cvt_split<<<(n4 + 255) / 256, 256>>>(gh, ghh, ghl, n4);
        n4 = (N * D_IN) / 4;
        cvt_split<<<(n4 + 255) / 256, 256>>>(node_feats, nfh, nfl, n4);
        int totw = L * 1024 * 256 + 128 * 256;
        prep_w<<<(totw + 255) / 256, 256>>>(a_w1, eps_w1, Wn_w, L);
        csr_clear<<<(N + 255) / 256, 256>>>(N);
        csr_hist<<<(E + 255) / 256, 256>>>(dst, E);
        csr_scan<<<1, 256>>>(N, E);
        csr_scatter<<<(E + 255) / 256, 256>>>(dst, E);
    }

    const int nblkN = (N + BM - 1) / BM;
    const int nblkE = (E + BM - 1) / BM;
    const size_t nsec = (size_t)N * H;

    // input projection -> out[0:N*H] (+ bf16 split)
    mma_gemm<<<dim3(nblkN, 1, 1), NTH, SMEM_TOTAL>>>(
        nfh, nfl, N, D_IN, wnh, wnl,
        out, 0, 0, Wn_b, 99,
        nullptr, nullptr, nullptr, nullptr,
        nullptr, nullptr, nullptr, nullptr, hh, hl);

    for (int l = 0; l < L; l++) {
        const float* hcur = out + (size_t)l * N * H;
        float*       hnext = out + (size_t)(l + 1) * N * H;
        const __nv_bfloat16* WhL = Wh + (size_t)l * 1024 * 256;
        const __nv_bfloat16* WlL = Wl + (size_t)l * 1024 * 256;

        // node GEMMs: z=0 -> P1, z=1 -> P2, z=2 -> eps scalar
        mma_gemm<<<dim3(nblkN, 1, 3), NTH, SMEM_TOTAL>>>(
            hh, hl, N, H, WhL, WlL,
            gP, nsec, (size_t)256 * 256, nullptr, 2,
            eps_b1 + (size_t)l * H, eps_w2 + (size_t)l * H, eps_b2 + l, epsv,
            nullptr, nullptr, nullptr, nullptr, nullptr, nullptr);

        // edge scores -> ae
        mma_gemm<<<dim3(nblkE, 1, 1), NTH, SMEM_TOTAL>>>(
            ghh, ghl, E, H, WhL + (size_t)768 * 256, WlL + (size_t)768 * 256,
            nullptr, 0, 0, nullptr, 0,
            a_b1 + (size_t)l * H, a_w2 + (size_t)l * H, a_b2 + l, ae,
            gP, gP + nsec, src, dst, nullptr, nullptr);

        // fused message + softmax + GIN update (+ bf16 split of h_next)
        msg_update<<<(N * 32 + 255) / 256, 256>>>(
            ae, src, gh, hcur, epsv, hnext, hh, hl, N);
    }
}

// round 6
// speedup vs baseline: 2.6448x; 1.2024x over previous
#include <cuda_runtime.h>
#include <cuda_fp16.h>
#include <math.h>
#include <stdint.h>

#define H 256
#define N_MAX 10240
#define E_MAX 163840
#define L_MAX 3

#define BM 128
#define BN 256
#define BK 32
#define NTH 256
#define NSTAGE 4

// ---------------- scratch (device globals) ---------------------------------
__device__ __half g_ghh[E_MAX * H];            // gh fp16 (single)
__device__ __half g_nfh[N_MAX * 128];
__device__ __half g_nfl[N_MAX * 128];
__device__ __half g_hh[N_MAX * H];
__device__ __half g_hl[N_MAX * H];
// combined per-layer weights: rows 0-255 P1W, 256-511 P2W, 512-767 epsW,
// 768-1023 edgeW (each [256k,256n] row-major)
__device__ __half g_Wh[L_MAX * 1024 * 256];
__device__ __half g_Wl[L_MAX * 1024 * 256];
__device__ __half g_wnh[128 * 256];
__device__ __half g_wnl[128 * 256];
__device__ float g_P[2 * N_MAX * H];
__device__ float g_eps[N_MAX];
__device__ float g_ae[E_MAX];
// CSR by dst
__device__ int g_cnt[N_MAX];
__device__ int g_off[N_MAX + 1];
__device__ int g_cur[N_MAX];
__device__ int g_perm[E_MAX];

// ---------------- helpers ----------------------------------------------------
__device__ __forceinline__ uint32_t smem_u32(const void* p) {
    uint32_t a;
    asm("{ .reg .u64 t; cvta.to.shared.u64 t, %1; cvt.u32.u64 %0, t; }" : "=r"(a) : "l"(p));
    return a;
}
__device__ __forceinline__ void cp16(uint32_t dst, const void* src) {
    asm volatile("cp.async.cg.shared.global [%0], [%1], 16;" :: "r"(dst), "l"(src));
}
__device__ __forceinline__ void ldsm4(uint32_t* r, uint32_t addr) {
    asm volatile("ldmatrix.sync.aligned.m8n8.x4.shared.b16 {%0,%1,%2,%3}, [%4];"
                 : "=r"(r[0]), "=r"(r[1]), "=r"(r[2]), "=r"(r[3]) : "r"(addr));
}
__device__ __forceinline__ void ldsm4t(uint32_t* r, uint32_t addr) {
    asm volatile("ldmatrix.sync.aligned.m8n8.x4.trans.shared.b16 {%0,%1,%2,%3}, [%4];"
                 : "=r"(r[0]), "=r"(r[1]), "=r"(r[2]), "=r"(r[3]) : "r"(addr));
}
__device__ __forceinline__ void mma16816(float* c, const uint32_t* a, const uint32_t* b) {
    asm volatile("mma.sync.aligned.m16n8k16.row.col.f32.f16.f16.f32 "
                 "{%0,%1,%2,%3}, {%4,%5,%6,%7}, {%8,%9}, {%0,%1,%2,%3};"
                 : "+f"(c[0]), "+f"(c[1]), "+f"(c[2]), "+f"(c[3])
                 : "r"(a[0]), "r"(a[1]), "r"(a[2]), "r"(a[3]), "r"(b[0]), "r"(b[1]));
}

// ---------------- fp32 -> fp16 hi(/lo) split ---------------------------------
__global__ void cvt_split(const float* __restrict__ x, __half* __restrict__ hi,
                          __half* __restrict__ lo, int n4)
{
    int i = blockIdx.x * blockDim.x + threadIdx.x;
    if (i >= n4) return;
    float4 v = ((const float4*)x)[i];
    __half h0 = __float2half(v.x), h1 = __float2half(v.y);
    __half h2 = __float2half(v.z), h3 = __float2half(v.w);
    __half2 hh0(h0, h1), hh1(h2, h3);
    ((__half2*)hi)[i * 2 + 0] = hh0;
    ((__half2*)hi)[i * 2 + 1] = hh1;
    if (lo) {
        __half2 ll0(__float2half(v.x - __half2float(h0)),
                    __float2half(v.y - __half2float(h1)));
        __half2 ll1(__float2half(v.z - __half2float(h2)),
                    __float2half(v.w - __half2float(h3)));
        ((__half2*)lo)[i * 2 + 0] = ll0;
        ((__half2*)lo)[i * 2 + 1] = ll1;
    }
}

// ---------------- weight prep ------------------------------------------------
__global__ void prep_w(const float* __restrict__ a_w1, const float* __restrict__ eps_w1,
                       const float* __restrict__ Wn_w, int L)
{
    const int totW = L * 1024 * 256;
    const int total = totW + 128 * 256;
    int idx = blockIdx.x * blockDim.x + threadIdx.x;
    if (idx >= total) return;
    float v;
    __half *dh, *dl;
    int di;
    if (idx < totW) {
        int l = idx / (1024 * 256);
        int r = (idx / 256) % 1024;
        int n = idx % 256;
        if (r < 512)      v = a_w1[((size_t)l * 768 + r) * 256 + n];
        else if (r < 768) v = eps_w1[((size_t)l * 256 + (r - 512)) * 256 + n];
        else              v = a_w1[((size_t)l * 768 + 512 + (r - 768)) * 256 + n];
        dh = g_Wh; dl = g_Wl; di = idx;
    } else {
        int i2 = idx - totW;
        v = Wn_w[i2];
        dh = g_wnh; dl = g_wnl; di = i2;
    }
    __half h = __float2half(v);
    dh[di] = h;
    dl[di] = __float2half(v - __half2float(h));
}

// ---------------- CSR build ---------------------------------------------------
__global__ void csr_clear(int N) {
    int i = blockIdx.x * blockDim.x + threadIdx.x;
    if (i < N) g_cnt[i] = 0;
}
__global__ void csr_hist(const int* __restrict__ dst, int E) {
    int e = blockIdx.x * blockDim.x + threadIdx.x;
    if (e < E) atomicAdd(&g_cnt[dst[e]], 1);
}
__global__ void csr_scan(int N, int E) {
    __shared__ int sums[256];
    const int tid = threadIdx.x;
    const int chunk = (N + 255) / 256;
    const int base = tid * chunk;
    int s = 0;
    for (int i = 0; i < chunk; i++) {
        int idx = base + i;
        if (idx < N) s += g_cnt[idx];
    }
    sums[tid] = s;
    __syncthreads();
    for (int d = 1; d < 256; d <<= 1) {
        int v = (tid >= d) ? sums[tid - d] : 0;
        __syncthreads();
        sums[tid] += v;
        __syncthreads();
    }
    int run = sums[tid] - s;
    for (int i = 0; i < chunk; i++) {
        int idx = base + i;
        if (idx < N) { g_off[idx] = run; g_cur[idx] = run; run += g_cnt[idx]; }
    }
    if (tid == 255) g_off[N] = E;
}
__global__ void csr_scatter(const int* __restrict__ dst, int E) {
    int e = blockIdx.x * blockDim.x + threadIdx.x;
    if (e < E) {
        int pos = atomicAdd(&g_cur[dst[e]], 1);
        g_perm[pos] = e;
    }
}

// ---------------- fp16-split tensor-core GEMM (BM=128, BN=256) ---------------
// TERMS=3: D = Ah*Bh + Al*Bh + Ah*Bl ; TERMS=2: D = Ah*Bh + Ah*Bl
template <int TERMS>
__global__ void __launch_bounds__(NTH, 1)
mma_gemm(const __half* __restrict__ Ah, const __half* __restrict__ Al,
         int M, int K,
         const __half* __restrict__ Bh, const __half* __restrict__ Bl,
         float* __restrict__ C, size_t zstrC, size_t zstrB,
         const float* __restrict__ bias, int scalar_z,
         const float* __restrict__ sbias, const float* __restrict__ w2,
         const float* __restrict__ b2, float* __restrict__ sout,
         const float* __restrict__ P1, const float* __restrict__ P2,
         const int* __restrict__ src, const int* __restrict__ dst,
         __half* __restrict__ ohh, __half* __restrict__ ohl)
{
    constexpr uint32_t AH_OFF = 0;
    constexpr uint32_t AL_OFF = 8192;
    constexpr uint32_t BH_OFF = (TERMS == 3) ? 16384u : 8192u;
    constexpr uint32_t BL_OFF = BH_OFF + 16384u;
    constexpr uint32_t STB = BL_OFF + 16384u;

    extern __shared__ char smem[];
    const uint32_t sb = smem_u32(smem);
    const int tid = threadIdx.x;
    const int lane = tid & 31;
    const int wid = tid >> 5;
    const int wm = wid & 3;
    const int wn = wid >> 2;
    const int m0 = blockIdx.x * BM;
    const int z = blockIdx.z;
    const int nchunks = K / BK;

    const __half* Bhz = Bh + zstrB * z;
    const __half* Blz = Bl + zstrB * z;

    float acc[2][16][4];
#pragma unroll
    for (int mi = 0; mi < 2; mi++)
#pragma unroll
        for (int nj = 0; nj < 16; nj++)
#pragma unroll
            for (int q = 0; q < 4; q++) acc[mi][nj][q] = 0.f;

    auto load_stage = [&](int s, int k0) {
        const uint32_t base = sb + s * STB;
#pragma unroll
        for (int i = 0; i < 2; i++) {
            int cid = tid + i * NTH;
            int row = cid >> 2;
            int cb = (cid & 3) * 16;
            int grow = m0 + row;
            if (grow >= M) grow = M - 1;
            size_t gb = ((size_t)grow * K + k0) * 2 + cb;
            uint32_t d = base + row * 64 + (cb ^ ((row & 3) << 4));
            cp16(d + AH_OFF, (const char*)Ah + gb);
            if (TERMS == 3) cp16(d + AL_OFF, (const char*)Al + gb);
        }
#pragma unroll
        for (int i = 0; i < 4; i++) {
            int cid = tid + i * NTH;
            int k = cid >> 5;
            int cb = (cid & 31) * 16;
            size_t gb = (size_t)(k0 + k) * 512 + cb;
            uint32_t d = base + k * 512 + (cb ^ ((k & 7) << 4));
            cp16(d + BH_OFF, (const char*)Bhz + gb);
            cp16(d + BL_OFF, (const char*)Blz + gb);
        }
        asm volatile("cp.async.commit_group;" ::: "memory");
    };

    auto compute_stage = [&](int s) {
        const uint32_t base = sb + s * STB;
#pragma unroll
        for (int kk = 0; kk < 2; kk++) {
            uint32_t ah[2][4], al[2][4];
#pragma unroll
            for (int mi = 0; mi < 2; mi++) {
                int row = wm * 32 + mi * 16 + (lane & 15);
                uint32_t cb = kk * 32 + ((lane >> 4) << 4);
                uint32_t ad = base + row * 64 + (cb ^ ((row & 3) << 4));
                ldsm4(ah[mi], ad + AH_OFF);
                if (TERMS == 3) ldsm4(al[mi], ad + AL_OFF);
            }
            const int kr = kk * 16 + (lane & 15);
            const uint32_t hi16 = (lane >> 4) << 4;
            uint32_t bhA[4], blA[4], bhB[4], blB[4];
            {
                uint32_t cb = wn * 256 + 0 * 32 + hi16;
                uint32_t bd = base + kr * 512 + (cb ^ ((kr & 7) << 4));
                ldsm4t(bhA, bd + BH_OFF);
                ldsm4t(blA, bd + BL_OFF);
            }
#pragma unroll
            for (int nj2 = 0; nj2 < 8; nj2++) {
                uint32_t* ch = (nj2 & 1) ? bhB : bhA;
                uint32_t* cl = (nj2 & 1) ? blB : blA;
                if (nj2 < 7) {
                    uint32_t* nh = (nj2 & 1) ? bhA : bhB;
                    uint32_t* nl = (nj2 & 1) ? blA : blB;
                    uint32_t cb = wn * 256 + (nj2 + 1) * 32 + hi16;
                    uint32_t bd = base + kr * 512 + (cb ^ ((kr & 7) << 4));
                    ldsm4t(nh, bd + BH_OFF);
                    ldsm4t(nl, bd + BL_OFF);
                }
#pragma unroll
                for (int mi = 0; mi < 2; mi++)
#pragma unroll
                    for (int sub = 0; sub < 2; sub++) {
                        int nj = nj2 * 2 + sub;
                        mma16816(acc[mi][nj], ah[mi], &ch[sub * 2]);
                        if (TERMS == 3) mma16816(acc[mi][nj], al[mi], &ch[sub * 2]);
                        mma16816(acc[mi][nj], ah[mi], &cl[sub * 2]);
                    }
            }
        }
    };

    for (int p = 0; p < 3 && p < nchunks; p++) load_stage(p, p * BK);
    for (int c = 0; c < nchunks; c++) {
        if (c + 3 < nchunks) load_stage((c + 3) & 3, (c + 3) * BK);
        else asm volatile("cp.async.commit_group;" ::: "memory");
        asm volatile("cp.async.wait_group 2;" ::: "memory");
        __syncthreads();
        compute_stage(c & 3);
        __syncthreads();
    }

    if (z < scalar_z) {
        float* Cz = C + zstrC * z;
#pragma unroll
        for (int mi = 0; mi < 2; mi++) {
#pragma unroll
            for (int half = 0; half < 2; half++) {
                int row = m0 + wm * 32 + mi * 16 + half * 8 + (lane >> 2);
                if (row >= M) continue;
                float* cr = Cz + (size_t)row * 256;
#pragma unroll
                for (int nj = 0; nj < 16; nj++) {
                    int col = wn * 128 + nj * 8 + (lane & 3) * 2;
                    float2 v;
                    v.x = acc[mi][nj][half * 2 + 0];
                    v.y = acc[mi][nj][half * 2 + 1];
                    if (bias) { v.x += bias[col]; v.y += bias[col + 1]; }
                    *(float2*)(cr + col) = v;
                    if (ohh) {
                        __half b0 = __float2half(v.x);
                        __half b1 = __float2half(v.y);
                        __half2 hp(b0, b1);
                        __half2 lp(__float2half(v.x - __half2float(b0)),
                                   __float2half(v.y - __half2float(b1)));
                        *(__half2*)(ohh + (size_t)row * 256 + col) = hp;
                        *(__half2*)(ohl + (size_t)row * 256 + col) = lp;
                    }
                }
            }
        }
    } else {
        float* sred = (float*)smem;   // [128][2]
#pragma unroll
        for (int mi = 0; mi < 2; mi++) {
#pragma unroll
            for (int half = 0; half < 2; half++) {
                int rowl = wm * 32 + mi * 16 + half * 8 + (lane >> 2);
                int row = m0 + rowl;
                int cl = (row < M) ? row : (M - 1);
                const float* p1 = P1 ? (P1 + (size_t)src[cl] * 256) : nullptr;
                const float* p2 = P2 ? (P2 + (size_t)dst[cl] * 256) : nullptr;
                float part = 0.f;
#pragma unroll
                for (int nj = 0; nj < 16; nj++) {
                    int col = wn * 128 + nj * 8 + (lane & 3) * 2;
                    float2 bv = *(const float2*)(sbias + col);
                    float2 wv = *(const float2*)(w2 + col);
                    float2 p1v = make_float2(0.f, 0.f), p2v = make_float2(0.f, 0.f);
                    if (p1) p1v = *(const float2*)(p1 + col);
                    if (p2) p2v = *(const float2*)(p2 + col);
                    float v0 = fmaxf(acc[mi][nj][half * 2 + 0] + bv.x + p1v.x + p2v.x, 0.f);
                    float v1 = fmaxf(acc[mi][nj][half * 2 + 1] + bv.y + p1v.y + p2v.y, 0.f);
                    part = fmaf(v0, wv.x, part);
                    part = fmaf(v1, wv.y, part);
                }
                part += __shfl_xor_sync(0xffffffffu, part, 1);
                part += __shfl_xor_sync(0xffffffffu, part, 2);
                if ((lane & 3) == 0) sred[rowl * 2 + wn] = part;
            }
        }
        __syncthreads();
        if (tid < 128) {
            int row = m0 + tid;
            if (row < M) sout[row] = sred[tid * 2] + sred[tid * 2 + 1] + b2[0];
        }
    }
}

// ---------------- fused message + softmax + update (warp per node) -----------
__global__ void msg_update(const float* __restrict__ ae, const int* __restrict__ src,
                           const __half* __restrict__ ghh, const float* __restrict__ h_old,
                           const float* __restrict__ epsv,
                           float* __restrict__ h_new,
                           __half* __restrict__ hh, __half* __restrict__ hl,
                           int N)
{
    const int w = (blockIdx.x * blockDim.x + threadIdx.x) >> 5;
    const int lane = threadIdx.x & 31;
    if (w >= N) return;
    const int lo = g_off[w], hi = g_off[w + 1];

    // each lane owns columns [8*lane, 8*lane+8)
    float acc8[8];
#pragma unroll
    for (int q = 0; q < 8; q++) acc8[q] = 0.f;
    float s = 0.f;

    if (hi > lo) {
        float mym = -INFINITY;
        for (int j = lo + lane; j < hi; j += 32)
            mym = fmaxf(mym, ae[g_perm[j]]);
#pragma unroll
        for (int o = 16; o; o >>= 1)
            mym = fmaxf(mym, __shfl_xor_sync(0xffffffffu, mym, o));
        const float m = mym;
        for (int base = lo; base < hi; base += 32) {
            const int j = base + lane;
            int e = 0, sr = 0;
            float c = 0.f;
            if (j < hi) {
                e = g_perm[j];
                c = __expf(ae[e] - m);
                sr = src[e];
            }
            s += c;
            const int cnt = min(32, hi - base);
            for (int i = 0; i < cnt; i++) {
                const float ci = __shfl_sync(0xffffffffu, c, i);
                const int ei = __shfl_sync(0xffffffffu, e, i);
                const int si = __shfl_sync(0xffffffffu, sr, i);
                const uint4 gv = *(const uint4*)(ghh + (size_t)ei * H + lane * 8);
                const float4* h4 = (const float4*)(h_old + (size_t)si * H + lane * 8);
                float4 hv0 = h4[0], hv1 = h4[1];
                float2 g0 = __half22float2(*(const __half2*)&gv.x);
                float2 g1 = __half22float2(*(const __half2*)&gv.y);
                float2 g2 = __half22float2(*(const __half2*)&gv.z);
                float2 g3 = __half22float2(*(const __half2*)&gv.w);
                acc8[0] = fmaf(ci * g0.x, hv0.x, acc8[0]);
                acc8[1] = fmaf(ci * g0.y, hv0.y, acc8[1]);
                acc8[2] = fmaf(ci * g1.x, hv0.z, acc8[2]);
                acc8[3] = fmaf(ci * g1.y, hv0.w, acc8[3]);
                acc8[4] = fmaf(ci * g2.x, hv1.x, acc8[4]);
                acc8[5] = fmaf(ci * g2.y, hv1.y, acc8[5]);
                acc8[6] = fmaf(ci * g3.x, hv1.z, acc8[6]);
                acc8[7] = fmaf(ci * g3.y, hv1.w, acc8[7]);
            }
        }
#pragma unroll
        for (int o = 16; o; o >>= 1)
            s += __shfl_xor_sync(0xffffffffu, s, o);
    }

    const float inv = (s > 0.f) ? (1.f / s) : 0.f;
    const float scale = (1.f + epsv[w]) * inv;

    const float4* hrow = (const float4*)(h_old + (size_t)w * H + lane * 8);
    float4 o0 = hrow[0], o1 = hrow[1];
    float4 r0, r1;
    r0.x = fmaf(acc8[0], scale, o0.x); r0.y = fmaf(acc8[1], scale, o0.y);
    r0.z = fmaf(acc8[2], scale, o0.z); r0.w = fmaf(acc8[3], scale, o0.w);
    r1.x = fmaf(acc8[4], scale, o1.x); r1.y = fmaf(acc8[5], scale, o1.y);
    r1.z = fmaf(acc8[6], scale, o1.z); r1.w = fmaf(acc8[7], scale, o1.w);
    float4* orow = (float4*)(h_new + (size_t)w * H + lane * 8);
    orow[0] = r0;
    orow[1] = r1;

    // fp16 hi/lo split for next layer's GEMMs
    __half2 hp[4], lp[4];
    float vv[8] = {r0.x, r0.y, r0.z, r0.w, r1.x, r1.y, r1.z, r1.w};
#pragma unroll
    for (int q = 0; q < 4; q++) {
        __half b0 = __float2half(vv[q * 2]);
        __half b1 = __float2half(vv[q * 2 + 1]);
        hp[q] = __half2(b0, b1);
        lp[q] = __half2(__float2half(vv[q * 2] - __half2float(b0)),
                        __float2half(vv[q * 2 + 1] - __half2float(b1)));
    }
    *(uint4*)(hh + (size_t)w * H + lane * 8) = *(uint4*)hp;
    *(uint4*)(hl + (size_t)w * H + lane * 8) = *(uint4*)lp;
}

// ---------------- launch -------------------------------------------------------
extern "C" void kernel_launch(void* const* d_in, const int* in_sizes, int n_in,
                              void* d_out, int out_size)
{
    (void)n_in; (void)out_size;
    const float* node_feats = (const float*)d_in[0];
    const float* gh         = (const float*)d_in[1];
    const int*   src        = (const int*)d_in[2];
    const int*   dst        = (const int*)d_in[3];
    const float* Wn_w       = (const float*)d_in[4];
    const float* Wn_b       = (const float*)d_in[5];
    const float* eps_w1     = (const float*)d_in[6];
    const float* eps_b1     = (const float*)d_in[7];
    const float* eps_w2     = (const float*)d_in[8];
    const float* eps_b2     = (const float*)d_in[9];
    const float* a_w1       = (const float*)d_in[10];
    const float* a_b1       = (const float*)d_in[11];
    const float* a_w2       = (const float*)d_in[12];
    const float* a_b2       = (const float*)d_in[13];

    const int D_IN = 128;
    const int N = in_sizes[0] / D_IN;
    const int E = in_sizes[2];
    const int L = in_sizes[6] / (H * H);

    float* out = (float*)d_out;

    __half *ghh, *nfh, *nfl, *hh, *hl, *Wh, *Wl, *wnh, *wnl;
    float *gP, *epsv, *ae;
    cudaGetSymbolAddress((void**)&ghh, g_ghh);
    cudaGetSymbolAddress((void**)&nfh, g_nfh);
    cudaGetSymbolAddress((void**)&nfl, g_nfl);
    cudaGetSymbolAddress((void**)&hh,  g_hh);
    cudaGetSymbolAddress((void**)&hl,  g_hl);
    cudaGetSymbolAddress((void**)&Wh,  g_Wh);
    cudaGetSymbolAddress((void**)&Wl,  g_Wl);
    cudaGetSymbolAddress((void**)&wnh, g_wnh);
    cudaGetSymbolAddress((void**)&wnl, g_wnl);
    cudaGetSymbolAddress((void**)&gP,   g_P);
    cudaGetSymbolAddress((void**)&epsv, g_eps);
    cudaGetSymbolAddress((void**)&ae,   g_ae);

    constexpr int SMEM3 = NSTAGE * (16384 + 32768);   // 196608
    constexpr int SMEM2 = NSTAGE * (8192 + 32768);    // 163840
    cudaFuncSetAttribute(mma_gemm<3>, cudaFuncAttributeMaxDynamicSharedMemorySize, SMEM3);
    cudaFuncSetAttribute(mma_gemm<2>, cudaFuncAttributeMaxDynamicSharedMemorySize, SMEM2);

    // one-time prep
    {
        int n4 = (E * H) / 4;
        cvt_split<<<(n4 + 255) / 256, 256>>>(gh, ghh, nullptr, n4);
        n4 = (N * D_IN) / 4;
        cvt_split<<<(n4 + 255) / 256, 256>>>(node_feats, nfh, nfl, n4);
        int totw = L * 1024 * 256 + 128 * 256;
        prep_w<<<(totw + 255) / 256, 256>>>(a_w1, eps_w1, Wn_w, L);
        csr_clear<<<(N + 255) / 256, 256>>>(N);
        csr_hist<<<(E + 255) / 256, 256>>>(dst, E);
        csr_scan<<<1, 256>>>(N, E);
        csr_scatter<<<(E + 255) / 256, 256>>>(dst, E);
    }

    const int nblkN = (N + BM - 1) / BM;
    const int nblkE = (E + BM - 1) / BM;
    const size_t nsec = (size_t)N * H;

    // input projection -> out[0:N*H] (+ fp16 split)
    mma_gemm<3><<<dim3(nblkN, 1, 1), NTH, SMEM3>>>(
        nfh, nfl, N, D_IN, wnh, wnl,
        out, 0, 0, Wn_b, 99,
        nullptr, nullptr, nullptr, nullptr,
        nullptr, nullptr, nullptr, nullptr, hh, hl);

    for (int l = 0; l < L; l++) {
        const float* hcur = out + (size_t)l * N * H;
        float*       hnext = out + (size_t)(l + 1) * N * H;
        const __half* WhL = Wh + (size_t)l * 1024 * 256;
        const __half* WlL = Wl + (size_t)l * 1024 * 256;

        // node GEMMs: z=0 -> P1, z=1 -> P2, z=2 -> eps scalar
        mma_gemm<3><<<dim3(nblkN, 1, 3), NTH, SMEM3>>>(
            hh, hl, N, H, WhL, WlL,
            gP, nsec, (size_t)256 * 256, nullptr, 2,
            eps_b1 + (size_t)l * H, eps_w2 + (size_t)l * H, eps_b2 + l, epsv,
            nullptr, nullptr, nullptr, nullptr, nullptr, nullptr);

        // edge scores -> ae (2-term: A = fp16(gh), B split hi/lo)
        mma_gemm<2><<<dim3(nblkE, 1, 1), NTH, SMEM2>>>(
            ghh, nullptr, E, H, WhL + (size_t)768 * 256, WlL + (size_t)768 * 256,
            nullptr, 0, 0, nullptr, 0,
            a_b1 + (size_t)l * H, a_w2 + (size_t)l * H, a_b2 + l, ae,
            gP, gP + nsec, src, dst, nullptr, nullptr);

        // fused message + softmax + GIN update (+ fp16 split of h_next)
        msg_update<<<(N * 32 + 255) / 256, 256>>>(
            ae, src, ghh, hcur, epsv, hnext, hh, hl, N);
    }
}

// round 7
// speedup vs baseline: 3.0850x; 1.1664x over previous
#include <cuda_runtime.h>
#include <cuda_fp16.h>
#include <math.h>
#include <stdint.h>

#define H 256
#define N_MAX 10240
#define E_MAX 163840
#define L_MAX 3

#define BM 128
#define BN 256
#define BK 32
#define NTH 256
#define NSTAGE 4

// ---------------- scratch (device globals) ---------------------------------
__device__ __half g_ghh[E_MAX * H];            // gh fp16 (single)
__device__ __half g_nfh[N_MAX * 128];
__device__ __half g_nfl[N_MAX * 128];
__device__ __half g_hh[N_MAX * H];
__device__ __half g_hl[N_MAX * H];
// combined per-layer weights: rows 0-255 P1W, 256-511 P2W, 512-767 epsW,
// 768-1023 edgeW (each [256k,256n] row-major)
__device__ __half g_Wh[L_MAX * 1024 * 256];
__device__ __half g_Wl[L_MAX * 1024 * 256];
__device__ __half g_wnh[128 * 256];
__device__ __half g_wnl[128 * 256];
__device__ float g_P[2 * N_MAX * H];
__device__ float g_eps[N_MAX];
__device__ float g_ae[E_MAX];
// CSR by dst
__device__ int g_cnt[N_MAX];
__device__ int g_off[N_MAX + 1];
__device__ int g_cur[N_MAX];
__device__ int g_perm[E_MAX];

// ---------------- helpers ----------------------------------------------------
__device__ __forceinline__ uint32_t smem_u32(const void* p) {
    uint32_t a;
    asm("{ .reg .u64 t; cvta.to.shared.u64 t, %1; cvt.u32.u64 %0, t; }" : "=r"(a) : "l"(p));
    return a;
}
__device__ __forceinline__ void cp16(uint32_t dst, const void* src) {
    asm volatile("cp.async.cg.shared.global [%0], [%1], 16;" :: "r"(dst), "l"(src));
}
__device__ __forceinline__ void ldsm4(uint32_t* r, uint32_t addr) {
    asm volatile("ldmatrix.sync.aligned.m8n8.x4.shared.b16 {%0,%1,%2,%3}, [%4];"
                 : "=r"(r[0]), "=r"(r[1]), "=r"(r[2]), "=r"(r[3]) : "r"(addr));
}
__device__ __forceinline__ void ldsm4t(uint32_t* r, uint32_t addr) {
    asm volatile("ldmatrix.sync.aligned.m8n8.x4.trans.shared.b16 {%0,%1,%2,%3}, [%4];"
                 : "=r"(r[0]), "=r"(r[1]), "=r"(r[2]), "=r"(r[3]) : "r"(addr));
}
__device__ __forceinline__ void mma16816(float* c, const uint32_t* a, const uint32_t* b) {
    asm volatile("mma.sync.aligned.m16n8k16.row.col.f32.f16.f16.f32 "
                 "{%0,%1,%2,%3}, {%4,%5,%6,%7}, {%8,%9}, {%0,%1,%2,%3};"
                 : "+f"(c[0]), "+f"(c[1]), "+f"(c[2]), "+f"(c[3])
                 : "r"(a[0]), "r"(a[1]), "r"(a[2]), "r"(a[3]), "r"(b[0]), "r"(b[1]));
}

// ---------------- fp32 -> fp16 hi(/lo) split ---------------------------------
__global__ void cvt_split(const float* __restrict__ x, __half* __restrict__ hi,
                          __half* __restrict__ lo, int n4)
{
    int i = blockIdx.x * blockDim.x + threadIdx.x;
    if (i >= n4) return;
    float4 v = ((const float4*)x)[i];
    __half h0 = __float2half(v.x), h1 = __float2half(v.y);
    __half h2 = __float2half(v.z), h3 = __float2half(v.w);
    __half2 hh0(h0, h1), hh1(h2, h3);
    ((__half2*)hi)[i * 2 + 0] = hh0;
    ((__half2*)hi)[i * 2 + 1] = hh1;
    if (lo) {
        __half2 ll0(__float2half(v.x - __half2float(h0)),
                    __float2half(v.y - __half2float(h1)));
        __half2 ll1(__float2half(v.z - __half2float(h2)),
                    __float2half(v.w - __half2float(h3)));
        ((__half2*)lo)[i * 2 + 0] = ll0;
        ((__half2*)lo)[i * 2 + 1] = ll1;
    }
}

// ---------------- weight prep ------------------------------------------------
__global__ void prep_w(const float* __restrict__ a_w1, const float* __restrict__ eps_w1,
                       const float* __restrict__ Wn_w, int L)
{
    const int totW = L * 1024 * 256;
    const int total = totW + 128 * 256;
    int idx = blockIdx.x * blockDim.x + threadIdx.x;
    if (idx >= total) return;
    float v;
    __half *dh, *dl;
    int di;
    if (idx < totW) {
        int l = idx / (1024 * 256);
        int r = (idx / 256) % 1024;
        int n = idx % 256;
        if (r < 512)      v = a_w1[((size_t)l * 768 + r) * 256 + n];
        else if (r < 768) v = eps_w1[((size_t)l * 256 + (r - 512)) * 256 + n];
        else              v = a_w1[((size_t)l * 768 + 512 + (r - 768)) * 256 + n];
        dh = g_Wh; dl = g_Wl; di = idx;
    } else {
        int i2 = idx - totW;
        v = Wn_w[i2];
        dh = g_wnh; dl = g_wnl; di = i2;
    }
    __half h = __float2half(v);
    dh[di] = h;
    dl[di] = __float2half(v - __half2float(h));
}

// ---------------- CSR build ---------------------------------------------------
__global__ void csr_clear(int N) {
    int i = blockIdx.x * blockDim.x + threadIdx.x;
    if (i < N) g_cnt[i] = 0;
}
__global__ void csr_hist(const int* __restrict__ dst, int E) {
    int e = blockIdx.x * blockDim.x + threadIdx.x;
    if (e < E) atomicAdd(&g_cnt[dst[e]], 1);
}
__global__ void csr_scan(int N, int E) {
    __shared__ int sums[256];
    const int tid = threadIdx.x;
    const int chunk = (N + 255) / 256;
    const int base = tid * chunk;
    int s = 0;
    for (int i = 0; i < chunk; i++) {
        int idx = base + i;
        if (idx < N) s += g_cnt[idx];
    }
    sums[tid] = s;
    __syncthreads();
    for (int d = 1; d < 256; d <<= 1) {
        int v = (tid >= d) ? sums[tid - d] : 0;
        __syncthreads();
        sums[tid] += v;
        __syncthreads();
    }
    int run = sums[tid] - s;
    for (int i = 0; i < chunk; i++) {
        int idx = base + i;
        if (idx < N) { g_off[idx] = run; g_cur[idx] = run; run += g_cnt[idx]; }
    }
    if (tid == 255) g_off[N] = E;
}
__global__ void csr_scatter(const int* __restrict__ dst, int E) {
    int e = blockIdx.x * blockDim.x + threadIdx.x;
    if (e < E) {
        int pos = atomicAdd(&g_cur[dst[e]], 1);
        g_perm[pos] = e;
    }
}

// ---------------- fp16-split tensor-core GEMM (BM=128, BN=256) ---------------
// TERMS=3: D = Ah*Bh + Al*Bh + Ah*Bl
// TERMS=1: D = Ah*Bh
template <int TERMS>
__global__ void __launch_bounds__(NTH, 1)
mma_gemm(const __half* __restrict__ Ah, const __half* __restrict__ Al,
         int M, int K,
         const __half* __restrict__ Bh, const __half* __restrict__ Bl,
         float* __restrict__ C, size_t zstrC, size_t zstrB,
         const float* __restrict__ bias, int scalar_z,
         const float* __restrict__ sbias, const float* __restrict__ w2,
         const float* __restrict__ b2, float* __restrict__ sout,
         const float* __restrict__ P1, const float* __restrict__ P2,
         const int* __restrict__ src, const int* __restrict__ dst,
         __half* __restrict__ ohh, __half* __restrict__ ohl)
{
    constexpr bool HAS_AL = (TERMS == 3);
    constexpr bool HAS_BL = (TERMS >= 2);
    constexpr uint32_t AH_OFF = 0;
    constexpr uint32_t AL_OFF = 8192;
    constexpr uint32_t BH_OFF = HAS_AL ? 16384u : 8192u;
    constexpr uint32_t BL_OFF = BH_OFF + (HAS_BL ? 16384u : 0u);
    constexpr uint32_t STB = BH_OFF + 16384u + (HAS_BL ? 16384u : 0u);

    extern __shared__ char smem[];
    const uint32_t sb = smem_u32(smem);
    const int tid = threadIdx.x;
    const int lane = tid & 31;
    const int wid = tid >> 5;
    const int wm = wid & 3;
    const int wn = wid >> 2;
    const int m0 = blockIdx.x * BM;
    const int z = blockIdx.z;
    const int nchunks = K / BK;

    const __half* Bhz = Bh + zstrB * z;
    const __half* Blz = HAS_BL ? (Bl + zstrB * z) : nullptr;

    float acc[2][16][4];
#pragma unroll
    for (int mi = 0; mi < 2; mi++)
#pragma unroll
        for (int nj = 0; nj < 16; nj++)
#pragma unroll
            for (int q = 0; q < 4; q++) acc[mi][nj][q] = 0.f;

    auto load_stage = [&](int s, int k0) {
        const uint32_t base = sb + s * STB;
#pragma unroll
        for (int i = 0; i < 2; i++) {
            int cid = tid + i * NTH;
            int row = cid >> 2;
            int cb = (cid & 3) * 16;
            int grow = m0 + row;
            if (grow >= M) grow = M - 1;
            size_t gb = ((size_t)grow * K + k0) * 2 + cb;
            uint32_t d = base + row * 64 + (cb ^ ((row & 3) << 4));
            cp16(d + AH_OFF, (const char*)Ah + gb);
            if (HAS_AL) cp16(d + AL_OFF, (const char*)Al + gb);
        }
#pragma unroll
        for (int i = 0; i < 4; i++) {
            int cid = tid + i * NTH;
            int k = cid >> 5;
            int cb = (cid & 31) * 16;
            size_t gb = (size_t)(k0 + k) * 512 + cb;
            uint32_t d = base + k * 512 + (cb ^ ((k & 7) << 4));
            cp16(d + BH_OFF, (const char*)Bhz + gb);
            if (HAS_BL) cp16(d + BL_OFF, (const char*)Blz + gb);
        }
        asm volatile("cp.async.commit_group;" ::: "memory");
    };

    auto compute_stage = [&](int s) {
        const uint32_t base = sb + s * STB;
#pragma unroll
        for (int kk = 0; kk < 2; kk++) {
            uint32_t ah[2][4], al[2][4];
#pragma unroll
            for (int mi = 0; mi < 2; mi++) {
                int row = wm * 32 + mi * 16 + (lane & 15);
                uint32_t cb = kk * 32 + ((lane >> 4) << 4);
                uint32_t ad = base + row * 64 + (cb ^ ((row & 3) << 4));
                ldsm4(ah[mi], ad + AH_OFF);
                if (HAS_AL) ldsm4(al[mi], ad + AL_OFF);
            }
            const int kr = kk * 16 + (lane & 15);
            const uint32_t hi16 = (lane >> 4) << 4;
            uint32_t bhA[4], blA[4], bhB[4], blB[4];
            {
                uint32_t cb = wn * 256 + 0 * 32 + hi16;
                uint32_t bd = base + kr * 512 + (cb ^ ((kr & 7) << 4));
                ldsm4t(bhA, bd + BH_OFF);
                if (HAS_BL) ldsm4t(blA, bd + BL_OFF);
            }
#pragma unroll
            for (int nj2 = 0; nj2 < 8; nj2++) {
                uint32_t* ch = (nj2 & 1) ? bhB : bhA;
                uint32_t* cl = (nj2 & 1) ? blB : blA;
                if (nj2 < 7) {
                    uint32_t* nh = (nj2 & 1) ? bhA : bhB;
                    uint32_t* nl = (nj2 & 1) ? blA : blB;
                    uint32_t cb = wn * 256 + (nj2 + 1) * 32 + hi16;
                    uint32_t bd = base + kr * 512 + (cb ^ ((kr & 7) << 4));
                    ldsm4t(nh, bd + BH_OFF);
                    if (HAS_BL) ldsm4t(nl, bd + BL_OFF);
                }
#pragma unroll
                for (int mi = 0; mi < 2; mi++)
#pragma unroll
                    for (int sub = 0; sub < 2; sub++) {
                        int nj = nj2 * 2 + sub;
                        mma16816(acc[mi][nj], ah[mi], &ch[sub * 2]);
                        if (HAS_AL) mma16816(acc[mi][nj], al[mi], &ch[sub * 2]);
                        if (HAS_BL) mma16816(acc[mi][nj], ah[mi], &cl[sub * 2]);
                    }
            }
        }
    };

    for (int p = 0; p < 3 && p < nchunks; p++) load_stage(p, p * BK);
    for (int c = 0; c < nchunks; c++) {
        if (c + 3 < nchunks) load_stage((c + 3) & 3, (c + 3) * BK);
        else asm volatile("cp.async.commit_group;" ::: "memory");
        asm volatile("cp.async.wait_group 2;" ::: "memory");
        __syncthreads();
        compute_stage(c & 3);
        __syncthreads();
    }

    if (z < scalar_z) {
        float* Cz = C + zstrC * z;
#pragma unroll
        for (int mi = 0; mi < 2; mi++) {
#pragma unroll
            for (int half = 0; half < 2; half++) {
                int row = m0 + wm * 32 + mi * 16 + half * 8 + (lane >> 2);
                if (row >= M) continue;
                float* cr = Cz + (size_t)row * 256;
#pragma unroll
                for (int nj = 0; nj < 16; nj++) {
                    int col = wn * 128 + nj * 8 + (lane & 3) * 2;
                    float2 v;
                    v.x = acc[mi][nj][half * 2 + 0];
                    v.y = acc[mi][nj][half * 2 + 1];
                    if (bias) { v.x += bias[col]; v.y += bias[col + 1]; }
                    *(float2*)(cr + col) = v;
                    if (ohh) {
                        __half b0 = __float2half(v.x);
                        __half b1 = __float2half(v.y);
                        __half2 hp(b0, b1);
                        __half2 lp(__float2half(v.x - __half2float(b0)),
                                   __float2half(v.y - __half2float(b1)));
                        *(__half2*)(ohh + (size_t)row * 256 + col) = hp;
                        *(__half2*)(ohl + (size_t)row * 256 + col) = lp;
                    }
                }
            }
        }
    } else {
        float* sred = (float*)smem;   // [128][2]
#pragma unroll
        for (int mi = 0; mi < 2; mi++) {
#pragma unroll
            for (int half = 0; half < 2; half++) {
                int rowl = wm * 32 + mi * 16 + half * 8 + (lane >> 2);
                int row = m0 + rowl;
                int cl = (row < M) ? row : (M - 1);
                const float* p1 = P1 ? (P1 + (size_t)src[cl] * 256) : nullptr;
                const float* p2 = P2 ? (P2 + (size_t)dst[cl] * 256) : nullptr;
                float part = 0.f;
#pragma unroll
                for (int nj = 0; nj < 16; nj++) {
                    int col = wn * 128 + nj * 8 + (lane & 3) * 2;
                    float2 bv = *(const float2*)(sbias + col);
                    float2 wv = *(const float2*)(w2 + col);
                    float2 p1v = make_float2(0.f, 0.f), p2v = make_float2(0.f, 0.f);
                    if (p1) p1v = *(const float2*)(p1 + col);
                    if (p2) p2v = *(const float2*)(p2 + col);
                    float v0 = fmaxf(acc[mi][nj][half * 2 + 0] + bv.x + p1v.x + p2v.x, 0.f);
                    float v1 = fmaxf(acc[mi][nj][half * 2 + 1] + bv.y + p1v.y + p2v.y, 0.f);
                    part = fmaf(v0, wv.x, part);
                    part = fmaf(v1, wv.y, part);
                }
                part += __shfl_xor_sync(0xffffffffu, part, 1);
                part += __shfl_xor_sync(0xffffffffu, part, 2);
                if ((lane & 3) == 0) sred[rowl * 2 + wn] = part;
            }
        }
        __syncthreads();
        if (tid < 128) {
            int row = m0 + tid;
            if (row < M) sout[row] = sred[tid * 2] + sred[tid * 2 + 1] + b2[0];
        }
    }
}

// ---------------- fused message + softmax + update (warp per node) -----------
__global__ void msg_update(const float* __restrict__ ae, const int* __restrict__ src,
                           const __half* __restrict__ ghh, const float* __restrict__ h_old,
                           const float* __restrict__ epsv,
                           float* __restrict__ h_new,
                           __half* __restrict__ hh, __half* __restrict__ hl,
                           int N)
{
    const int w = (blockIdx.x * blockDim.x + threadIdx.x) >> 5;
    const int lane = threadIdx.x & 31;
    if (w >= N) return;
    const int lo = g_off[w], hi = g_off[w + 1];

    // each lane owns columns [8*lane, 8*lane+8)
    float acc8[8];
#pragma unroll
    for (int q = 0; q < 8; q++) acc8[q] = 0.f;
    float s = 0.f;

    if (hi > lo) {
        float mym = -INFINITY;
        for (int j = lo + lane; j < hi; j += 32)
            mym = fmaxf(mym, ae[g_perm[j]]);
#pragma unroll
        for (int o = 16; o; o >>= 1)
            mym = fmaxf(mym, __shfl_xor_sync(0xffffffffu, mym, o));
        const float m = mym;
        for (int base = lo; base < hi; base += 32) {
            const int j = base + lane;
            int e = 0, sr = 0;
            float c = 0.f;
            if (j < hi) {
                e = g_perm[j];
                c = __expf(ae[e] - m);
                sr = src[e];
            }
            s += c;
            const int cnt = min(32, hi - base);
            for (int i = 0; i < cnt; i++) {
                const float ci = __shfl_sync(0xffffffffu, c, i);
                const int ei = __shfl_sync(0xffffffffu, e, i);
                const int si = __shfl_sync(0xffffffffu, sr, i);
                const uint4 gv = *(const uint4*)(ghh + (size_t)ei * H + lane * 8);
                const float4* h4 = (const float4*)(h_old + (size_t)si * H + lane * 8);
                float4 hv0 = h4[0], hv1 = h4[1];
                float2 g0 = __half22float2(*(const __half2*)&gv.x);
                float2 g1 = __half22float2(*(const __half2*)&gv.y);
                float2 g2 = __half22float2(*(const __half2*)&gv.z);
                float2 g3 = __half22float2(*(const __half2*)&gv.w);
                acc8[0] = fmaf(ci * g0.x, hv0.x, acc8[0]);
                acc8[1] = fmaf(ci * g0.y, hv0.y, acc8[1]);
                acc8[2] = fmaf(ci * g1.x, hv0.z, acc8[2]);
                acc8[3] = fmaf(ci * g1.y, hv0.w, acc8[3]);
                acc8[4] = fmaf(ci * g2.x, hv1.x, acc8[4]);
                acc8[5] = fmaf(ci * g2.y, hv1.y, acc8[5]);
                acc8[6] = fmaf(ci * g3.x, hv1.z, acc8[6]);
                acc8[7] = fmaf(ci * g3.y, hv1.w, acc8[7]);
            }
        }
#pragma unroll
        for (int o = 16; o; o >>= 1)
            s += __shfl_xor_sync(0xffffffffu, s, o);
    }

    const float inv = (s > 0.f) ? (1.f / s) : 0.f;
    const float scale = (1.f + epsv[w]) * inv;

    const float4* hrow = (const float4*)(h_old + (size_t)w * H + lane * 8);
    float4 o0 = hrow[0], o1 = hrow[1];
    float4 r0, r1;
    r0.x = fmaf(acc8[0], scale, o0.x); r0.y = fmaf(acc8[1], scale, o0.y);
    r0.z = fmaf(acc8[2], scale, o0.z); r0.w = fmaf(acc8[3], scale, o0.w);
    r1.x = fmaf(acc8[4], scale, o1.x); r1.y = fmaf(acc8[5], scale, o1.y);
    r1.z = fmaf(acc8[6], scale, o1.z); r1.w = fmaf(acc8[7], scale, o1.w);
    float4* orow = (float4*)(h_new + (size_t)w * H + lane * 8);
    orow[0] = r0;
    orow[1] = r1;

    // fp16 hi/lo split for next layer's GEMMs
    __half2 hp[4], lp[4];
    float vv[8] = {r0.x, r0.y, r0.z, r0.w, r1.x, r1.y, r1.z, r1.w};
#pragma unroll
    for (int q = 0; q < 4; q++) {
        __half b0 = __float2half(vv[q * 2]);
        __half b1 = __float2half(vv[q * 2 + 1]);
        hp[q] = __half2(b0, b1);
        lp[q] = __half2(__float2half(vv[q * 2] - __half2float(b0)),
                        __float2half(vv[q * 2 + 1] - __half2float(b1)));
    }
    *(uint4*)(hh + (size_t)w * H + lane * 8) = *(uint4*)hp;
    *(uint4*)(hl + (size_t)w * H + lane * 8) = *(uint4*)lp;
}

// ---------------- launch -------------------------------------------------------
extern "C" void kernel_launch(void* const* d_in, const int* in_sizes, int n_in,
                              void* d_out, int out_size)
{
    (void)n_in; (void)out_size;
    const float* node_feats = (const float*)d_in[0];
    const float* gh         = (const float*)d_in[1];
    const int*   src        = (const int*)d_in[2];
    const int*   dst        = (const int*)d_in[3];
    const float* Wn_w       = (const float*)d_in[4];
    const float* Wn_b       = (const float*)d_in[5];
    const float* eps_w1     = (const float*)d_in[6];
    const float* eps_b1     = (const float*)d_in[7];
    const float* eps_w2     = (const float*)d_in[8];
    const float* eps_b2     = (const float*)d_in[9];
    const float* a_w1       = (const float*)d_in[10];
    const float* a_b1       = (const float*)d_in[11];
    const float* a_w2       = (const float*)d_in[12];
    const float* a_b2       = (const float*)d_in[13];

    const int D_IN = 128;
    const int N = in_sizes[0] / D_IN;
    const int E = in_sizes[2];
    const int L = in_sizes[6] / (H * H);

    float* out = (float*)d_out;

    __half *ghh, *nfh, *nfl, *hh, *hl, *Wh, *Wl, *wnh, *wnl;
    float *gP, *epsv, *ae;
    cudaGetSymbolAddress((void**)&ghh, g_ghh);
    cudaGetSymbolAddress((void**)&nfh, g_nfh);
    cudaGetSymbolAddress((void**)&nfl, g_nfl);
    cudaGetSymbolAddress((void**)&hh,  g_hh);
    cudaGetSymbolAddress((void**)&hl,  g_hl);
    cudaGetSymbolAddress((void**)&Wh,  g_Wh);
    cudaGetSymbolAddress((void**)&Wl,  g_Wl);
    cudaGetSymbolAddress((void**)&wnh, g_wnh);
    cudaGetSymbolAddress((void**)&wnl, g_wnl);
    cudaGetSymbolAddress((void**)&gP,   g_P);
    cudaGetSymbolAddress((void**)&epsv, g_eps);
    cudaGetSymbolAddress((void**)&ae,   g_ae);

    constexpr int SMEM3 = NSTAGE * (16384 + 32768);   // 196608
    constexpr int SMEM1 = NSTAGE * (8192 + 16384);    // 98304
    cudaFuncSetAttribute(mma_gemm<3>, cudaFuncAttributeMaxDynamicSharedMemorySize, SMEM3);
    cudaFuncSetAttribute(mma_gemm<1>, cudaFuncAttributeMaxDynamicSharedMemorySize, SMEM1);

    // one-time prep
    {
        int n4 = (E * H) / 4;
        cvt_split<<<(n4 + 255) / 256, 256>>>(gh, ghh, nullptr, n4);
        n4 = (N * D_IN) / 4;
        cvt_split<<<(n4 + 255) / 256, 256>>>(node_feats, nfh, nfl, n4);
        int totw = L * 1024 * 256 + 128 * 256;
        prep_w<<<(totw + 255) / 256, 256>>>(a_w1, eps_w1, Wn_w, L);
        csr_clear<<<(N + 255) / 256, 256>>>(N);
        csr_hist<<<(E + 255) / 256, 256>>>(dst, E);
        csr_scan<<<1, 256>>>(N, E);
        csr_scatter<<<(E + 255) / 256, 256>>>(dst, E);
    }

    const int nblkN = (N + BM - 1) / BM;
    const int nblkE = (E + BM - 1) / BM;
    const size_t nsec = (size_t)N * H;

    // input projection -> out[0:N*H] (+ fp16 split)
    mma_gemm<3><<<dim3(nblkN, 1, 1), NTH, SMEM3>>>(
        nfh, nfl, N, D_IN, wnh, wnl,
        out, 0, 0, Wn_b, 99,
        nullptr, nullptr, nullptr, nullptr,
        nullptr, nullptr, nullptr, nullptr, hh, hl);

    for (int l = 0; l < L; l++) {
        const float* hcur = out + (size_t)l * N * H;
        float*       hnext = out + (size_t)(l + 1) * N * H;
        const __half* WhL = Wh + (size_t)l * 1024 * 256;
        const __half* WlL = Wl + (size_t)l * 1024 * 256;

        // node GEMMs: z=0 -> P1, z=1 -> P2, z=2 -> eps scalar (3-term)
        mma_gemm<3><<<dim3(nblkN, 1, 3), NTH, SMEM3>>>(
            hh, hl, N, H, WhL, WlL,
            gP, nsec, (size_t)256 * 256, nullptr, 2,
            eps_b1 + (size_t)l * H, eps_w2 + (size_t)l * H, eps_b2 + l, epsv,
            nullptr, nullptr, nullptr, nullptr, nullptr, nullptr);

        // edge scores -> ae (1-term: A = fp16(gh), B = fp16(W))
        mma_gemm<1><<<dim3(nblkE, 1, 1), NTH, SMEM1>>>(
            ghh, nullptr, E, H, WhL + (size_t)768 * 256, nullptr,
            nullptr, 0, 0, nullptr, 0,
            a_b1 + (size_t)l * H, a_w2 + (size_t)l * H, a_b2 + l, ae,
            gP, gP + nsec, src, dst, nullptr, nullptr);

        // fused message + softmax + GIN update (+ fp16 split of h_next)
        msg_update<<<(N * 32 + 255) / 256, 256>>>(
            ae, src, ghh, hcur, epsv, hnext, hh, hl, N);
    }
}

// round 8
// speedup vs baseline: 3.3822x; 1.0963x over previous
#include <cuda_runtime.h>
#include <cuda_fp16.h>
#include <math.h>
#include <stdint.h>

#define H 256
#define N_MAX 10240
#define E_MAX 163840
#define L_MAX 3

#define BM 128
#define BN 256
#define BK 32
#define NTH 256
#define NSTAGE 4

// ---------------- scratch (device globals) ---------------------------------
__device__ __half g_ghh[E_MAX * H];            // gh fp16
__device__ __half g_nfh[N_MAX * 128];
__device__ __half g_nfl[N_MAX * 128];
__device__ __half g_hh[2][N_MAX * H];          // double-buffered per layer
__device__ __half g_hl[2][N_MAX * H];
// combined per-layer weights: rows 0-255 P1W, 256-511 P2W, 512-767 epsW,
// 768-1023 edgeW (each [256k,256n] row-major)
__device__ __half g_Wh[L_MAX * 1024 * 256];
__device__ __half g_Wl[L_MAX * 1024 * 256];
__device__ __half g_wnh[128 * 256];
__device__ __half g_wnl[128 * 256];
__device__ __half g_P[2 * N_MAX * H];          // P1,P2 in fp16
__device__ float g_eps[N_MAX];
__device__ float g_ae[E_MAX];
// CSR by dst
__device__ int g_cnt[N_MAX];
__device__ int g_off[N_MAX + 1];
__device__ int g_cur[N_MAX];
__device__ int g_perm[E_MAX];

// ---------------- helpers ----------------------------------------------------
__device__ __forceinline__ uint32_t smem_u32(const void* p) {
    uint32_t a;
    asm("{ .reg .u64 t; cvta.to.shared.u64 t, %1; cvt.u32.u64 %0, t; }" : "=r"(a) : "l"(p));
    return a;
}
__device__ __forceinline__ void cp16(uint32_t dst, const void* src) {
    asm volatile("cp.async.cg.shared.global [%0], [%1], 16;" :: "r"(dst), "l"(src));
}
__device__ __forceinline__ void ldsm4(uint32_t* r, uint32_t addr) {
    asm volatile("ldmatrix.sync.aligned.m8n8.x4.shared.b16 {%0,%1,%2,%3}, [%4];"
                 : "=r"(r[0]), "=r"(r[1]), "=r"(r[2]), "=r"(r[3]) : "r"(addr));
}
__device__ __forceinline__ void ldsm4t(uint32_t* r, uint32_t addr) {
    asm volatile("ldmatrix.sync.aligned.m8n8.x4.trans.shared.b16 {%0,%1,%2,%3}, [%4];"
                 : "=r"(r[0]), "=r"(r[1]), "=r"(r[2]), "=r"(r[3]) : "r"(addr));
}
__device__ __forceinline__ void mma16816(float* c, const uint32_t* a, const uint32_t* b) {
    asm volatile("mma.sync.aligned.m16n8k16.row.col.f32.f16.f16.f32 "
                 "{%0,%1,%2,%3}, {%4,%5,%6,%7}, {%8,%9}, {%0,%1,%2,%3};"
                 : "+f"(c[0]), "+f"(c[1]), "+f"(c[2]), "+f"(c[3])
                 : "r"(a[0]), "r"(a[1]), "r"(a[2]), "r"(a[3]), "r"(b[0]), "r"(b[1]));
}

// ---------------- fp32 -> fp16 hi(/lo) split ---------------------------------
__global__ void cvt_split(const float* __restrict__ x, __half* __restrict__ hi,
                          __half* __restrict__ lo, int n4)
{
    int i = blockIdx.x * blockDim.x + threadIdx.x;
    if (i >= n4) return;
    float4 v = ((const float4*)x)[i];
    __half h0 = __float2half(v.x), h1 = __float2half(v.y);
    __half h2 = __float2half(v.z), h3 = __float2half(v.w);
    __half2 hh0(h0, h1), hh1(h2, h3);
    ((__half2*)hi)[i * 2 + 0] = hh0;
    ((__half2*)hi)[i * 2 + 1] = hh1;
    if (lo) {
        __half2 ll0(__float2half(v.x - __half2float(h0)),
                    __float2half(v.y - __half2float(h1)));
        __half2 ll1(__float2half(v.z - __half2float(h2)),
                    __float2half(v.w - __half2float(h3)));
        ((__half2*)lo)[i * 2 + 0] = ll0;
        ((__half2*)lo)[i * 2 + 1] = ll1;
    }
}

// ---------------- weight prep ------------------------------------------------
__global__ void prep_w(const float* __restrict__ a_w1, const float* __restrict__ eps_w1,
                       const float* __restrict__ Wn_w, int L)
{
    const int totW = L * 1024 * 256;
    const int total = totW + 128 * 256;
    int idx = blockIdx.x * blockDim.x + threadIdx.x;
    if (idx >= total) return;
    float v;
    __half *dh, *dl;
    int di;
    if (idx < totW) {
        int l = idx / (1024 * 256);
        int r = (idx / 256) % 1024;
        int n = idx % 256;
        if (r < 512)      v = a_w1[((size_t)l * 768 + r) * 256 + n];
        else if (r < 768) v = eps_w1[((size_t)l * 256 + (r - 512)) * 256 + n];
        else              v = a_w1[((size_t)l * 768 + 512 + (r - 768)) * 256 + n];
        dh = g_Wh; dl = g_Wl; di = idx;
    } else {
        int i2 = idx - totW;
        v = Wn_w[i2];
        dh = g_wnh; dl = g_wnl; di = i2;
    }
    __half h = __float2half(v);
    dh[di] = h;
    dl[di] = __float2half(v - __half2float(h));
}

// ---------------- CSR build ---------------------------------------------------
__global__ void csr_clear(int N) {
    int i = blockIdx.x * blockDim.x + threadIdx.x;
    if (i < N) g_cnt[i] = 0;
}
__global__ void csr_hist(const int* __restrict__ dst, int E) {
    int e = blockIdx.x * blockDim.x + threadIdx.x;
    if (e < E) atomicAdd(&g_cnt[dst[e]], 1);
}
__global__ void csr_scan(int N, int E) {
    __shared__ int sums[256];
    const int tid = threadIdx.x;
    const int chunk = (N + 255) / 256;
    const int base = tid * chunk;
    int s = 0;
    for (int i = 0; i < chunk; i++) {
        int idx = base + i;
        if (idx < N) s += g_cnt[idx];
    }
    sums[tid] = s;
    __syncthreads();
    for (int d = 1; d < 256; d <<= 1) {
        int v = (tid >= d) ? sums[tid - d] : 0;
        __syncthreads();
        sums[tid] += v;
        __syncthreads();
    }
    int run = sums[tid] - s;
    for (int i = 0; i < chunk; i++) {
        int idx = base + i;
        if (idx < N) { g_off[idx] = run; g_cur[idx] = run; run += g_cnt[idx]; }
    }
    if (tid == 255) g_off[N] = E;
}
__global__ void csr_scatter(const int* __restrict__ dst, int E) {
    int e = blockIdx.x * blockDim.x + threadIdx.x;
    if (e < E) {
        int pos = atomicAdd(&g_cur[dst[e]], 1);
        g_perm[pos] = e;
    }
}

// ---------------- fp16-split tensor-core GEMM (BM=128, BN=256) ---------------
// TERMS=3: D = Ah*Bh + Al*Bh + Ah*Bl
// TERMS=2: D = Ah*Bh + Al*Bh
// TERMS=1: D = Ah*Bh
// z < scalar_z : write D (+bias): to PC (fp16) if given, else C (fp32),
//                plus optional fp16 hi/lo split to ohh/ohl
// z >= scalar_z: sout[row] = sum relu(D + sbias + P1[src] + P2[dst]) . w2 + b2
template <int TERMS>
__global__ void __launch_bounds__(NTH, 1)
mma_gemm(const __half* __restrict__ Ah, const __half* __restrict__ Al,
         int M, int K,
         const __half* __restrict__ Bh, const __half* __restrict__ Bl,
         float* __restrict__ C, __half* __restrict__ PC,
         size_t zstrC, size_t zstrB,
         const float* __restrict__ bias, int scalar_z,
         const float* __restrict__ sbias, const float* __restrict__ w2,
         const float* __restrict__ b2, float* __restrict__ sout,
         const __half* __restrict__ P1, const __half* __restrict__ P2,
         const int* __restrict__ src, const int* __restrict__ dst,
         __half* __restrict__ ohh, __half* __restrict__ ohl)
{
    constexpr bool HAS_AL = (TERMS >= 2);
    constexpr bool HAS_BL = (TERMS == 3);
    constexpr uint32_t AH_OFF = 0;
    constexpr uint32_t AL_OFF = 8192;
    constexpr uint32_t BH_OFF = HAS_AL ? 16384u : 8192u;
    constexpr uint32_t BL_OFF = BH_OFF + 16384u;
    constexpr uint32_t STB = BH_OFF + 16384u + (HAS_BL ? 16384u : 0u);

    extern __shared__ char smem[];
    const uint32_t sb = smem_u32(smem);
    const int tid = threadIdx.x;
    const int lane = tid & 31;
    const int wid = tid >> 5;
    const int wm = wid & 3;
    const int wn = wid >> 2;
    const int m0 = blockIdx.x * BM;
    const int z = blockIdx.z;
    const int nchunks = K / BK;

    const __half* Bhz = Bh + zstrB * z;
    const __half* Blz = HAS_BL ? (Bl + zstrB * z) : nullptr;

    float acc[2][16][4];
#pragma unroll
    for (int mi = 0; mi < 2; mi++)
#pragma unroll
        for (int nj = 0; nj < 16; nj++)
#pragma unroll
            for (int q = 0; q < 4; q++) acc[mi][nj][q] = 0.f;

    auto load_stage = [&](int s, int k0) {
        const uint32_t base = sb + s * STB;
#pragma unroll
        for (int i = 0; i < 2; i++) {
            int cid = tid + i * NTH;
            int row = cid >> 2;
            int cb = (cid & 3) * 16;
            int grow = m0 + row;
            if (grow >= M) grow = M - 1;
            size_t gb = ((size_t)grow * K + k0) * 2 + cb;
            uint32_t d = base + row * 64 + (cb ^ ((row & 3) << 4));
            cp16(d + AH_OFF, (const char*)Ah + gb);
            if (HAS_AL) cp16(d + AL_OFF, (const char*)Al + gb);
        }
#pragma unroll
        for (int i = 0; i < 4; i++) {
            int cid = tid + i * NTH;
            int k = cid >> 5;
            int cb = (cid & 31) * 16;
            size_t gb = (size_t)(k0 + k) * 512 + cb;
            uint32_t d = base + k * 512 + (cb ^ ((k & 7) << 4));
            cp16(d + BH_OFF, (const char*)Bhz + gb);
            if (HAS_BL) cp16(d + BL_OFF, (const char*)Blz + gb);
        }
        asm volatile("cp.async.commit_group;" ::: "memory");
    };

    auto compute_stage = [&](int s) {
        const uint32_t base = sb + s * STB;
#pragma unroll
        for (int kk = 0; kk < 2; kk++) {
            uint32_t ah[2][4], al[2][4];
#pragma unroll
            for (int mi = 0; mi < 2; mi++) {
                int row = wm * 32 + mi * 16 + (lane & 15);
                uint32_t cb = kk * 32 + ((lane >> 4) << 4);
                uint32_t ad = base + row * 64 + (cb ^ ((row & 3) << 4));
                ldsm4(ah[mi], ad + AH_OFF);
                if (HAS_AL) ldsm4(al[mi], ad + AL_OFF);
            }
            const int kr = kk * 16 + (lane & 15);
            const uint32_t hi16 = (lane >> 4) << 4;
            uint32_t bhA[4], blA[4], bhB[4], blB[4];
            {
                uint32_t cb = wn * 256 + 0 * 32 + hi16;
                uint32_t bd = base + kr * 512 + (cb ^ ((kr & 7) << 4));
                ldsm4t(bhA, bd + BH_OFF);
                if (HAS_BL) ldsm4t(blA, bd + BL_OFF);
            }
#pragma unroll
            for (int nj2 = 0; nj2 < 8; nj2++) {
                uint32_t* ch = (nj2 & 1) ? bhB : bhA;
                uint32_t* cl = (nj2 & 1) ? blB : blA;
                if (nj2 < 7) {
                    uint32_t* nh = (nj2 & 1) ? bhA : bhB;
                    uint32_t* nl = (nj2 & 1) ? blA : blB;
                    uint32_t cb = wn * 256 + (nj2 + 1) * 32 + hi16;
                    uint32_t bd = base + kr * 512 + (cb ^ ((kr & 7) << 4));
                    ldsm4t(nh, bd + BH_OFF);
                    if (HAS_BL) ldsm4t(nl, bd + BL_OFF);
                }
#pragma unroll
                for (int mi = 0; mi < 2; mi++)
#pragma unroll
                    for (int sub = 0; sub < 2; sub++) {
                        int nj = nj2 * 2 + sub;
                        mma16816(acc[mi][nj], ah[mi], &ch[sub * 2]);
                        if (HAS_AL) mma16816(acc[mi][nj], al[mi], &ch[sub * 2]);
                        if (HAS_BL) mma16816(acc[mi][nj], ah[mi], &cl[sub * 2]);
                    }
            }
        }
    };

    for (int p = 0; p < 3 && p < nchunks; p++) load_stage(p, p * BK);
    for (int c = 0; c < nchunks; c++) {
        if (c + 3 < nchunks) load_stage((c + 3) & 3, (c + 3) * BK);
        else asm volatile("cp.async.commit_group;" ::: "memory");
        asm volatile("cp.async.wait_group 2;" ::: "memory");
        __syncthreads();
        compute_stage(c & 3);
        __syncthreads();
    }

    if (z < scalar_z) {
#pragma unroll
        for (int mi = 0; mi < 2; mi++) {
#pragma unroll
            for (int half = 0; half < 2; half++) {
                int row = m0 + wm * 32 + mi * 16 + half * 8 + (lane >> 2);
                if (row >= M) continue;
#pragma unroll
                for (int nj = 0; nj < 16; nj++) {
                    int col = wn * 128 + nj * 8 + (lane & 3) * 2;
                    float2 v;
                    v.x = acc[mi][nj][half * 2 + 0];
                    v.y = acc[mi][nj][half * 2 + 1];
                    if (bias) { v.x += bias[col]; v.y += bias[col + 1]; }
                    if (PC) {
                        __half2 hp(__float2half(v.x), __float2half(v.y));
                        *(__half2*)(PC + zstrC * z + (size_t)row * 256 + col) = hp;
                    } else {
                        *(float2*)(C + zstrC * z + (size_t)row * 256 + col) = v;
                    }
                    if (ohh) {
                        __half b0 = __float2half(v.x);
                        __half b1 = __float2half(v.y);
                        __half2 hp(b0, b1);
                        __half2 lp(__float2half(v.x - __half2float(b0)),
                                   __float2half(v.y - __half2float(b1)));
                        *(__half2*)(ohh + (size_t)row * 256 + col) = hp;
                        *(__half2*)(ohl + (size_t)row * 256 + col) = lp;
                    }
                }
            }
        }
    } else {
        float* sred = (float*)smem;   // [128][2]
#pragma unroll
        for (int mi = 0; mi < 2; mi++) {
#pragma unroll
            for (int half = 0; half < 2; half++) {
                int rowl = wm * 32 + mi * 16 + half * 8 + (lane >> 2);
                int row = m0 + rowl;
                int cl = (row < M) ? row : (M - 1);
                const __half* p1 = P1 ? (P1 + (size_t)src[cl] * 256) : nullptr;
                const __half* p2 = P2 ? (P2 + (size_t)dst[cl] * 256) : nullptr;
                float part = 0.f;
#pragma unroll
                for (int nj = 0; nj < 16; nj++) {
                    int col = wn * 128 + nj * 8 + (lane & 3) * 2;
                    float2 bv = *(const float2*)(sbias + col);
                    float2 wv = *(const float2*)(w2 + col);
                    float2 p1v = make_float2(0.f, 0.f), p2v = make_float2(0.f, 0.f);
                    if (p1) p1v = __half22float2(*(const __half2*)(p1 + col));
                    if (p2) p2v = __half22float2(*(const __half2*)(p2 + col));
                    float v0 = fmaxf(acc[mi][nj][half * 2 + 0] + bv.x + p1v.x + p2v.x, 0.f);
                    float v1 = fmaxf(acc[mi][nj][half * 2 + 1] + bv.y + p1v.y + p2v.y, 0.f);
                    part = fmaf(v0, wv.x, part);
                    part = fmaf(v1, wv.y, part);
                }
                part += __shfl_xor_sync(0xffffffffu, part, 1);
                part += __shfl_xor_sync(0xffffffffu, part, 2);
                if ((lane & 3) == 0) sred[rowl * 2 + wn] = part;
            }
        }
        __syncthreads();
        if (tid < 128) {
            int row = m0 + tid;
            if (row < M) sout[row] = sred[tid * 2] + sred[tid * 2 + 1] + b2[0];
        }
    }
}

// ---------------- fused message + softmax + update (warp per node) -----------
__global__ void msg_update(const float* __restrict__ ae, const int* __restrict__ src,
                           const __half* __restrict__ ghh,
                           const __half* __restrict__ hh_r,   // fp16 h (gather)
                           const float* __restrict__ h_old,   // fp32 h (residual)
                           const float* __restrict__ epsv,
                           float* __restrict__ h_new,
                           __half* __restrict__ hh_w, __half* __restrict__ hl_w,
                           int N)
{
    const int w = (blockIdx.x * blockDim.x + threadIdx.x) >> 5;
    const int lane = threadIdx.x & 31;
    if (w >= N) return;
    const int lo = g_off[w], hi = g_off[w + 1];

    float acc8[8];
#pragma unroll
    for (int q = 0; q < 8; q++) acc8[q] = 0.f;
    float s = 0.f;

    if (hi > lo) {
        float mym = -INFINITY;
        for (int j = lo + lane; j < hi; j += 32)
            mym = fmaxf(mym, ae[g_perm[j]]);
#pragma unroll
        for (int o = 16; o; o >>= 1)
            mym = fmaxf(mym, __shfl_xor_sync(0xffffffffu, mym, o));
        const float m = mym;
        for (int base = lo; base < hi; base += 32) {
            const int j = base + lane;
            int e = 0, sr = 0;
            float c = 0.f;
            if (j < hi) {
                e = g_perm[j];
                c = __expf(ae[e] - m);
                sr = src[e];
            }
            s += c;
            const int cnt = min(32, hi - base);
            for (int i = 0; i < cnt; i++) {
                const float ci = __shfl_sync(0xffffffffu, c, i);
                const int ei = __shfl_sync(0xffffffffu, e, i);
                const int si = __shfl_sync(0xffffffffu, sr, i);
                const uint4 gv = *(const uint4*)(ghh + (size_t)ei * H + lane * 8);
                const uint4 hv16 = *(const uint4*)(hh_r + (size_t)si * H + lane * 8);
                float2 g0 = __half22float2(*(const __half2*)&gv.x);
                float2 g1 = __half22float2(*(const __half2*)&gv.y);
                float2 g2 = __half22float2(*(const __half2*)&gv.z);
                float2 g3 = __half22float2(*(const __half2*)&gv.w);
                float2 q0 = __half22float2(*(const __half2*)&hv16.x);
                float2 q1 = __half22float2(*(const __half2*)&hv16.y);
                float2 q2 = __half22float2(*(const __half2*)&hv16.z);
                float2 q3 = __half22float2(*(const __half2*)&hv16.w);
                acc8[0] = fmaf(ci * g0.x, q0.x, acc8[0]);
                acc8[1] = fmaf(ci * g0.y, q0.y, acc8[1]);
                acc8[2] = fmaf(ci * g1.x, q1.x, acc8[2]);
                acc8[3] = fmaf(ci * g1.y, q1.y, acc8[3]);
                acc8[4] = fmaf(ci * g2.x, q2.x, acc8[4]);
                acc8[5] = fmaf(ci * g2.y, q2.y, acc8[5]);
                acc8[6] = fmaf(ci * g3.x, q3.x, acc8[6]);
                acc8[7] = fmaf(ci * g3.y, q3.y, acc8[7]);
            }
        }
#pragma unroll
        for (int o = 16; o; o >>= 1)
            s += __shfl_xor_sync(0xffffffffu, s, o);
    }

    const float inv = (s > 0.f) ? (1.f / s) : 0.f;
    const float scale = (1.f + epsv[w]) * inv;

    const float4* hrow = (const float4*)(h_old + (size_t)w * H + lane * 8);
    float4 o0 = hrow[0], o1 = hrow[1];
    float4 r0, r1;
    r0.x = fmaf(acc8[0], scale, o0.x); r0.y = fmaf(acc8[1], scale, o0.y);
    r0.z = fmaf(acc8[2], scale, o0.z); r0.w = fmaf(acc8[3], scale, o0.w);
    r1.x = fmaf(acc8[4], scale, o1.x); r1.y = fmaf(acc8[5], scale, o1.y);
    r1.z = fmaf(acc8[6], scale, o1.z); r1.w = fmaf(acc8[7], scale, o1.w);
    float4* orow = (float4*)(h_new + (size_t)w * H + lane * 8);
    orow[0] = r0;
    orow[1] = r1;

    __half2 hp[4], lp[4];
    float vv[8] = {r0.x, r0.y, r0.z, r0.w, r1.x, r1.y, r1.z, r1.w};
#pragma unroll
    for (int q = 0; q < 4; q++) {
        __half b0 = __float2half(vv[q * 2]);
        __half b1 = __float2half(vv[q * 2 + 1]);
        hp[q] = __half2(b0, b1);
        lp[q] = __half2(__float2half(vv[q * 2] - __half2float(b0)),
                        __float2half(vv[q * 2 + 1] - __half2float(b1)));
    }
    *(uint4*)(hh_w + (size_t)w * H + lane * 8) = *(uint4*)hp;
    *(uint4*)(hl_w + (size_t)w * H + lane * 8) = *(uint4*)lp;
}

// ---------------- launch -------------------------------------------------------
extern "C" void kernel_launch(void* const* d_in, const int* in_sizes, int n_in,
                              void* d_out, int out_size)
{
    (void)n_in; (void)out_size;
    const float* node_feats = (const float*)d_in[0];
    const float* gh         = (const float*)d_in[1];
    const int*   src        = (const int*)d_in[2];
    const int*   dst        = (const int*)d_in[3];
    const float* Wn_w       = (const float*)d_in[4];
    const float* Wn_b       = (const float*)d_in[5];
    const float* eps_w1     = (const float*)d_in[6];
    const float* eps_b1     = (const float*)d_in[7];
    const float* eps_w2     = (const float*)d_in[8];
    const float* eps_b2     = (const float*)d_in[9];
    const float* a_w1       = (const float*)d_in[10];
    const float* a_b1       = (const float*)d_in[11];
    const float* a_w2       = (const float*)d_in[12];
    const float* a_b2       = (const float*)d_in[13];

    const int D_IN = 128;
    const int N = in_sizes[0] / D_IN;
    const int E = in_sizes[2];
    const int L = in_sizes[6] / (H * H);

    float* out = (float*)d_out;

    __half *ghh, *nfh, *nfl, *hh0, *hl0, *Wh, *Wl, *wnh, *wnl, *gP;
    float *epsv, *ae;
    cudaGetSymbolAddress((void**)&ghh, g_ghh);
    cudaGetSymbolAddress((void**)&nfh, g_nfh);
    cudaGetSymbolAddress((void**)&nfl, g_nfl);
    cudaGetSymbolAddress((void**)&hh0, g_hh);
    cudaGetSymbolAddress((void**)&hl0, g_hl);
    cudaGetSymbolAddress((void**)&Wh,  g_Wh);
    cudaGetSymbolAddress((void**)&Wl,  g_Wl);
    cudaGetSymbolAddress((void**)&wnh, g_wnh);
    cudaGetSymbolAddress((void**)&wnl, g_wnl);
    cudaGetSymbolAddress((void**)&gP,   g_P);
    cudaGetSymbolAddress((void**)&epsv, g_eps);
    cudaGetSymbolAddress((void**)&ae,   g_ae);

    constexpr int SMEM3 = NSTAGE * (16384 + 32768);   // input proj (3-term)
    constexpr int SMEM2 = NSTAGE * (16384 + 16384);   // node GEMMs (2-term)
    constexpr int SMEM1 = NSTAGE * (8192 + 16384);    // edge GEMM (1-term)
    cudaFuncSetAttribute(mma_gemm<3>, cudaFuncAttributeMaxDynamicSharedMemorySize, SMEM3);
    cudaFuncSetAttribute(mma_gemm<2>, cudaFuncAttributeMaxDynamicSharedMemorySize, SMEM2);
    cudaFuncSetAttribute(mma_gemm<1>, cudaFuncAttributeMaxDynamicSharedMemorySize, SMEM1);

    // one-time prep
    {
        int n4 = (E * H) / 4;
        cvt_split<<<(n4 + 255) / 256, 256>>>(gh, ghh, nullptr, n4);
        n4 = (N * D_IN) / 4;
        cvt_split<<<(n4 + 255) / 256, 256>>>(node_feats, nfh, nfl, n4);
        int totw = L * 1024 * 256 + 128 * 256;
        prep_w<<<(totw + 255) / 256, 256>>>(a_w1, eps_w1, Wn_w, L);
        csr_clear<<<(N + 255) / 256, 256>>>(N);
        csr_hist<<<(E + 255) / 256, 256>>>(dst, E);
        csr_scan<<<1, 256>>>(N, E);
        csr_scatter<<<(E + 255) / 256, 256>>>(dst, E);
    }

    const int nblkN = (N + BM - 1) / BM;
    const int nblkE = (E + BM - 1) / BM;
    const size_t nsec = (size_t)N * H;
    const size_t hbuf = (size_t)N_MAX * H;

    // input projection -> out[0:N*H] fp32 (+ fp16 split into buffer 0)
    mma_gemm<3><<<dim3(nblkN, 1, 1), NTH, SMEM3>>>(
        nfh, nfl, N, D_IN, wnh, wnl,
        out, nullptr, 0, 0, Wn_b, 99,
        nullptr, nullptr, nullptr, nullptr,
        nullptr, nullptr, nullptr, nullptr, hh0, hl0);

    for (int l = 0; l < L; l++) {
        const float* hcur = out + (size_t)l * N * H;
        float*       hnext = out + (size_t)(l + 1) * N * H;
        const __half* WhL = Wh + (size_t)l * 1024 * 256;
        const __half* WlL = Wl + (size_t)l * 1024 * 256;
        __half* hhr = hh0 + (size_t)(l & 1) * hbuf;
        __half* hlr = hl0 + (size_t)(l & 1) * hbuf;
        __half* hhw = hh0 + (size_t)((l + 1) & 1) * hbuf;
        __half* hlw = hl0 + (size_t)((l + 1) & 1) * hbuf;

        // node GEMMs (2-term): z=0 -> P1 fp16, z=1 -> P2 fp16, z=2 -> eps scalar
        mma_gemm<2><<<dim3(nblkN, 1, 3), NTH, SMEM2>>>(
            hhr, hlr, N, H, WhL, WlL,
            nullptr, gP, nsec, (size_t)256 * 256, nullptr, 2,
            eps_b1 + (size_t)l * H, eps_w2 + (size_t)l * H, eps_b2 + l, epsv,
            nullptr, nullptr, nullptr, nullptr, nullptr, nullptr);

        // edge scores -> ae (1-term: A = fp16(gh), B = fp16(W))
        mma_gemm<1><<<dim3(nblkE, 1, 1), NTH, SMEM1>>>(
            ghh, nullptr, E, H, WhL + (size_t)768 * 256, nullptr,
            nullptr, nullptr, 0, 0, nullptr, 0,
            a_b1 + (size_t)l * H, a_w2 + (size_t)l * H, a_b2 + l, ae,
            gP, gP + nsec, src, dst, nullptr, nullptr);

        // fused message + softmax + GIN update (+ fp16 split of h_next)
        msg_update<<<(N * 32 + 255) / 256, 256>>>(
            ae, src, ghh, hhr, hcur, epsv, hnext, hhw, hlw, N);
    }
}

// round 9
// speedup vs baseline: 3.5437x; 1.0478x over previous
#include <cuda_runtime.h>
#include <cuda_fp16.h>
#include <math.h>
#include <stdint.h>

#define H 256
#define N_MAX 10240
#define E_MAX 163840
#define L_MAX 3

#define BM 128
#define BN 256
#define BK 32
#define NTH 256
#define NSTAGE 4

// ---------------- scratch (device globals) ---------------------------------
__device__ __half g_ghh[E_MAX * H];            // gh fp16
__device__ __half g_nfh[N_MAX * 128];
__device__ __half g_nfl[N_MAX * 128];
__device__ __half g_hh[2][N_MAX * H];          // double-buffered per layer
__device__ __half g_hl[2][N_MAX * H];
// combined per-layer weights: rows 0-255 P1W, 256-511 P2W, 512-767 epsW,
// 768-1023 edgeW (each [256k,256n] row-major)
__device__ __half g_Wh[L_MAX * 1024 * 256];
__device__ __half g_wnh[128 * 256];
__device__ __half g_P[2 * N_MAX * H];          // P1,P2 in fp16
__device__ float g_eps[N_MAX];
__device__ float g_ae[E_MAX];
// CSR by dst
__device__ int g_cnt[N_MAX];
__device__ int g_off[N_MAX + 1];
__device__ int g_cur[N_MAX];
__device__ int g_perm[E_MAX];

// ---------------- helpers ----------------------------------------------------
__device__ __forceinline__ uint32_t smem_u32(const void* p) {
    uint32_t a;
    asm("{ .reg .u64 t; cvta.to.shared.u64 t, %1; cvt.u32.u64 %0, t; }" : "=r"(a) : "l"(p));
    return a;
}
__device__ __forceinline__ void cp16(uint32_t dst, const void* src) {
    asm volatile("cp.async.cg.shared.global [%0], [%1], 16;" :: "r"(dst), "l"(src));
}
__device__ __forceinline__ void ldsm4(uint32_t* r, uint32_t addr) {
    asm volatile("ldmatrix.sync.aligned.m8n8.x4.shared.b16 {%0,%1,%2,%3}, [%4];"
                 : "=r"(r[0]), "=r"(r[1]), "=r"(r[2]), "=r"(r[3]) : "r"(addr));
}
__device__ __forceinline__ void ldsm4t(uint32_t* r, uint32_t addr) {
    asm volatile("ldmatrix.sync.aligned.m8n8.x4.trans.shared.b16 {%0,%1,%2,%3}, [%4];"
                 : "=r"(r[0]), "=r"(r[1]), "=r"(r[2]), "=r"(r[3]) : "r"(addr));
}
__device__ __forceinline__ void mma16816(float* c, const uint32_t* a, const uint32_t* b) {
    asm volatile("mma.sync.aligned.m16n8k16.row.col.f32.f16.f16.f32 "
                 "{%0,%1,%2,%3}, {%4,%5,%6,%7}, {%8,%9}, {%0,%1,%2,%3};"
                 : "+f"(c[0]), "+f"(c[1]), "+f"(c[2]), "+f"(c[3])
                 : "r"(a[0]), "r"(a[1]), "r"(a[2]), "r"(a[3]), "r"(b[0]), "r"(b[1]));
}

// ============ shared GEMM machinery (macros over common body) ================
// SMEM stage: A hi [8KB] (+ A lo [8KB] if AL), B hi [16KB]

// ---------------- fp32 -> fp16 hi(/lo) split ---------------------------------
__global__ void cvt_split(const float* __restrict__ x, __half* __restrict__ hi,
                          __half* __restrict__ lo, int n4)
{
    int i = blockIdx.x * blockDim.x + threadIdx.x;
    if (i >= n4) return;
    float4 v = ((const float4*)x)[i];
    __half h0 = __float2half(v.x), h1 = __float2half(v.y);
    __half h2 = __float2half(v.z), h3 = __float2half(v.w);
    __half2 hh0(h0, h1), hh1(h2, h3);
    ((__half2*)hi)[i * 2 + 0] = hh0;
    ((__half2*)hi)[i * 2 + 1] = hh1;
    if (lo) {
        __half2 ll0(__float2half(v.x - __half2float(h0)),
                    __float2half(v.y - __half2float(h1)));
        __half2 ll1(__float2half(v.z - __half2float(h2)),
                    __float2half(v.w - __half2float(h3)));
        ((__half2*)lo)[i * 2 + 0] = ll0;
        ((__half2*)lo)[i * 2 + 1] = ll1;
    }
}

// ---------------- weight prep (hi only) --------------------------------------
__global__ void prep_w(const float* __restrict__ a_w1, const float* __restrict__ eps_w1,
                       const float* __restrict__ Wn_w, int L)
{
    const int totW = L * 1024 * 256;
    const int total = totW + 128 * 256;
    int idx = blockIdx.x * blockDim.x + threadIdx.x;
    if (idx >= total) return;
    float v;
    __half* dh;
    int di;
    if (idx < totW) {
        int l = idx / (1024 * 256);
        int r = (idx / 256) % 1024;
        int n = idx % 256;
        if (r < 512)      v = a_w1[((size_t)l * 768 + r) * 256 + n];
        else if (r < 768) v = eps_w1[((size_t)l * 256 + (r - 512)) * 256 + n];
        else              v = a_w1[((size_t)l * 768 + 512 + (r - 768)) * 256 + n];
        dh = g_Wh; di = idx;
    } else {
        int i2 = idx - totW;
        v = Wn_w[i2];
        dh = g_wnh; di = i2;
    }
    dh[di] = __float2half(v);
}

// ---------------- CSR build ---------------------------------------------------
__global__ void csr_clear(int N) {
    int i = blockIdx.x * blockDim.x + threadIdx.x;
    if (i < N) g_cnt[i] = 0;
}
__global__ void csr_hist(const int* __restrict__ dst, int E) {
    int e = blockIdx.x * blockDim.x + threadIdx.x;
    if (e < E) atomicAdd(&g_cnt[dst[e]], 1);
}
__global__ void csr_scan(int N, int E) {
    __shared__ int sums[256];
    const int tid = threadIdx.x;
    const int chunk = (N + 255) / 256;
    const int base = tid * chunk;
    int s = 0;
    for (int i = 0; i < chunk; i++) {
        int idx = base + i;
        if (idx < N) s += g_cnt[idx];
    }
    sums[tid] = s;
    __syncthreads();
    for (int d = 1; d < 256; d <<= 1) {
        int v = (tid >= d) ? sums[tid - d] : 0;
        __syncthreads();
        sums[tid] += v;
        __syncthreads();
    }
    int run = sums[tid] - s;
    for (int i = 0; i < chunk; i++) {
        int idx = base + i;
        if (idx < N) { g_off[idx] = run; g_cur[idx] = run; run += g_cnt[idx]; }
    }
    if (tid == 255) g_off[N] = E;
}
__global__ void csr_scatter(const int* __restrict__ dst, int E) {
    int e = blockIdx.x * blockDim.x + threadIdx.x;
    if (e < E) {
        int pos = atomicAdd(&g_cur[dst[e]], 1);
        g_perm[pos] = e;
    }
}

// ============ GEMM body macros ================================================
// Declares acc, runs pipelined mainloop over K. Requires: A, AL (maybe null),
// M, K, Bz, sb, tid, lane, wm, wn, m0.  HAS_AL is compile-time.
#define GEMM_MAINLOOP(HAS_AL)                                                  \
    constexpr uint32_t AH_OFF = 0;                                             \
    constexpr uint32_t AL_OFF = 8192;                                          \
    constexpr uint32_t BH_OFF = (HAS_AL) ? 16384u : 8192u;                     \
    constexpr uint32_t STB = BH_OFF + 16384u;                                  \
    float acc[2][16][4];                                                       \
    _Pragma("unroll") for (int mi = 0; mi < 2; mi++)                           \
    _Pragma("unroll") for (int nj = 0; nj < 16; nj++)                          \
    _Pragma("unroll") for (int q = 0; q < 4; q++) acc[mi][nj][q] = 0.f;        \
    const int nchunks = K / BK;                                                \
    auto load_stage = [&](int s, int k0) {                                     \
        const uint32_t base = sb + s * STB;                                    \
        _Pragma("unroll") for (int i = 0; i < 2; i++) {                        \
            int cid = tid + i * NTH;                                           \
            int row = cid >> 2;                                                \
            int cb = (cid & 3) * 16;                                           \
            int grow = m0 + row;                                               \
            if (grow >= M) grow = M - 1;                                       \
            size_t gb = ((size_t)grow * K + k0) * 2 + cb;                      \
            uint32_t d = base + row * 64 + (cb ^ ((row & 3) << 4));            \
            cp16(d + AH_OFF, (const char*)A + gb);                             \
            if (HAS_AL) cp16(d + AL_OFF, (const char*)AL + gb);                \
        }                                                                      \
        _Pragma("unroll") for (int i = 0; i < 4; i++) {                        \
            int cid = tid + i * NTH;                                           \
            int k = cid >> 5;                                                  \
            int cb = (cid & 31) * 16;                                          \
            size_t gb = (size_t)(k0 + k) * 512 + cb;                           \
            uint32_t d = base + k * 512 + (cb ^ ((k & 7) << 4));               \
            cp16(d + BH_OFF, (const char*)Bz + gb);                            \
        }                                                                      \
        asm volatile("cp.async.commit_group;" ::: "memory");                   \
    };                                                                         \
    auto compute_stage = [&](int s) {                                          \
        const uint32_t base = sb + s * STB;                                    \
        _Pragma("unroll") for (int kk = 0; kk < 2; kk++) {                     \
            uint32_t ah[2][4], al[2][4];                                       \
            _Pragma("unroll") for (int mi = 0; mi < 2; mi++) {                 \
                int row = wm * 32 + mi * 16 + (lane & 15);                     \
                uint32_t cb = kk * 32 + ((lane >> 4) << 4);                    \
                uint32_t ad = base + row * 64 + (cb ^ ((row & 3) << 4));       \
                ldsm4(ah[mi], ad + AH_OFF);                                    \
                if (HAS_AL) ldsm4(al[mi], ad + AL_OFF);                        \
            }                                                                  \
            const int kr = kk * 16 + (lane & 15);                              \
            const uint32_t hi16 = (lane >> 4) << 4;                            \
            uint32_t bhA[4], bhB[4];                                           \
            {                                                                  \
                uint32_t cb = wn * 256 + hi16;                                 \
                uint32_t bd = base + kr * 512 + (cb ^ ((kr & 7) << 4));        \
                ldsm4t(bhA, bd + BH_OFF);                                      \
            }                                                                  \
            _Pragma("unroll") for (int nj2 = 0; nj2 < 8; nj2++) {              \
                uint32_t* ch = (nj2 & 1) ? bhB : bhA;                          \
                if (nj2 < 7) {                                                 \
                    uint32_t* nh = (nj2 & 1) ? bhA : bhB;                      \
                    uint32_t cb = wn * 256 + (nj2 + 1) * 32 + hi16;            \
                    uint32_t bd = base + kr * 512 + (cb ^ ((kr & 7) << 4));    \
                    ldsm4t(nh, bd + BH_OFF);                                   \
                }                                                              \
                _Pragma("unroll") for (int mi = 0; mi < 2; mi++)               \
                _Pragma("unroll") for (int sub = 0; sub < 2; sub++) {          \
                    int nj = nj2 * 2 + sub;                                    \
                    mma16816(acc[mi][nj], ah[mi], &ch[sub * 2]);               \
                    if (HAS_AL) mma16816(acc[mi][nj], al[mi], &ch[sub * 2]);   \
                }                                                              \
            }                                                                  \
        }                                                                      \
    };                                                                         \
    for (int p = 0; p < 3 && p < nchunks; p++) load_stage(p, p * BK);          \
    for (int c = 0; c < nchunks; c++) {                                        \
        if (c + 3 < nchunks) load_stage((c + 3) & 3, (c + 3) * BK);            \
        else asm volatile("cp.async.commit_group;" ::: "memory");              \
        asm volatile("cp.async.wait_group 2;" ::: "memory");                   \
        __syncthreads();                                                       \
        compute_stage(c & 3);                                                  \
        __syncthreads();                                                       \
    }

// scalar epilogue: sout[row] = sum relu(acc + sbias + P1[src]+P2[dst]) . w2 + b2
#define GEMM_EPI_SCALAR(P1, P2, SBIAS, W2, B2, SOUT)                           \
    {                                                                          \
        float* sred = (float*)smem;                                            \
        _Pragma("unroll") for (int mi = 0; mi < 2; mi++)                       \
        _Pragma("unroll") for (int half = 0; half < 2; half++) {               \
            int rowl = wm * 32 + mi * 16 + half * 8 + (lane >> 2);             \
            int row = m0 + rowl;                                               \
            int cl = (row < M) ? row : (M - 1);                                \
            const __half* p1 = (P1) ? ((P1) + (size_t)src[cl] * 256) : nullptr;\
            const __half* p2 = (P2) ? ((P2) + (size_t)dst[cl] * 256) : nullptr;\
            float part = 0.f;                                                  \
            _Pragma("unroll") for (int nj = 0; nj < 16; nj++) {                \
                int col = wn * 128 + nj * 8 + (lane & 3) * 2;                  \
                float2 bv = *(const float2*)((SBIAS) + col);                   \
                float2 wv = *(const float2*)((W2) + col);                      \
                float2 p1v = make_float2(0.f, 0.f), p2v = make_float2(0.f, 0.f);\
                if (p1) p1v = __half22float2(*(const __half2*)(p1 + col));     \
                if (p2) p2v = __half22float2(*(const __half2*)(p2 + col));     \
                float v0 = fmaxf(acc[mi][nj][half * 2 + 0] + bv.x + p1v.x + p2v.x, 0.f);\
                float v1 = fmaxf(acc[mi][nj][half * 2 + 1] + bv.y + p1v.y + p2v.y, 0.f);\
                part = fmaf(v0, wv.x, part);                                   \
                part = fmaf(v1, wv.y, part);                                   \
            }                                                                  \
            part += __shfl_xor_sync(0xffffffffu, part, 1);                     \
            part += __shfl_xor_sync(0xffffffffu, part, 2);                     \
            if ((lane & 3) == 0) sred[rowl * 2 + wn] = part;                   \
        }                                                                      \
        __syncthreads();                                                       \
        if (tid < 128) {                                                       \
            int row = m0 + tid;                                                \
            if (row < M) (SOUT)[row] = sred[tid * 2] + sred[tid * 2 + 1] + (B2)[0];\
        }                                                                      \
    }

// ---------------- input projection GEMM (2-term exact-A) ----------------------
__global__ void __launch_bounds__(NTH, 1)
proj_gemm(const __half* __restrict__ A, const __half* __restrict__ AL,
          int M, int K, const __half* __restrict__ Bz,
          const float* __restrict__ bias, float* __restrict__ C,
          __half* __restrict__ ohh, __half* __restrict__ ohl)
{
    extern __shared__ char smem[];
    const uint32_t sb = smem_u32(smem);
    const int tid = threadIdx.x;
    const int lane = tid & 31;
    const int wid = tid >> 5;
    const int wm = wid & 3;
    const int wn = wid >> 2;
    const int m0 = blockIdx.x * BM;

    GEMM_MAINLOOP(true)

#pragma unroll
    for (int mi = 0; mi < 2; mi++) {
#pragma unroll
        for (int half = 0; half < 2; half++) {
            int row = m0 + wm * 32 + mi * 16 + half * 8 + (lane >> 2);
            if (row >= M) continue;
#pragma unroll
            for (int nj = 0; nj < 16; nj++) {
                int col = wn * 128 + nj * 8 + (lane & 3) * 2;
                float2 v;
                v.x = acc[mi][nj][half * 2 + 0] + bias[col];
                v.y = acc[mi][nj][half * 2 + 1] + bias[col + 1];
                *(float2*)(C + (size_t)row * 256 + col) = v;
                __half b0 = __float2half(v.x);
                __half b1 = __float2half(v.y);
                *(__half2*)(ohh + (size_t)row * 256 + col) = __half2(b0, b1);
                *(__half2*)(ohl + (size_t)row * 256 + col) =
                    __half2(__float2half(v.x - __half2float(b0)),
                            __float2half(v.y - __half2float(b1)));
            }
        }
    }
}

// ---------------- node GEMM: P1/P2 (1-term, fp16 out) --------------------------
__global__ void __launch_bounds__(NTH, 1)
node_gemm(const __half* __restrict__ A, int M, int K,
          const __half* __restrict__ Bh, __half* __restrict__ PC)
{
    extern __shared__ char smem[];
    const uint32_t sb = smem_u32(smem);
    const int tid = threadIdx.x;
    const int lane = tid & 31;
    const int wid = tid >> 5;
    const int wm = wid & 3;
    const int wn = wid >> 2;
    const int m0 = blockIdx.x * BM;
    const int z = blockIdx.z;
    const __half* AL = nullptr;
    const __half* Bz = Bh + (size_t)z * 65536;

    GEMM_MAINLOOP(false)

    __half* Pz = PC + (size_t)z * N_MAX * H;
#pragma unroll
    for (int mi = 0; mi < 2; mi++) {
#pragma unroll
        for (int half = 0; half < 2; half++) {
            int row = m0 + wm * 32 + mi * 16 + half * 8 + (lane >> 2);
            if (row >= M) continue;
#pragma unroll
            for (int nj = 0; nj < 16; nj++) {
                int col = wn * 128 + nj * 8 + (lane & 3) * 2;
                __half2 hp(__float2half(acc[mi][nj][half * 2 + 0]),
                           __float2half(acc[mi][nj][half * 2 + 1]));
                *(__half2*)(Pz + (size_t)row * 256 + col) = hp;
            }
        }
    }
}

// ---------------- edge + eps GEMM (1-term, scalar epilogues) -------------------
// z=0: edge scores (M=E, A=ghh, B=+768*256, P1/P2 gather) -> ae
// z=1: eps (M=N, A=hh, B=+512*256) -> epsv
__global__ void __launch_bounds__(NTH, 1)
edge_eps_gemm(const __half* __restrict__ Aedge, int E,
              const __half* __restrict__ Anode, int Nn,
              const __half* __restrict__ WhL,
              const float* __restrict__ a_b1, const float* __restrict__ a_w2,
              const float* __restrict__ a_b2, float* __restrict__ ae,
              const __half* __restrict__ P1, const __half* __restrict__ P2,
              const int* __restrict__ src, const int* __restrict__ dst,
              const float* __restrict__ eps_b1, const float* __restrict__ eps_w2,
              const float* __restrict__ eps_b2, float* __restrict__ epsv)
{
    extern __shared__ char smem[];
    const uint32_t sb = smem_u32(smem);
    const int tid = threadIdx.x;
    const int lane = tid & 31;
    const int wid = tid >> 5;
    const int wm = wid & 3;
    const int wn = wid >> 2;
    const int m0 = blockIdx.x * BM;
    const int z = blockIdx.z;
    const int K = H;

    const __half* A = (z == 0) ? Aedge : Anode;
    const __half* AL = nullptr;
    const int M = (z == 0) ? E : Nn;
    if (m0 >= M) return;
    const __half* Bz = WhL + (size_t)((z == 0) ? 768 : 512) * 256;

    GEMM_MAINLOOP(false)

    if (z == 0) {
        GEMM_EPI_SCALAR(P1, P2, a_b1, a_w2, a_b2, ae)
    } else {
        GEMM_EPI_SCALAR((const __half*)nullptr, (const __half*)nullptr,
                        eps_b1, eps_w2, eps_b2, epsv)
    }
}

// ---------------- fused message + softmax + update (warp per node) -----------
__global__ void msg_update(const float* __restrict__ ae, const int* __restrict__ src,
                           const __half* __restrict__ ghh,
                           const __half* __restrict__ hh_r,
                           const float* __restrict__ h_old,
                           const float* __restrict__ epsv,
                           float* __restrict__ h_new,
                           __half* __restrict__ hh_w, __half* __restrict__ hl_w,
                           int N)
{
    const int w = (blockIdx.x * blockDim.x + threadIdx.x) >> 5;
    const int lane = threadIdx.x & 31;
    if (w >= N) return;
    const int lo = g_off[w], hi = g_off[w + 1];

    float acc8[8];
#pragma unroll
    for (int q = 0; q < 8; q++) acc8[q] = 0.f;
    float s = 0.f;

    if (hi > lo) {
        float mym = -INFINITY;
        for (int j = lo + lane; j < hi; j += 32)
            mym = fmaxf(mym, ae[g_perm[j]]);
#pragma unroll
        for (int o = 16; o; o >>= 1)
            mym = fmaxf(mym, __shfl_xor_sync(0xffffffffu, mym, o));
        const float m = mym;
        for (int base = lo; base < hi; base += 32) {
            const int j = base + lane;
            int e = 0, sr = 0;
            float c = 0.f;
            if (j < hi) {
                e = g_perm[j];
                c = __expf(ae[e] - m);
                sr = src[e];
            }
            s += c;
            const int cnt = min(32, hi - base);
            for (int i = 0; i < cnt; i++) {
                const float ci = __shfl_sync(0xffffffffu, c, i);
                const int ei = __shfl_sync(0xffffffffu, e, i);
                const int si = __shfl_sync(0xffffffffu, sr, i);
                const uint4 gv = *(const uint4*)(ghh + (size_t)ei * H + lane * 8);
                const uint4 hv16 = *(const uint4*)(hh_r + (size_t)si * H + lane * 8);
                float2 g0 = __half22float2(*(const __half2*)&gv.x);
                float2 g1 = __half22float2(*(const __half2*)&gv.y);
                float2 g2 = __half22float2(*(const __half2*)&gv.z);
                float2 g3 = __half22float2(*(const __half2*)&gv.w);
                float2 q0 = __half22float2(*(const __half2*)&hv16.x);
                float2 q1 = __half22float2(*(const __half2*)&hv16.y);
                float2 q2 = __half22float2(*(const __half2*)&hv16.z);
                float2 q3 = __half22float2(*(const __half2*)&hv16.w);
                acc8[0] = fmaf(ci * g0.x, q0.x, acc8[0]);
                acc8[1] = fmaf(ci * g0.y, q0.y, acc8[1]);
                acc8[2] = fmaf(ci * g1.x, q1.x, acc8[2]);
                acc8[3] = fmaf(ci * g1.y, q1.y, acc8[3]);
                acc8[4] = fmaf(ci * g2.x, q2.x, acc8[4]);
                acc8[5] = fmaf(ci * g2.y, q2.y, acc8[5]);
                acc8[6] = fmaf(ci * g3.x, q3.x, acc8[6]);
                acc8[7] = fmaf(ci * g3.y, q3.y, acc8[7]);
            }
        }
#pragma unroll
        for (int o = 16; o; o >>= 1)
            s += __shfl_xor_sync(0xffffffffu, s, o);
    }

    const float inv = (s > 0.f) ? (1.f / s) : 0.f;
    const float scale = (1.f + epsv[w]) * inv;

    const float4* hrow = (const float4*)(h_old + (size_t)w * H + lane * 8);
    float4 o0 = hrow[0], o1 = hrow[1];
    float4 r0, r1;
    r0.x = fmaf(acc8[0], scale, o0.x); r0.y = fmaf(acc8[1], scale, o0.y);
    r0.z = fmaf(acc8[2], scale, o0.z); r0.w = fmaf(acc8[3], scale, o0.w);
    r1.x = fmaf(acc8[4], scale, o1.x); r1.y = fmaf(acc8[5], scale, o1.y);
    r1.z = fmaf(acc8[6], scale, o1.z); r1.w = fmaf(acc8[7], scale, o1.w);
    float4* orow = (float4*)(h_new + (size_t)w * H + lane * 8);
    orow[0] = r0;
    orow[1] = r1;

    __half2 hp[4], lp[4];
    float vv[8] = {r0.x, r0.y, r0.z, r0.w, r1.x, r1.y, r1.z, r1.w};
#pragma unroll
    for (int q = 0; q < 4; q++) {
        __half b0 = __float2half(vv[q * 2]);
        __half b1 = __float2half(vv[q * 2 + 1]);
        hp[q] = __half2(b0, b1);
        lp[q] = __half2(__float2half(vv[q * 2] - __half2float(b0)),
                        __float2half(vv[q * 2 + 1] - __half2float(b1)));
    }
    *(uint4*)(hh_w + (size_t)w * H + lane * 8) = *(uint4*)hp;
    *(uint4*)(hl_w + (size_t)w * H + lane * 8) = *(uint4*)lp;
}

// ---------------- launch -------------------------------------------------------
extern "C" void kernel_launch(void* const* d_in, const int* in_sizes, int n_in,
                              void* d_out, int out_size)
{
    (void)n_in; (void)out_size;
    const float* node_feats = (const float*)d_in[0];
    const float* gh         = (const float*)d_in[1];
    const int*   src        = (const int*)d_in[2];
    const int*   dst        = (const int*)d_in[3];
    const float* Wn_w       = (const float*)d_in[4];
    const float* Wn_b       = (const float*)d_in[5];
    const float* eps_w1     = (const float*)d_in[6];
    const float* eps_b1     = (const float*)d_in[7];
    const float* eps_w2     = (const float*)d_in[8];
    const float* eps_b2     = (const float*)d_in[9];
    const float* a_w1       = (const float*)d_in[10];
    const float* a_b1       = (const float*)d_in[11];
    const float* a_w2       = (const float*)d_in[12];
    const float* a_b2       = (const float*)d_in[13];

    const int D_IN = 128;
    const int N = in_sizes[0] / D_IN;
    const int E = in_sizes[2];
    const int L = in_sizes[6] / (H * H);

    float* out = (float*)d_out;

    __half *ghh, *nfh, *nfl, *hh0, *hl0, *Wh, *wnh, *gP;
    float *epsv, *ae;
    cudaGetSymbolAddress((void**)&ghh, g_ghh);
    cudaGetSymbolAddress((void**)&nfh, g_nfh);
    cudaGetSymbolAddress((void**)&nfl, g_nfl);
    cudaGetSymbolAddress((void**)&hh0, g_hh);
    cudaGetSymbolAddress((void**)&hl0, g_hl);
    cudaGetSymbolAddress((void**)&Wh,  g_Wh);
    cudaGetSymbolAddress((void**)&wnh, g_wnh);
    cudaGetSymbolAddress((void**)&gP,   g_P);
    cudaGetSymbolAddress((void**)&epsv, g_eps);
    cudaGetSymbolAddress((void**)&ae,   g_ae);

    constexpr int SMEM2 = NSTAGE * (16384 + 16384);   // 2-term (proj)
    constexpr int SMEM1 = NSTAGE * (8192 + 16384);    // 1-term
    cudaFuncSetAttribute(proj_gemm, cudaFuncAttributeMaxDynamicSharedMemorySize, SMEM2);
    cudaFuncSetAttribute(node_gemm, cudaFuncAttributeMaxDynamicSharedMemorySize, SMEM1);
    cudaFuncSetAttribute(edge_eps_gemm, cudaFuncAttributeMaxDynamicSharedMemorySize, SMEM1);

    // one-time prep
    {
        int n4 = (E * H) / 4;
        cvt_split<<<(n4 + 255) / 256, 256>>>(gh, ghh, nullptr, n4);
        n4 = (N * D_IN) / 4;
        cvt_split<<<(n4 + 255) / 256, 256>>>(node_feats, nfh, nfl, n4);
        int totw = L * 1024 * 256 + 128 * 256;
        prep_w<<<(totw + 255) / 256, 256>>>(a_w1, eps_w1, Wn_w, L);
        csr_clear<<<(N + 255) / 256, 256>>>(N);
        csr_hist<<<(E + 255) / 256, 256>>>(dst, E);
        csr_scan<<<1, 256>>>(N, E);
        csr_scatter<<<(E + 255) / 256, 256>>>(dst, E);
    }

    const int nblkN = (N + BM - 1) / BM;
    const int nblkE = (E + BM - 1) / BM;
    const size_t hbuf = (size_t)N_MAX * H;

    // input projection -> out[0:N*H] fp32 (+ fp16 split into buffer 0)
    proj_gemm<<<dim3(nblkN, 1, 1), NTH, SMEM2>>>(
        nfh, nfl, N, D_IN, wnh, Wn_b, out, hh0, hl0);

    for (int l = 0; l < L; l++) {
        const float* hcur = out + (size_t)l * N * H;
        float*       hnext = out + (size_t)(l + 1) * N * H;
        const __half* WhL = Wh + (size_t)l * 1024 * 256;
        __half* hhr = hh0 + (size_t)(l & 1) * hbuf;
        __half* hhw = hh0 + (size_t)((l + 1) & 1) * hbuf;
        __half* hlw = hl0 + (size_t)((l + 1) & 1) * hbuf;

        // P1/P2 (1-term, fp16 out)
        node_gemm<<<dim3(nblkN, 1, 2), NTH, SMEM1>>>(hhr, N, H, WhL, gP);

        // edge scores + eps in one launch
        edge_eps_gemm<<<dim3(nblkE, 1, 2), NTH, SMEM1>>>(
            ghh, E, hhr, N, WhL,
            a_b1 + (size_t)l * H, a_w2 + (size_t)l * H, a_b2 + l, ae,
            gP, gP + hbuf, src, dst,
            eps_b1 + (size_t)l * H, eps_w2 + (size_t)l * H, eps_b2 + l, epsv);

        // fused message + softmax + GIN update (+ fp16 split of h_next)
        msg_update<<<(N * 32 + 255) / 256, 256>>>(
            ae, src, ghh, hhr, hcur, epsv, hnext, hhw, hlw, N);
    }
}

// round 10
// speedup vs baseline: 3.7004x; 1.0442x over previous
#include <cuda_runtime.h>
#include <cuda_fp16.h>
#include <math.h>
#include <stdint.h>

#define H 256
#define N_MAX 10240
#define E_MAX 163840
#define L_MAX 3

#define BM 128
#define BN 256
#define BK 32
#define NTH 256
#define NSTAGE 5

// ---------------- scratch (device globals) ---------------------------------
__device__ __half g_ghh[E_MAX * H];            // gh fp16
__device__ __half g_nfh[N_MAX * 128];
__device__ __half g_nfl[N_MAX * 128];
__device__ __half g_hh[2][N_MAX * H];          // double-buffered per layer
__device__ __half g_hl[2][N_MAX * H];
// combined per-layer weights: rows 0-255 P1W, 256-511 P2W, 512-767 epsW,
// 768-1023 edgeW (each [256k,256n] row-major)
__device__ __half g_Wh[L_MAX * 1024 * 256];
__device__ __half g_wnh[128 * 256];
__device__ __half g_P[2 * N_MAX * H];          // P1,P2 in fp16
__device__ float g_eps[N_MAX];
__device__ float g_ae[E_MAX];
// CSR by dst
__device__ int g_cnt[N_MAX];
__device__ int g_off[N_MAX + 1];
__device__ int g_cur[N_MAX];
__device__ int g_perm[E_MAX];

// ---------------- helpers ----------------------------------------------------
__device__ __forceinline__ uint32_t smem_u32(const void* p) {
    uint32_t a;
    asm("{ .reg .u64 t; cvta.to.shared.u64 t, %1; cvt.u32.u64 %0, t; }" : "=r"(a) : "l"(p));
    return a;
}
__device__ __forceinline__ void cp16(uint32_t dst, const void* src) {
    asm volatile("cp.async.cg.shared.global [%0], [%1], 16;" :: "r"(dst), "l"(src));
}
__device__ __forceinline__ void ldsm4(uint32_t* r, uint32_t addr) {
    asm volatile("ldmatrix.sync.aligned.m8n8.x4.shared.b16 {%0,%1,%2,%3}, [%4];"
                 : "=r"(r[0]), "=r"(r[1]), "=r"(r[2]), "=r"(r[3]) : "r"(addr));
}
__device__ __forceinline__ void ldsm4t(uint32_t* r, uint32_t addr) {
    asm volatile("ldmatrix.sync.aligned.m8n8.x4.trans.shared.b16 {%0,%1,%2,%3}, [%4];"
                 : "=r"(r[0]), "=r"(r[1]), "=r"(r[2]), "=r"(r[3]) : "r"(addr));
}
__device__ __forceinline__ void mma16816(float* c, const uint32_t* a, const uint32_t* b) {
    asm volatile("mma.sync.aligned.m16n8k16.row.col.f32.f16.f16.f32 "
                 "{%0,%1,%2,%3}, {%4,%5,%6,%7}, {%8,%9}, {%0,%1,%2,%3};"
                 : "+f"(c[0]), "+f"(c[1]), "+f"(c[2]), "+f"(c[3])
                 : "r"(a[0]), "r"(a[1]), "r"(a[2]), "r"(a[3]), "r"(b[0]), "r"(b[1]));
}

// ---------------- gh cvt (fp16 hi) + csr_clear fused --------------------------
__global__ void cvt_gh_clear(const float* __restrict__ x, __half* __restrict__ hi,
                             int n4, int Nclr)
{
    int i = blockIdx.x * blockDim.x + threadIdx.x;
    if (i < Nclr) g_cnt[i] = 0;
    if (i >= n4) return;
    float4 v = ((const float4*)x)[i];
    __half2 hh0(__float2half(v.x), __float2half(v.y));
    __half2 hh1(__float2half(v.z), __float2half(v.w));
    ((__half2*)hi)[i * 2 + 0] = hh0;
    ((__half2*)hi)[i * 2 + 1] = hh1;
}

// ---------------- nf cvt (fp16 hi/lo) + csr_hist fused ------------------------
__global__ void cvt_nf_hist(const float* __restrict__ x, __half* __restrict__ hi,
                            __half* __restrict__ lo, int n4,
                            const int* __restrict__ dst, int E)
{
    int i = blockIdx.x * blockDim.x + threadIdx.x;
    if (i < E) atomicAdd(&g_cnt[dst[i]], 1);
    if (i >= n4) return;
    float4 v = ((const float4*)x)[i];
    __half h0 = __float2half(v.x), h1 = __float2half(v.y);
    __half h2 = __float2half(v.z), h3 = __float2half(v.w);
    ((__half2*)hi)[i * 2 + 0] = __half2(h0, h1);
    ((__half2*)hi)[i * 2 + 1] = __half2(h2, h3);
    ((__half2*)lo)[i * 2 + 0] = __half2(__float2half(v.x - __half2float(h0)),
                                        __float2half(v.y - __half2float(h1)));
    ((__half2*)lo)[i * 2 + 1] = __half2(__float2half(v.z - __half2float(h2)),
                                        __float2half(v.w - __half2float(h3)));
}

// ---------------- weight prep (hi only) --------------------------------------
__global__ void prep_w(const float* __restrict__ a_w1, const float* __restrict__ eps_w1,
                       const float* __restrict__ Wn_w, int L)
{
    const int totW = L * 1024 * 256;
    const int total = totW + 128 * 256;
    int idx = blockIdx.x * blockDim.x + threadIdx.x;
    if (idx >= total) return;
    float v;
    __half* dh;
    int di;
    if (idx < totW) {
        int l = idx / (1024 * 256);
        int r = (idx / 256) % 1024;
        int n = idx % 256;
        if (r < 512)      v = a_w1[((size_t)l * 768 + r) * 256 + n];
        else if (r < 768) v = eps_w1[((size_t)l * 256 + (r - 512)) * 256 + n];
        else              v = a_w1[((size_t)l * 768 + 512 + (r - 768)) * 256 + n];
        dh = g_Wh; di = idx;
    } else {
        int i2 = idx - totW;
        v = Wn_w[i2];
        dh = g_wnh; di = i2;
    }
    dh[di] = __float2half(v);
}

// ---------------- CSR scan + scatter ------------------------------------------
__global__ void csr_scan(int N, int E) {
    __shared__ int sums[256];
    const int tid = threadIdx.x;
    const int chunk = (N + 255) / 256;
    const int base = tid * chunk;
    int s = 0;
    for (int i = 0; i < chunk; i++) {
        int idx = base + i;
        if (idx < N) s += g_cnt[idx];
    }
    sums[tid] = s;
    __syncthreads();
    for (int d = 1; d < 256; d <<= 1) {
        int v = (tid >= d) ? sums[tid - d] : 0;
        __syncthreads();
        sums[tid] += v;
        __syncthreads();
    }
    int run = sums[tid] - s;
    for (int i = 0; i < chunk; i++) {
        int idx = base + i;
        if (idx < N) { g_off[idx] = run; g_cur[idx] = run; run += g_cnt[idx]; }
    }
    if (tid == 255) g_off[N] = E;
}
__global__ void csr_scatter(const int* __restrict__ dst, int E) {
    int e = blockIdx.x * blockDim.x + threadIdx.x;
    if (e < E) {
        int pos = atomicAdd(&g_cur[dst[e]], 1);
        g_perm[pos] = e;
    }
}

// ============ GEMM body macros ================================================
// 5-stage pipeline, prefetch distance 3, wait_group 2, ONE barrier per iter.
// Requires: A, AL (maybe null), M, K, Bz, sb, tid, lane, wm, wn, m0.
#define GEMM_MAINLOOP(HAS_AL)                                                  \
    constexpr uint32_t AH_OFF = 0;                                             \
    constexpr uint32_t AL_OFF = 8192;                                          \
    constexpr uint32_t BH_OFF = (HAS_AL) ? 16384u : 8192u;                     \
    constexpr uint32_t STB = BH_OFF + 16384u;                                  \
    float acc[2][16][4];                                                       \
    _Pragma("unroll") for (int mi = 0; mi < 2; mi++)                           \
    _Pragma("unroll") for (int nj = 0; nj < 16; nj++)                          \
    _Pragma("unroll") for (int q = 0; q < 4; q++) acc[mi][nj][q] = 0.f;        \
    const int nchunks = K / BK;                                                \
    auto load_stage = [&](int s, int k0) {                                     \
        const uint32_t base = sb + s * STB;                                    \
        _Pragma("unroll") for (int i = 0; i < 2; i++) {                        \
            int cid = tid + i * NTH;                                           \
            int row = cid >> 2;                                                \
            int cb = (cid & 3) * 16;                                           \
            int grow = m0 + row;                                               \
            if (grow >= M) grow = M - 1;                                       \
            size_t gb = ((size_t)grow * K + k0) * 2 + cb;                      \
            uint32_t d = base + row * 64 + (cb ^ ((row & 3) << 4));            \
            cp16(d + AH_OFF, (const char*)A + gb);                             \
            if (HAS_AL) cp16(d + AL_OFF, (const char*)AL + gb);                \
        }                                                                      \
        _Pragma("unroll") for (int i = 0; i < 4; i++) {                        \
            int cid = tid + i * NTH;                                           \
            int k = cid >> 5;                                                  \
            int cb = (cid & 31) * 16;                                          \
            size_t gb = (size_t)(k0 + k) * 512 + cb;                           \
            uint32_t d = base + k * 512 + (cb ^ ((k & 7) << 4));               \
            cp16(d + BH_OFF, (const char*)Bz + gb);                            \
        }                                                                      \
        asm volatile("cp.async.commit_group;" ::: "memory");                   \
    };                                                                         \
    auto compute_stage = [&](int s) {                                          \
        const uint32_t base = sb + s * STB;                                    \
        _Pragma("unroll") for (int kk = 0; kk < 2; kk++) {                     \
            uint32_t ah[2][4], al[2][4];                                       \
            _Pragma("unroll") for (int mi = 0; mi < 2; mi++) {                 \
                int row = wm * 32 + mi * 16 + (lane & 15);                     \
                uint32_t cb = kk * 32 + ((lane >> 4) << 4);                    \
                uint32_t ad = base + row * 64 + (cb ^ ((row & 3) << 4));       \
                ldsm4(ah[mi], ad + AH_OFF);                                    \
                if (HAS_AL) ldsm4(al[mi], ad + AL_OFF);                        \
            }                                                                  \
            const int kr = kk * 16 + (lane & 15);                              \
            const uint32_t hi16 = (lane >> 4) << 4;                            \
            uint32_t bhA[4], bhB[4];                                           \
            {                                                                  \
                uint32_t cb = wn * 256 + hi16;                                 \
                uint32_t bd = base + kr * 512 + (cb ^ ((kr & 7) << 4));        \
                ldsm4t(bhA, bd + BH_OFF);                                      \
            }                                                                  \
            _Pragma("unroll") for (int nj2 = 0; nj2 < 8; nj2++) {              \
                uint32_t* ch = (nj2 & 1) ? bhB : bhA;                          \
                if (nj2 < 7) {                                                 \
                    uint32_t* nh = (nj2 & 1) ? bhA : bhB;                      \
                    uint32_t cb = wn * 256 + (nj2 + 1) * 32 + hi16;            \
                    uint32_t bd = base + kr * 512 + (cb ^ ((kr & 7) << 4));    \
                    ldsm4t(nh, bd + BH_OFF);                                   \
                }                                                              \
                _Pragma("unroll") for (int mi = 0; mi < 2; mi++)               \
                _Pragma("unroll") for (int sub = 0; sub < 2; sub++) {          \
                    int nj = nj2 * 2 + sub;                                    \
                    mma16816(acc[mi][nj], ah[mi], &ch[sub * 2]);               \
                    if (HAS_AL) mma16816(acc[mi][nj], al[mi], &ch[sub * 2]);   \
                }                                                              \
            }                                                                  \
        }                                                                      \
    };                                                                         \
    for (int p = 0; p < 3 && p < nchunks; p++) load_stage(p, p * BK);          \
    {                                                                          \
        int cs = 0, ls = 3;                                                    \
        for (int c = 0; c < nchunks; c++) {                                    \
            if (c + 3 < nchunks) load_stage(ls, (c + 3) * BK);                 \
            else asm volatile("cp.async.commit_group;" ::: "memory");          \
            asm volatile("cp.async.wait_group 2;" ::: "memory");               \
            __syncthreads();                                                   \
            compute_stage(cs);                                                 \
            if (++cs == NSTAGE) cs = 0;                                        \
            if (++ls == NSTAGE) ls = 0;                                        \
        }                                                                      \
    }

// scalar epilogue: sout[row] = sum relu(acc + sbias + P1[src]+P2[dst]) . w2 + b2
#define GEMM_EPI_SCALAR(P1, P2, SBIAS, W2, B2, SOUT)                           \
    {                                                                          \
        float* sred = (float*)smem;                                            \
        _Pragma("unroll") for (int mi = 0; mi < 2; mi++)                       \
        _Pragma("unroll") for (int half = 0; half < 2; half++) {               \
            int rowl = wm * 32 + mi * 16 + half * 8 + (lane >> 2);             \
            int row = m0 + rowl;                                               \
            int cl = (row < M) ? row : (M - 1);                                \
            const __half* p1 = (P1) ? ((P1) + (size_t)src[cl] * 256) : nullptr;\
            const __half* p2 = (P2) ? ((P2) + (size_t)dst[cl] * 256) : nullptr;\
            float part = 0.f;                                                  \
            _Pragma("unroll") for (int nj = 0; nj < 16; nj++) {                \
                int col = wn * 128 + nj * 8 + (lane & 3) * 2;                  \
                float2 bv = *(const float2*)((SBIAS) + col);                   \
                float2 wv = *(const float2*)((W2) + col);                      \
                float2 p1v = make_float2(0.f, 0.f), p2v = make_float2(0.f, 0.f);\
                if (p1) p1v = __half22float2(*(const __half2*)(p1 + col));     \
                if (p2) p2v = __half22float2(*(const __half2*)(p2 + col));     \
                float v0 = fmaxf(acc[mi][nj][half * 2 + 0] + bv.x + p1v.x + p2v.x, 0.f);\
                float v1 = fmaxf(acc[mi][nj][half * 2 + 1] + bv.y + p1v.y + p2v.y, 0.f);\
                part = fmaf(v0, wv.x, part);                                   \
                part = fmaf(v1, wv.y, part);                                   \
            }                                                                  \
            part += __shfl_xor_sync(0xffffffffu, part, 1);                     \
            part += __shfl_xor_sync(0xffffffffu, part, 2);                     \
            if ((lane & 3) == 0) sred[rowl * 2 + wn] = part;                   \
        }                                                                      \
        __syncthreads();                                                       \
        if (tid < 128) {                                                       \
            int row = m0 + tid;                                                \
            if (row < M) (SOUT)[row] = sred[tid * 2] + sred[tid * 2 + 1] + (B2)[0];\
        }                                                                      \
    }

// ---------------- input projection GEMM (2-term exact-A) ----------------------
__global__ void __launch_bounds__(NTH, 1)
proj_gemm(const __half* __restrict__ A, const __half* __restrict__ AL,
          int M, int K, const __half* __restrict__ Bz,
          const float* __restrict__ bias, float* __restrict__ C,
          __half* __restrict__ ohh, __half* __restrict__ ohl)
{
    extern __shared__ char smem[];
    const uint32_t sb = smem_u32(smem);
    const int tid = threadIdx.x;
    const int lane = tid & 31;
    const int wid = tid >> 5;
    const int wm = wid & 3;
    const int wn = wid >> 2;
    const int m0 = blockIdx.x * BM;

    GEMM_MAINLOOP(true)

#pragma unroll
    for (int mi = 0; mi < 2; mi++) {
#pragma unroll
        for (int half = 0; half < 2; half++) {
            int row = m0 + wm * 32 + mi * 16 + half * 8 + (lane >> 2);
            if (row >= M) continue;
#pragma unroll
            for (int nj = 0; nj < 16; nj++) {
                int col = wn * 128 + nj * 8 + (lane & 3) * 2;
                float2 v;
                v.x = acc[mi][nj][half * 2 + 0] + bias[col];
                v.y = acc[mi][nj][half * 2 + 1] + bias[col + 1];
                *(float2*)(C + (size_t)row * 256 + col) = v;
                __half b0 = __float2half(v.x);
                __half b1 = __float2half(v.y);
                *(__half2*)(ohh + (size_t)row * 256 + col) = __half2(b0, b1);
                *(__half2*)(ohl + (size_t)row * 256 + col) =
                    __half2(__float2half(v.x - __half2float(b0)),
                            __float2half(v.y - __half2float(b1)));
            }
        }
    }
}

// ---------------- node GEMM: P1/P2 (1-term, fp16 out) --------------------------
__global__ void __launch_bounds__(NTH, 1)
node_gemm(const __half* __restrict__ A, int M, int K,
          const __half* __restrict__ Bh, __half* __restrict__ PC)
{
    extern __shared__ char smem[];
    const uint32_t sb = smem_u32(smem);
    const int tid = threadIdx.x;
    const int lane = tid & 31;
    const int wid = tid >> 5;
    const int wm = wid & 3;
    const int wn = wid >> 2;
    const int m0 = blockIdx.x * BM;
    const int z = blockIdx.z;
    const __half* AL = nullptr;
    const __half* Bz = Bh + (size_t)z * 65536;

    GEMM_MAINLOOP(false)

    __half* Pz = PC + (size_t)z * N_MAX * H;
#pragma unroll
    for (int mi = 0; mi < 2; mi++) {
#pragma unroll
        for (int half = 0; half < 2; half++) {
            int row = m0 + wm * 32 + mi * 16 + half * 8 + (lane >> 2);
            if (row >= M) continue;
#pragma unroll
            for (int nj = 0; nj < 16; nj++) {
                int col = wn * 128 + nj * 8 + (lane & 3) * 2;
                __half2 hp(__float2half(acc[mi][nj][half * 2 + 0]),
                           __float2half(acc[mi][nj][half * 2 + 1]));
                *(__half2*)(Pz + (size_t)row * 256 + col) = hp;
            }
        }
    }
}

// ---------------- edge + eps GEMM (1-term, scalar epilogues) -------------------
__global__ void __launch_bounds__(NTH, 1)
edge_eps_gemm(const __half* __restrict__ Aedge, int E,
              const __half* __restrict__ Anode, int Nn,
              const __half* __restrict__ WhL,
              const float* __restrict__ a_b1, const float* __restrict__ a_w2,
              const float* __restrict__ a_b2, float* __restrict__ ae,
              const __half* __restrict__ P1, const __half* __restrict__ P2,
              const int* __restrict__ src, const int* __restrict__ dst,
              const float* __restrict__ eps_b1, const float* __restrict__ eps_w2,
              const float* __restrict__ eps_b2, float* __restrict__ epsv)
{
    extern __shared__ char smem[];
    const uint32_t sb = smem_u32(smem);
    const int tid = threadIdx.x;
    const int lane = tid & 31;
    const int wid = tid >> 5;
    const int wm = wid & 3;
    const int wn = wid >> 2;
    const int m0 = blockIdx.x * BM;
    const int z = blockIdx.z;
    const int K = H;

    const __half* A = (z == 0) ? Aedge : Anode;
    const __half* AL = nullptr;
    const int M = (z == 0) ? E : Nn;
    if (m0 >= M) return;
    const __half* Bz = WhL + (size_t)((z == 0) ? 768 : 512) * 256;

    GEMM_MAINLOOP(false)

    if (z == 0) {
        GEMM_EPI_SCALAR(P1, P2, a_b1, a_w2, a_b2, ae)
    } else {
        GEMM_EPI_SCALAR((const __half*)nullptr, (const __half*)nullptr,
                        eps_b1, eps_w2, eps_b2, epsv)
    }
}

// ---------------- fused message + softmax + update (warp per node) -----------
__global__ void msg_update(const float* __restrict__ ae, const int* __restrict__ src,
                           const __half* __restrict__ ghh,
                           const __half* __restrict__ hh_r,
                           const float* __restrict__ h_old,
                           const float* __restrict__ epsv,
                           float* __restrict__ h_new,
                           __half* __restrict__ hh_w, __half* __restrict__ hl_w,
                           int N)
{
    const int w = (blockIdx.x * blockDim.x + threadIdx.x) >> 5;
    const int lane = threadIdx.x & 31;
    if (w >= N) return;
    const int lo = g_off[w], hi = g_off[w + 1];

    float acc8[8];
#pragma unroll
    for (int q = 0; q < 8; q++) acc8[q] = 0.f;
    float s = 0.f;

    if (hi > lo) {
        float mym = -INFINITY;
        for (int j = lo + lane; j < hi; j += 32)
            mym = fmaxf(mym, ae[g_perm[j]]);
#pragma unroll
        for (int o = 16; o; o >>= 1)
            mym = fmaxf(mym, __shfl_xor_sync(0xffffffffu, mym, o));
        const float m = mym;
        for (int base = lo; base < hi; base += 32) {
            const int j = base + lane;
            int e = 0, sr = 0;
            float c = 0.f;
            if (j < hi) {
                e = g_perm[j];
                c = __expf(ae[e] - m);
                sr = src[e];
            }
            s += c;
            const int cnt = min(32, hi - base);
            for (int i = 0; i < cnt; i++) {
                const float ci = __shfl_sync(0xffffffffu, c, i);
                const int ei = __shfl_sync(0xffffffffu, e, i);
                const int si = __shfl_sync(0xffffffffu, sr, i);
                const uint4 gv = *(const uint4*)(ghh + (size_t)ei * H + lane * 8);
                const uint4 hv16 = *(const uint4*)(hh_r + (size_t)si * H + lane * 8);
                float2 g0 = __half22float2(*(const __half2*)&gv.x);
                float2 g1 = __half22float2(*(const __half2*)&gv.y);
                float2 g2 = __half22float2(*(const __half2*)&gv.z);
                float2 g3 = __half22float2(*(const __half2*)&gv.w);
                float2 q0 = __half22float2(*(const __half2*)&hv16.x);
                float2 q1 = __half22float2(*(const __half2*)&hv16.y);
                float2 q2 = __half22float2(*(const __half2*)&hv16.z);
                float2 q3 = __half22float2(*(const __half2*)&hv16.w);
                acc8[0] = fmaf(ci * g0.x, q0.x, acc8[0]);
                acc8[1] = fmaf(ci * g0.y, q0.y, acc8[1]);
                acc8[2] = fmaf(ci * g1.x, q1.x, acc8[2]);
                acc8[3] = fmaf(ci * g1.y, q1.y, acc8[3]);
                acc8[4] = fmaf(ci * g2.x, q2.x, acc8[4]);
                acc8[5] = fmaf(ci * g2.y, q2.y, acc8[5]);
                acc8[6] = fmaf(ci * g3.x, q3.x, acc8[6]);
                acc8[7] = fmaf(ci * g3.y, q3.y, acc8[7]);
            }
        }
#pragma unroll
        for (int o = 16; o; o >>= 1)
            s += __shfl_xor_sync(0xffffffffu, s, o);
    }

    const float inv = (s > 0.f) ? (1.f / s) : 0.f;
    const float scale = (1.f + epsv[w]) * inv;

    const float4* hrow = (const float4*)(h_old + (size_t)w * H + lane * 8);
    float4 o0 = hrow[0], o1 = hrow[1];
    float4 r0, r1;
    r0.x = fmaf(acc8[0], scale, o0.x); r0.y = fmaf(acc8[1], scale, o0.y);
    r0.z = fmaf(acc8[2], scale, o0.z); r0.w = fmaf(acc8[3], scale, o0.w);
    r1.x = fmaf(acc8[4], scale, o1.x); r1.y = fmaf(acc8[5], scale, o1.y);
    r1.z = fmaf(acc8[6], scale, o1.z); r1.w = fmaf(acc8[7], scale, o1.w);
    float4* orow = (float4*)(h_new + (size_t)w * H + lane * 8);
    orow[0] = r0;
    orow[1] = r1;

    __half2 hp[4], lp[4];
    float vv[8] = {r0.x, r0.y, r0.z, r0.w, r1.x, r1.y, r1.z, r1.w};
#pragma unroll
    for (int q = 0; q < 4; q++) {
        __half b0 = __float2half(vv[q * 2]);
        __half b1 = __float2half(vv[q * 2 + 1]);
        hp[q] = __half2(b0, b1);
        lp[q] = __half2(__float2half(vv[q * 2] - __half2float(b0)),
                        __float2half(vv[q * 2 + 1] - __half2float(b1)));
    }
    *(uint4*)(hh_w + (size_t)w * H + lane * 8) = *(uint4*)hp;
    *(uint4*)(hl_w + (size_t)w * H + lane * 8) = *(uint4*)lp;
}

// ---------------- launch -------------------------------------------------------
extern "C" void kernel_launch(void* const* d_in, const int* in_sizes, int n_in,
                              void* d_out, int out_size)
{
    (void)n_in; (void)out_size;
    const float* node_feats = (const float*)d_in[0];
    const float* gh         = (const float*)d_in[1];
    const int*   src        = (const int*)d_in[2];
    const int*   dst        = (const int*)d_in[3];
    const float* Wn_w       = (const float*)d_in[4];
    const float* Wn_b       = (const float*)d_in[5];
    const float* eps_w1     = (const float*)d_in[6];
    const float* eps_b1     = (const float*)d_in[7];
    const float* eps_w2     = (const float*)d_in[8];
    const float* eps_b2     = (const float*)d_in[9];
    const float* a_w1       = (const float*)d_in[10];
    const float* a_b1       = (const float*)d_in[11];
    const float* a_w2       = (const float*)d_in[12];
    const float* a_b2       = (const float*)d_in[13];

    const int D_IN = 128;
    const int N = in_sizes[0] / D_IN;
    const int E = in_sizes[2];
    const int L = in_sizes[6] / (H * H);

    float* out = (float*)d_out;

    __half *ghh, *nfh, *nfl, *hh0, *hl0, *Wh, *wnh, *gP;
    float *epsv, *ae;
    cudaGetSymbolAddress((void**)&ghh, g_ghh);
    cudaGetSymbolAddress((void**)&nfh, g_nfh);
    cudaGetSymbolAddress((void**)&nfl, g_nfl);
    cudaGetSymbolAddress((void**)&hh0, g_hh);
    cudaGetSymbolAddress((void**)&hl0, g_hl);
    cudaGetSymbolAddress((void**)&Wh,  g_Wh);
    cudaGetSymbolAddress((void**)&wnh, g_wnh);
    cudaGetSymbolAddress((void**)&gP,   g_P);
    cudaGetSymbolAddress((void**)&epsv, g_eps);
    cudaGetSymbolAddress((void**)&ae,   g_ae);

    constexpr int SMEM2 = NSTAGE * (16384 + 16384);   // 2-term (proj) = 160KB
    constexpr int SMEM1 = NSTAGE * (8192 + 16384);    // 1-term = 120KB
    cudaFuncSetAttribute(proj_gemm, cudaFuncAttributeMaxDynamicSharedMemorySize, SMEM2);
    cudaFuncSetAttribute(node_gemm, cudaFuncAttributeMaxDynamicSharedMemorySize, SMEM1);
    cudaFuncSetAttribute(edge_eps_gemm, cudaFuncAttributeMaxDynamicSharedMemorySize, SMEM1);

    // one-time prep (csr clear/hist fused into cvt launches)
    {
        int n4 = (E * H) / 4;
        cvt_gh_clear<<<(n4 + 255) / 256, 256>>>(gh, ghh, n4, N);
        n4 = (N * D_IN) / 4;
        int thr = (n4 > E) ? n4 : E;
        cvt_nf_hist<<<(thr + 255) / 256, 256>>>(node_feats, nfh, nfl, n4, dst, E);
        int totw = L * 1024 * 256 + 128 * 256;
        prep_w<<<(totw + 255) / 256, 256>>>(a_w1, eps_w1, Wn_w, L);
        csr_scan<<<1, 256>>>(N, E);
        csr_scatter<<<(E + 255) / 256, 256>>>(dst, E);
    }

    const int nblkN = (N + BM - 1) / BM;
    const int nblkE = (E + BM - 1) / BM;
    const size_t hbuf = (size_t)N_MAX * H;

    // input projection -> out[0:N*H] fp32 (+ fp16 split into buffer 0)
    proj_gemm<<<dim3(nblkN, 1, 1), NTH, SMEM2>>>(
        nfh, nfl, N, D_IN, wnh, Wn_b, out, hh0, hl0);

    for (int l = 0; l < L; l++) {
        const float* hcur = out + (size_t)l * N * H;
        float*       hnext = out + (size_t)(l + 1) * N * H;
        const __half* WhL = Wh + (size_t)l * 1024 * 256;
        __half* hhr = hh0 + (size_t)(l & 1) * hbuf;
        __half* hhw = hh0 + (size_t)((l + 1) & 1) * hbuf;
        __half* hlw = hl0 + (size_t)((l + 1) & 1) * hbuf;

        // P1/P2 (1-term, fp16 out)
        node_gemm<<<dim3(nblkN, 1, 2), NTH, SMEM1>>>(hhr, N, H, WhL, gP);

        // edge scores + eps in one launch
        edge_eps_gemm<<<dim3(nblkE, 1, 2), NTH, SMEM1>>>(
            ghh, E, hhr, N, WhL,
            a_b1 + (size_t)l * H, a_w2 + (size_t)l * H, a_b2 + l, ae,
            gP, gP + hbuf, src, dst,
            eps_b1 + (size_t)l * H, eps_w2 + (size_t)l * H, eps_b2 + l, epsv);

        // fused message + softmax + GIN update (+ fp16 split of h_next)
        msg_update<<<(N * 32 + 255) / 256, 256>>>(
            ae, src, ghh, hhr, hcur, epsv, hnext, hhw, hlw, N);
    }
}

// round 11
// speedup vs baseline: 3.7065x; 1.0017x over previous
#include <cuda_runtime.h>
#include <cuda_fp16.h>
#include <math.h>
#include <stdint.h>

#define H 256
#define N_MAX 10240
#define E_MAX 163840
#define L_MAX 3

#define BM 128
#define BN 256
#define BK 32
#define NTH 256
#define NSTAGE 5

// ---------------- scratch (device globals) ---------------------------------
__device__ __half g_ghh[E_MAX * H];            // gh fp16
__device__ __half g_nfh[N_MAX * 128];
__device__ __half g_nfl[N_MAX * 128];
__device__ __half g_hh[2][N_MAX * H];          // double-buffered per layer
__device__ __half g_hl[2][N_MAX * H];
// combined per-layer weights: rows 0-255 P1W, 256-511 P2W, 512-767 epsW,
// 768-1023 edgeW (each [256k,256n] row-major)
__device__ __half g_Wh[L_MAX * 1024 * 256];
__device__ __half g_wnh[128 * 256];
__device__ __half g_P[2 * N_MAX * H];          // P1,P2 in fp16
__device__ float g_eps[N_MAX];
__device__ float g_ae[E_MAX];
// CSR by dst
__device__ int g_cnt[N_MAX];
__device__ int g_off[N_MAX + 1];
__device__ int g_cur[N_MAX];
__device__ int g_perm[E_MAX];

// ---------------- helpers ----------------------------------------------------
__device__ __forceinline__ uint32_t smem_u32(const void* p) {
    uint32_t a;
    asm("{ .reg .u64 t; cvta.to.shared.u64 t, %1; cvt.u32.u64 %0, t; }" : "=r"(a) : "l"(p));
    return a;
}
__device__ __forceinline__ void cp16(uint32_t dst, const void* src) {
    asm volatile("cp.async.cg.shared.global [%0], [%1], 16;" :: "r"(dst), "l"(src));
}
__device__ __forceinline__ void ldsm4(uint32_t* r, uint32_t addr) {
    asm volatile("ldmatrix.sync.aligned.m8n8.x4.shared.b16 {%0,%1,%2,%3}, [%4];"
                 : "=r"(r[0]), "=r"(r[1]), "=r"(r[2]), "=r"(r[3]) : "r"(addr));
}
__device__ __forceinline__ void ldsm4t(uint32_t* r, uint32_t addr) {
    asm volatile("ldmatrix.sync.aligned.m8n8.x4.trans.shared.b16 {%0,%1,%2,%3}, [%4];"
                 : "=r"(r[0]), "=r"(r[1]), "=r"(r[2]), "=r"(r[3]) : "r"(addr));
}
__device__ __forceinline__ void mma16816(float* c, const uint32_t* a, const uint32_t* b) {
    asm volatile("mma.sync.aligned.m16n8k16.row.col.f32.f16.f16.f32 "
                 "{%0,%1,%2,%3}, {%4,%5,%6,%7}, {%8,%9}, {%0,%1,%2,%3};"
                 : "+f"(c[0]), "+f"(c[1]), "+f"(c[2]), "+f"(c[3])
                 : "r"(a[0]), "r"(a[1]), "r"(a[2]), "r"(a[3]), "r"(b[0]), "r"(b[1]));
}

// ---------------- gh cvt (fp16 hi) + csr_clear fused --------------------------
__global__ void cvt_gh_clear(const float* __restrict__ x, __half* __restrict__ hi,
                             int n4, int Nclr)
{
    int i = blockIdx.x * blockDim.x + threadIdx.x;
    if (i < Nclr) g_cnt[i] = 0;
    if (i >= n4) return;
    float4 v = ((const float4*)x)[i];
    __half2 hh0(__float2half(v.x), __float2half(v.y));
    __half2 hh1(__float2half(v.z), __float2half(v.w));
    ((__half2*)hi)[i * 2 + 0] = hh0;
    ((__half2*)hi)[i * 2 + 1] = hh1;
}

// ---------------- nf cvt (fp16 hi/lo) + csr_hist fused ------------------------
__global__ void cvt_nf_hist(const float* __restrict__ x, __half* __restrict__ hi,
                            __half* __restrict__ lo, int n4,
                            const int* __restrict__ dst, int E)
{
    int i = blockIdx.x * blockDim.x + threadIdx.x;
    if (i < E) atomicAdd(&g_cnt[dst[i]], 1);
    if (i >= n4) return;
    float4 v = ((const float4*)x)[i];
    __half h0 = __float2half(v.x), h1 = __float2half(v.y);
    __half h2 = __float2half(v.z), h3 = __float2half(v.w);
    ((__half2*)hi)[i * 2 + 0] = __half2(h0, h1);
    ((__half2*)hi)[i * 2 + 1] = __half2(h2, h3);
    ((__half2*)lo)[i * 2 + 0] = __half2(__float2half(v.x - __half2float(h0)),
                                        __float2half(v.y - __half2float(h1)));
    ((__half2*)lo)[i * 2 + 1] = __half2(__float2half(v.z - __half2float(h2)),
                                        __float2half(v.w - __half2float(h3)));
}

// ---------------- weight prep (hi only) --------------------------------------
__global__ void prep_w(const float* __restrict__ a_w1, const float* __restrict__ eps_w1,
                       const float* __restrict__ Wn_w, int L)
{
    const int totW = L * 1024 * 256;
    const int total = totW + 128 * 256;
    int idx = blockIdx.x * blockDim.x + threadIdx.x;
    if (idx >= total) return;
    float v;
    __half* dh;
    int di;
    if (idx < totW) {
        int l = idx / (1024 * 256);
        int r = (idx / 256) % 1024;
        int n = idx % 256;
        if (r < 512)      v = a_w1[((size_t)l * 768 + r) * 256 + n];
        else if (r < 768) v = eps_w1[((size_t)l * 256 + (r - 512)) * 256 + n];
        else              v = a_w1[((size_t)l * 768 + 512 + (r - 768)) * 256 + n];
        dh = g_Wh; di = idx;
    } else {
        int i2 = idx - totW;
        v = Wn_w[i2];
        dh = g_wnh; di = i2;
    }
    dh[di] = __float2half(v);
}

// ---------------- CSR scan (1024 threads, block scan) -------------------------
__global__ void csr_scan(int N, int E) {
    __shared__ int sums[1024];
    const int tid = threadIdx.x;
    const int chunk = (N + 1023) / 1024;
    const int base = tid * chunk;
    int s = 0;
#pragma unroll 4
    for (int i = 0; i < chunk; i++) {
        int idx = base + i;
        if (idx < N) s += g_cnt[idx];
    }
    sums[tid] = s;
    __syncthreads();
    for (int d = 1; d < 1024; d <<= 1) {
        int v = (tid >= d) ? sums[tid - d] : 0;
        __syncthreads();
        sums[tid] += v;
        __syncthreads();
    }
    int run = sums[tid] - s;
    for (int i = 0; i < chunk; i++) {
        int idx = base + i;
        if (idx < N) { g_off[idx] = run; g_cur[idx] = run; run += g_cnt[idx]; }
    }
    if (tid == 1023) g_off[N] = E;
}
__global__ void csr_scatter(const int* __restrict__ dst, int E) {
    int e = blockIdx.x * blockDim.x + threadIdx.x;
    if (e < E) {
        int pos = atomicAdd(&g_cur[dst[e]], 1);
        g_perm[pos] = e;
    }
}

// ============ GEMM body macros ================================================
// 5-stage pipeline, prefetch distance 3, wait_group 2, ONE barrier per iter.
#define GEMM_MAINLOOP(HAS_AL)                                                  \
    constexpr uint32_t AH_OFF = 0;                                             \
    constexpr uint32_t AL_OFF = 8192;                                          \
    constexpr uint32_t BH_OFF = (HAS_AL) ? 16384u : 8192u;                     \
    constexpr uint32_t STB = BH_OFF + 16384u;                                  \
    float acc[2][16][4];                                                       \
    _Pragma("unroll") for (int mi = 0; mi < 2; mi++)                           \
    _Pragma("unroll") for (int nj = 0; nj < 16; nj++)                          \
    _Pragma("unroll") for (int q = 0; q < 4; q++) acc[mi][nj][q] = 0.f;        \
    const int nchunks = K / BK;                                                \
    auto load_stage = [&](int s, int k0) {                                     \
        const uint32_t base = sb + s * STB;                                    \
        _Pragma("unroll") for (int i = 0; i < 2; i++) {                        \
            int cid = tid + i * NTH;                                           \
            int row = cid >> 2;                                                \
            int cb = (cid & 3) * 16;                                           \
            int grow = m0 + row;                                               \
            if (grow >= M) grow = M - 1;                                       \
            size_t gb = ((size_t)grow * K + k0) * 2 + cb;                      \
            uint32_t d = base + row * 64 + (cb ^ ((row & 3) << 4));            \
            cp16(d + AH_OFF, (const char*)A + gb);                             \
            if (HAS_AL) cp16(d + AL_OFF, (const char*)AL + gb);                \
        }                                                                      \
        _Pragma("unroll") for (int i = 0; i < 4; i++) {                        \
            int cid = tid + i * NTH;                                           \
            int k = cid >> 5;                                                  \
            int cb = (cid & 31) * 16;                                          \
            size_t gb = (size_t)(k0 + k) * 512 + cb;                           \
            uint32_t d = base + k * 512 + (cb ^ ((k & 7) << 4));               \
            cp16(d + BH_OFF, (const char*)Bz + gb);                            \
        }                                                                      \
        asm volatile("cp.async.commit_group;" ::: "memory");                   \
    };                                                                         \
    auto compute_stage = [&](int s) {                                          \
        const uint32_t base = sb + s * STB;                                    \
        _Pragma("unroll") for (int kk = 0; kk < 2; kk++) {                     \
            uint32_t ah[2][4], al[2][4];                                       \
            _Pragma("unroll") for (int mi = 0; mi < 2; mi++) {                 \
                int row = wm * 32 + mi * 16 + (lane & 15);                     \
                uint32_t cb = kk * 32 + ((lane >> 4) << 4);                    \
                uint32_t ad = base + row * 64 + (cb ^ ((row & 3) << 4));       \
                ldsm4(ah[mi], ad + AH_OFF);                                    \
                if (HAS_AL) ldsm4(al[mi], ad + AL_OFF);                        \
            }                                                                  \
            const int kr = kk * 16 + (lane & 15);                              \
            const uint32_t hi16 = (lane >> 4) << 4;                            \
            uint32_t bhA[4], bhB[4];                                           \
            {                                                                  \
                uint32_t cb = wn * 256 + hi16;                                 \
                uint32_t bd = base + kr * 512 + (cb ^ ((kr & 7) << 4));        \
                ldsm4t(bhA, bd + BH_OFF);                                      \
            }                                                                  \
            _Pragma("unroll") for (int nj2 = 0; nj2 < 8; nj2++) {              \
                uint32_t* ch = (nj2 & 1) ? bhB : bhA;                          \
                if (nj2 < 7) {                                                 \
                    uint32_t* nh = (nj2 & 1) ? bhA : bhB;                      \
                    uint32_t cb = wn * 256 + (nj2 + 1) * 32 + hi16;            \
                    uint32_t bd = base + kr * 512 + (cb ^ ((kr & 7) << 4));    \
                    ldsm4t(nh, bd + BH_OFF);                                   \
                }                                                              \
                _Pragma("unroll") for (int mi = 0; mi < 2; mi++)               \
                _Pragma("unroll") for (int sub = 0; sub < 2; sub++) {          \
                    int nj = nj2 * 2 + sub;                                    \
                    mma16816(acc[mi][nj], ah[mi], &ch[sub * 2]);               \
                    if (HAS_AL) mma16816(acc[mi][nj], al[mi], &ch[sub * 2]);   \
                }                                                              \
            }                                                                  \
        }                                                                      \
    };                                                                         \
    for (int p = 0; p < 3 && p < nchunks; p++) load_stage(p, p * BK);          \
    {                                                                          \
        int cs = 0, ls = 3;                                                    \
        for (int c = 0; c < nchunks; c++) {                                    \
            if (c + 3 < nchunks) load_stage(ls, (c + 3) * BK);                 \
            else asm volatile("cp.async.commit_group;" ::: "memory");          \
            asm volatile("cp.async.wait_group 2;" ::: "memory");               \
            __syncthreads();                                                   \
            compute_stage(cs);                                                 \
            if (++cs == NSTAGE) cs = 0;                                        \
            if (++ls == NSTAGE) ls = 0;                                        \
        }                                                                      \
    }

// scalar epilogue: sout[row] = sum relu(acc + sbias + P1[src]+P2[dst]) . w2 + b2
#define GEMM_EPI_SCALAR(P1, P2, SBIAS, W2, B2, SOUT)                           \
    {                                                                          \
        float* sred = (float*)smem;                                            \
        _Pragma("unroll") for (int mi = 0; mi < 2; mi++)                       \
        _Pragma("unroll") for (int half = 0; half < 2; half++) {               \
            int rowl = wm * 32 + mi * 16 + half * 8 + (lane >> 2);             \
            int row = m0 + rowl;                                               \
            int cl = (row < M) ? row : (M - 1);                                \
            const __half* p1 = (P1) ? ((P1) + (size_t)src[cl] * 256) : nullptr;\
            const __half* p2 = (P2) ? ((P2) + (size_t)dst[cl] * 256) : nullptr;\
            float part = 0.f;                                                  \
            _Pragma("unroll") for (int nj = 0; nj < 16; nj++) {                \
                int col = wn * 128 + nj * 8 + (lane & 3) * 2;                  \
                float2 bv = *(const float2*)((SBIAS) + col);                   \
                float2 wv = *(const float2*)((W2) + col);                      \
                float2 p1v = make_float2(0.f, 0.f), p2v = make_float2(0.f, 0.f);\
                if (p1) p1v = __half22float2(*(const __half2*)(p1 + col));     \
                if (p2) p2v = __half22float2(*(const __half2*)(p2 + col));     \
                float v0 = fmaxf(acc[mi][nj][half * 2 + 0] + bv.x + p1v.x + p2v.x, 0.f);\
                float v1 = fmaxf(acc[mi][nj][half * 2 + 1] + bv.y + p1v.y + p2v.y, 0.f);\
                part = fmaf(v0, wv.x, part);                                   \
                part = fmaf(v1, wv.y, part);                                   \
            }                                                                  \
            part += __shfl_xor_sync(0xffffffffu, part, 1);                     \
            part += __shfl_xor_sync(0xffffffffu, part, 2);                     \
            if ((lane & 3) == 0) sred[rowl * 2 + wn] = part;                   \
        }                                                                      \
        __syncthreads();                                                       \
        if (tid < 128) {                                                       \
            int row = m0 + tid;                                                \
            if (row < M) (SOUT)[row] = sred[tid * 2] + sred[tid * 2 + 1] + (B2)[0];\
        }                                                                      \
    }

// ---------------- input projection GEMM (2-term exact-A) ----------------------
__global__ void __launch_bounds__(NTH, 1)
proj_gemm(const __half* __restrict__ A, const __half* __restrict__ AL,
          int M, int K, const __half* __restrict__ Bz,
          const float* __restrict__ bias, float* __restrict__ C,
          __half* __restrict__ ohh, __half* __restrict__ ohl)
{
    extern __shared__ char smem[];
    const uint32_t sb = smem_u32(smem);
    const int tid = threadIdx.x;
    const int lane = tid & 31;
    const int wid = tid >> 5;
    const int wm = wid & 3;
    const int wn = wid >> 2;
    const int m0 = blockIdx.x * BM;

    GEMM_MAINLOOP(true)

#pragma unroll
    for (int mi = 0; mi < 2; mi++) {
#pragma unroll
        for (int half = 0; half < 2; half++) {
            int row = m0 + wm * 32 + mi * 16 + half * 8 + (lane >> 2);
            if (row >= M) continue;
#pragma unroll
            for (int nj = 0; nj < 16; nj++) {
                int col = wn * 128 + nj * 8 + (lane & 3) * 2;
                float2 v;
                v.x = acc[mi][nj][half * 2 + 0] + bias[col];
                v.y = acc[mi][nj][half * 2 + 1] + bias[col + 1];
                *(float2*)(C + (size_t)row * 256 + col) = v;
                __half b0 = __float2half(v.x);
                __half b1 = __float2half(v.y);
                *(__half2*)(ohh + (size_t)row * 256 + col) = __half2(b0, b1);
                *(__half2*)(ohl + (size_t)row * 256 + col) =
                    __half2(__float2half(v.x - __half2float(b0)),
                            __float2half(v.y - __half2float(b1)));
            }
        }
    }
}

// ---------------- node GEMM: P1/P2 (1-term, fp16 out) --------------------------
__global__ void __launch_bounds__(NTH, 1)
node_gemm(const __half* __restrict__ A, int M, int K,
          const __half* __restrict__ Bh, __half* __restrict__ PC)
{
    extern __shared__ char smem[];
    const uint32_t sb = smem_u32(smem);
    const int tid = threadIdx.x;
    const int lane = tid & 31;
    const int wid = tid >> 5;
    const int wm = wid & 3;
    const int wn = wid >> 2;
    const int m0 = blockIdx.x * BM;
    const int z = blockIdx.z;
    const __half* AL = nullptr;
    const __half* Bz = Bh + (size_t)z * 65536;

    GEMM_MAINLOOP(false)

    __half* Pz = PC + (size_t)z * N_MAX * H;
#pragma unroll
    for (int mi = 0; mi < 2; mi++) {
#pragma unroll
        for (int half = 0; half < 2; half++) {
            int row = m0 + wm * 32 + mi * 16 + half * 8 + (lane >> 2);
            if (row >= M) continue;
#pragma unroll
            for (int nj = 0; nj < 16; nj++) {
                int col = wn * 128 + nj * 8 + (lane & 3) * 2;
                __half2 hp(__float2half(acc[mi][nj][half * 2 + 0]),
                           __float2half(acc[mi][nj][half * 2 + 1]));
                *(__half2*)(Pz + (size_t)row * 256 + col) = hp;
            }
        }
    }
}

// ---------------- edge + eps GEMM (1-term, flat 1D grid) -----------------------
// bid < nblkE : edge scores (M=E, A=ghh, B=+768*256, P1/P2 gather) -> ae
// bid >= nblkE: eps (M=N, A=hh, B=+512*256) -> epsv
__global__ void __launch_bounds__(NTH, 1)
edge_eps_gemm(const __half* __restrict__ Aedge, int E,
              const __half* __restrict__ Anode, int Nn, int nblkE,
              const __half* __restrict__ WhL,
              const float* __restrict__ a_b1, const float* __restrict__ a_w2,
              const float* __restrict__ a_b2, float* __restrict__ ae,
              const __half* __restrict__ P1, const __half* __restrict__ P2,
              const int* __restrict__ src, const int* __restrict__ dst,
              const float* __restrict__ eps_b1, const float* __restrict__ eps_w2,
              const float* __restrict__ eps_b2, float* __restrict__ epsv)
{
    extern __shared__ char smem[];
    const uint32_t sb = smem_u32(smem);
    const int tid = threadIdx.x;
    const int lane = tid & 31;
    const int wid = tid >> 5;
    const int wm = wid & 3;
    const int wn = wid >> 2;
    const int bid = blockIdx.x;
    const int is_edge = (bid < nblkE);
    const int m0 = (is_edge ? bid : (bid - nblkE)) * BM;
    const int K = H;

    const __half* A = is_edge ? Aedge : Anode;
    const __half* AL = nullptr;
    const int M = is_edge ? E : Nn;
    const __half* Bz = WhL + (size_t)(is_edge ? 768 : 512) * 256;

    GEMM_MAINLOOP(false)

    if (is_edge) {
        GEMM_EPI_SCALAR(P1, P2, a_b1, a_w2, a_b2, ae)
    } else {
        GEMM_EPI_SCALAR((const __half*)nullptr, (const __half*)nullptr,
                        eps_b1, eps_w2, eps_b2, epsv)
    }
}

// ---------------- fused message + softmax + update (warp per node) -----------
__global__ void msg_update(const float* __restrict__ ae, const int* __restrict__ src,
                           const __half* __restrict__ ghh,
                           const __half* __restrict__ hh_r,
                           const float* __restrict__ h_old,
                           const float* __restrict__ epsv,
                           float* __restrict__ h_new,
                           __half* __restrict__ hh_w, __half* __restrict__ hl_w,
                           int N)
{
    const int w = (blockIdx.x * blockDim.x + threadIdx.x) >> 5;
    const int lane = threadIdx.x & 31;
    if (w >= N) return;
    const int lo = g_off[w], hi = g_off[w + 1];

    float acc8[8];
#pragma unroll
    for (int q = 0; q < 8; q++) acc8[q] = 0.f;
    float s = 0.f;

    if (hi > lo) {
        float mym = -INFINITY;
        for (int j = lo + lane; j < hi; j += 32)
            mym = fmaxf(mym, ae[g_perm[j]]);
#pragma unroll
        for (int o = 16; o; o >>= 1)
            mym = fmaxf(mym, __shfl_xor_sync(0xffffffffu, mym, o));
        const float m = mym;
        for (int base = lo; base < hi; base += 32) {
            const int j = base + lane;
            int e = 0, sr = 0;
            float c = 0.f;
            if (j < hi) {
                e = g_perm[j];
                c = __expf(ae[e] - m);
                sr = src[e];
            }
            s += c;
            const int cnt = min(32, hi - base);
            for (int i = 0; i < cnt; i++) {
                const float ci = __shfl_sync(0xffffffffu, c, i);
                const int ei = __shfl_sync(0xffffffffu, e, i);
                const int si = __shfl_sync(0xffffffffu, sr, i);
                const uint4 gv = *(const uint4*)(ghh + (size_t)ei * H + lane * 8);
                const uint4 hv16 = *(const uint4*)(hh_r + (size_t)si * H + lane * 8);
                float2 g0 = __half22float2(*(const __half2*)&gv.x);
                float2 g1 = __half22float2(*(const __half2*)&gv.y);
                float2 g2 = __half22float2(*(const __half2*)&gv.z);
                float2 g3 = __half22float2(*(const __half2*)&gv.w);
                float2 q0 = __half22float2(*(const __half2*)&hv16.x);
                float2 q1 = __half22float2(*(const __half2*)&hv16.y);
                float2 q2 = __half22float2(*(const __half2*)&hv16.z);
                float2 q3 = __half22float2(*(const __half2*)&hv16.w);
                acc8[0] = fmaf(ci * g0.x, q0.x, acc8[0]);
                acc8[1] = fmaf(ci * g0.y, q0.y, acc8[1]);
                acc8[2] = fmaf(ci * g1.x, q1.x, acc8[2]);
                acc8[3] = fmaf(ci * g1.y, q1.y, acc8[3]);
                acc8[4] = fmaf(ci * g2.x, q2.x, acc8[4]);
                acc8[5] = fmaf(ci * g2.y, q2.y, acc8[5]);
                acc8[6] = fmaf(ci * g3.x, q3.x, acc8[6]);
                acc8[7] = fmaf(ci * g3.y, q3.y, acc8[7]);
            }
        }
#pragma unroll
        for (int o = 16; o; o >>= 1)
            s += __shfl_xor_sync(0xffffffffu, s, o);
    }

    const float inv = (s > 0.f) ? (1.f / s) : 0.f;
    const float scale = (1.f + epsv[w]) * inv;

    const float4* hrow = (const float4*)(h_old + (size_t)w * H + lane * 8);
    float4 o0 = hrow[0], o1 = hrow[1];
    float4 r0, r1;
    r0.x = fmaf(acc8[0], scale, o0.x); r0.y = fmaf(acc8[1], scale, o0.y);
    r0.z = fmaf(acc8[2], scale, o0.z); r0.w = fmaf(acc8[3], scale, o0.w);
    r1.x = fmaf(acc8[4], scale, o1.x); r1.y = fmaf(acc8[5], scale, o1.y);
    r1.z = fmaf(acc8[6], scale, o1.z); r1.w = fmaf(acc8[7], scale, o1.w);
    float4* orow = (float4*)(h_new + (size_t)w * H + lane * 8);
    orow[0] = r0;
    orow[1] = r1;

    __half2 hp[4], lp[4];
    float vv[8] = {r0.x, r0.y, r0.z, r0.w, r1.x, r1.y, r1.z, r1.w};
#pragma unroll
    for (int q = 0; q < 4; q++) {
        __half b0 = __float2half(vv[q * 2]);
        __half b1 = __float2half(vv[q * 2 + 1]);
        hp[q] = __half2(b0, b1);
        lp[q] = __half2(__float2half(vv[q * 2] - __half2float(b0)),
                        __float2half(vv[q * 2 + 1] - __half2float(b1)));
    }
    *(uint4*)(hh_w + (size_t)w * H + lane * 8) = *(uint4*)hp;
    *(uint4*)(hl_w + (size_t)w * H + lane * 8) = *(uint4*)lp;
}

// ---------------- launch -------------------------------------------------------
extern "C" void kernel_launch(void* const* d_in, const int* in_sizes, int n_in,
                              void* d_out, int out_size)
{
    (void)n_in; (void)out_size;
    const float* node_feats = (const float*)d_in[0];
    const float* gh         = (const float*)d_in[1];
    const int*   src        = (const int*)d_in[2];
    const int*   dst        = (const int*)d_in[3];
    const float* Wn_w       = (const float*)d_in[4];
    const float* Wn_b       = (const float*)d_in[5];
    const float* eps_w1     = (const float*)d_in[6];
    const float* eps_b1     = (const float*)d_in[7];
    const float* eps_w2     = (const float*)d_in[8];
    const float* eps_b2     = (const float*)d_in[9];
    const float* a_w1       = (const float*)d_in[10];
    const float* a_b1       = (const float*)d_in[11];
    const float* a_w2       = (const float*)d_in[12];
    const float* a_b2       = (const float*)d_in[13];

    const int D_IN = 128;
    const int N = in_sizes[0] / D_IN;
    const int E = in_sizes[2];
    const int L = in_sizes[6] / (H * H);

    float* out = (float*)d_out;

    __half *ghh, *nfh, *nfl, *hh0, *hl0, *Wh, *wnh, *gP;
    float *epsv, *ae;
    cudaGetSymbolAddress((void**)&ghh, g_ghh);
    cudaGetSymbolAddress((void**)&nfh, g_nfh);
    cudaGetSymbolAddress((void**)&nfl, g_nfl);
    cudaGetSymbolAddress((void**)&hh0, g_hh);
    cudaGetSymbolAddress((void**)&hl0, g_hl);
    cudaGetSymbolAddress((void**)&Wh,  g_Wh);
    cudaGetSymbolAddress((void**)&wnh, g_wnh);
    cudaGetSymbolAddress((void**)&gP,   g_P);
    cudaGetSymbolAddress((void**)&epsv, g_eps);
    cudaGetSymbolAddress((void**)&ae,   g_ae);

    constexpr int SMEM2 = NSTAGE * (16384 + 16384);   // 2-term (proj) = 160KB
    constexpr int SMEM1 = NSTAGE * (8192 + 16384);    // 1-term = 120KB
    cudaFuncSetAttribute(proj_gemm, cudaFuncAttributeMaxDynamicSharedMemorySize, SMEM2);
    cudaFuncSetAttribute(node_gemm, cudaFuncAttributeMaxDynamicSharedMemorySize, SMEM1);
    cudaFuncSetAttribute(edge_eps_gemm, cudaFuncAttributeMaxDynamicSharedMemorySize, SMEM1);

    // one-time prep (csr clear/hist fused into cvt launches)
    {
        int n4 = (E * H) / 4;
        cvt_gh_clear<<<(n4 + 255) / 256, 256>>>(gh, ghh, n4, N);
        n4 = (N * D_IN) / 4;
        int thr = (n4 > E) ? n4 : E;
        cvt_nf_hist<<<(thr + 255) / 256, 256>>>(node_feats, nfh, nfl, n4, dst, E);
        int totw = L * 1024 * 256 + 128 * 256;
        prep_w<<<(totw + 255) / 256, 256>>>(a_w1, eps_w1, Wn_w, L);
        csr_scan<<<1, 1024>>>(N, E);
        csr_scatter<<<(E + 255) / 256, 256>>>(dst, E);
    }

    const int nblkN = (N + BM - 1) / BM;
    const int nblkE = (E + BM - 1) / BM;
    const size_t hbuf = (size_t)N_MAX * H;

    // input projection -> out[0:N*H] fp32 (+ fp16 split into buffer 0)
    proj_gemm<<<dim3(nblkN, 1, 1), NTH, SMEM2>>>(
        nfh, nfl, N, D_IN, wnh, Wn_b, out, hh0, hl0);

    for (int l = 0; l < L; l++) {
        const float* hcur = out + (size_t)l * N * H;
        float*       hnext = out + (size_t)(l + 1) * N * H;
        const __half* WhL = Wh + (size_t)l * 1024 * 256;
        __half* hhr = hh0 + (size_t)(l & 1) * hbuf;
        __half* hhw = hh0 + (size_t)((l + 1) & 1) * hbuf;
        __half* hlw = hl0 + (size_t)((l + 1) & 1) * hbuf;

        // P1/P2 (1-term, fp16 out)
        node_gemm<<<dim3(nblkN, 1, 2), NTH, SMEM1>>>(hhr, N, H, WhL, gP);

        // edge scores + eps in one flat launch (no empty CTAs)
        edge_eps_gemm<<<dim3(nblkE + nblkN, 1, 1), NTH, SMEM1>>>(
            ghh, E, hhr, N, nblkE, WhL,
            a_b1 + (size_t)l * H, a_w2 + (size_t)l * H, a_b2 + l, ae,
            gP, gP + hbuf, src, dst,
            eps_b1 + (size_t)l * H, eps_w2 + (size_t)l * H, eps_b2 + l, epsv);

        // fused message + softmax + GIN update (+ fp16 split of h_next)
        msg_update<<<(N * 32 + 255) / 256, 256>>>(
            ae, src, ghh, hhr, hcur, epsv, hnext, hhw, hlw, N);
    }
}

// round 12
// speedup vs baseline: 3.9580x; 1.0679x over previous
#include <cuda_runtime.h>
#include <cuda_fp16.h>
#include <math.h>
#include <stdint.h>

#define H 256
#define N_MAX 10240
#define E_MAX 163840
#define L_MAX 3

#define BM 128
#define BN 256
#define BK 32
#define NTH 256
#define NSTAGE 5

// ---------------- scratch (device globals) ---------------------------------
__device__ __half g_ghh[E_MAX * H];            // gh fp16, PERMUTED by dst-sorted order
__device__ __half g_nfh[N_MAX * 128];
__device__ __half g_nfl[N_MAX * 128];
__device__ __half g_hh[2][N_MAX * H];          // double-buffered per layer
__device__ __half g_hl[2][N_MAX * H];
// combined per-layer weights: rows 0-255 P1W, 256-511 P2W, 512-767 epsW,
// 768-1023 edgeW (each [256k,256n] row-major)
__device__ __half g_Wh[L_MAX * 1024 * 256];
__device__ __half g_wnh[128 * 256];
__device__ __half g_P[2 * N_MAX * H];          // P1,P2 in fp16
__device__ float g_eps[N_MAX];
__device__ float g_ae[E_MAX];                  // edge scores, permuted order
// CSR by dst
__device__ int g_cnt[N_MAX];
__device__ int g_off[N_MAX + 1];
__device__ int g_cur[N_MAX];
__device__ int g_perm[E_MAX];
__device__ int g_srcp[E_MAX];                  // src in permuted order
__device__ int g_dstp[E_MAX];                  // dst in permuted order

// ---------------- helpers ----------------------------------------------------
__device__ __forceinline__ uint32_t smem_u32(const void* p) {
    uint32_t a;
    asm("{ .reg .u64 t; cvta.to.shared.u64 t, %1; cvt.u32.u64 %0, t; }" : "=r"(a) : "l"(p));
    return a;
}
__device__ __forceinline__ void cp16(uint32_t dst, const void* src) {
    asm volatile("cp.async.cg.shared.global [%0], [%1], 16;" :: "r"(dst), "l"(src));
}
__device__ __forceinline__ void ldsm4(uint32_t* r, uint32_t addr) {
    asm volatile("ldmatrix.sync.aligned.m8n8.x4.shared.b16 {%0,%1,%2,%3}, [%4];"
                 : "=r"(r[0]), "=r"(r[1]), "=r"(r[2]), "=r"(r[3]) : "r"(addr));
}
__device__ __forceinline__ void ldsm4t(uint32_t* r, uint32_t addr) {
    asm volatile("ldmatrix.sync.aligned.m8n8.x4.trans.shared.b16 {%0,%1,%2,%3}, [%4];"
                 : "=r"(r[0]), "=r"(r[1]), "=r"(r[2]), "=r"(r[3]) : "r"(addr));
}
__device__ __forceinline__ void mma16816(float* c, const uint32_t* a, const uint32_t* b) {
    asm volatile("mma.sync.aligned.m16n8k16.row.col.f32.f16.f16.f32 "
                 "{%0,%1,%2,%3}, {%4,%5,%6,%7}, {%8,%9}, {%0,%1,%2,%3};"
                 : "+f"(c[0]), "+f"(c[1]), "+f"(c[2]), "+f"(c[3])
                 : "r"(a[0]), "r"(a[1]), "r"(a[2]), "r"(a[3]), "r"(b[0]), "r"(b[1]));
}

// ---------------- weight prep (hi only) + csr clear ---------------------------
__global__ void prep_w(const float* __restrict__ a_w1, const float* __restrict__ eps_w1,
                       const float* __restrict__ Wn_w, int L, int N)
{
    const int totW = L * 1024 * 256;
    const int total = totW + 128 * 256;
    int idx = blockIdx.x * blockDim.x + threadIdx.x;
    if (idx < N) g_cnt[idx] = 0;
    if (idx >= total) return;
    float v;
    __half* dh;
    int di;
    if (idx < totW) {
        int l = idx / (1024 * 256);
        int r = (idx / 256) % 1024;
        int n = idx % 256;
        if (r < 512)      v = a_w1[((size_t)l * 768 + r) * 256 + n];
        else if (r < 768) v = eps_w1[((size_t)l * 256 + (r - 512)) * 256 + n];
        else              v = a_w1[((size_t)l * 768 + 512 + (r - 768)) * 256 + n];
        dh = g_Wh; di = idx;
    } else {
        int i2 = idx - totW;
        v = Wn_w[i2];
        dh = g_wnh; di = i2;
    }
    dh[di] = __float2half(v);
}

// ---------------- nf cvt (fp16 hi/lo) + csr_hist fused ------------------------
__global__ void cvt_nf_hist(const float* __restrict__ x, __half* __restrict__ hi,
                            __half* __restrict__ lo, int n4,
                            const int* __restrict__ dst, int E)
{
    int i = blockIdx.x * blockDim.x + threadIdx.x;
    if (i < E) atomicAdd(&g_cnt[dst[i]], 1);
    if (i >= n4) return;
    float4 v = ((const float4*)x)[i];
    __half h0 = __float2half(v.x), h1 = __float2half(v.y);
    __half h2 = __float2half(v.z), h3 = __float2half(v.w);
    ((__half2*)hi)[i * 2 + 0] = __half2(h0, h1);
    ((__half2*)hi)[i * 2 + 1] = __half2(h2, h3);
    ((__half2*)lo)[i * 2 + 0] = __half2(__float2half(v.x - __half2float(h0)),
                                        __float2half(v.y - __half2float(h1)));
    ((__half2*)lo)[i * 2 + 1] = __half2(__float2half(v.z - __half2float(h2)),
                                        __float2half(v.w - __half2float(h3)));
}

// ---------------- CSR scan (1024 thr, warp-shuffle two-level, 2 barriers) -----
__global__ void csr_scan(int N, int E) {
    __shared__ int wsum[32];
    const int tid = threadIdx.x;
    const int lane = tid & 31;
    const int wrp = tid >> 5;
    const int chunk = (N + 1023) / 1024;
    const int base = tid * chunk;
    int s = 0;
#pragma unroll 4
    for (int i = 0; i < chunk; i++) {
        int idx = base + i;
        if (idx < N) s += g_cnt[idx];
    }
    int sc = s;
#pragma unroll
    for (int o = 1; o < 32; o <<= 1) {
        int v = __shfl_up_sync(0xffffffffu, sc, o);
        if (lane >= o) sc += v;
    }
    if (lane == 31) wsum[wrp] = sc;
    __syncthreads();
    if (wrp == 0) {
        int t = wsum[lane];
#pragma unroll
        for (int o = 1; o < 32; o <<= 1) {
            int v = __shfl_up_sync(0xffffffffu, t, o);
            if (lane >= o) t += v;
        }
        wsum[lane] = t;
    }
    __syncthreads();
    int run = sc - s + (wrp ? wsum[wrp - 1] : 0);
    for (int i = 0; i < chunk; i++) {
        int idx = base + i;
        if (idx < N) { g_off[idx] = run; g_cur[idx] = run; run += g_cnt[idx]; }
    }
    if (tid == 1023) g_off[N] = E;
}

// ---------------- CSR scatter (also records permuted src/dst) -----------------
__global__ void csr_scatter(const int* __restrict__ src, const int* __restrict__ dst,
                            int E)
{
    int e = blockIdx.x * blockDim.x + threadIdx.x;
    if (e < E) {
        int d = dst[e];
        int pos = atomicAdd(&g_cur[d], 1);
        g_perm[pos] = e;
        g_srcp[pos] = src[e];
        g_dstp[pos] = d;
    }
}

// ---------------- gh cvt: gather rows in permuted order -----------------------
__global__ void cvt_gh_perm(const float* __restrict__ gh, __half* __restrict__ hi,
                            int n4)
{
    int i = blockIdx.x * blockDim.x + threadIdx.x;    // float4 index in output
    if (i >= n4) return;
    const int row = i >> 6;             // H/4 = 64 float4 per row
    const int c4 = i & 63;
    const int e = g_perm[row];
    float4 v = ((const float4*)(gh + (size_t)e * H))[c4];
    __half2 hh0(__float2half(v.x), __float2half(v.y));
    __half2 hh1(__float2half(v.z), __float2half(v.w));
    ((__half2*)hi)[i * 2 + 0] = hh0;
    ((__half2*)hi)[i * 2 + 1] = hh1;
}

// ============ GEMM body macros ================================================
#define GEMM_MAINLOOP(HAS_AL)                                                  \
    constexpr uint32_t AH_OFF = 0;                                             \
    constexpr uint32_t AL_OFF = 8192;                                          \
    constexpr uint32_t BH_OFF = (HAS_AL) ? 16384u : 8192u;                     \
    constexpr uint32_t STB = BH_OFF + 16384u;                                  \
    float acc[2][16][4];                                                       \
    _Pragma("unroll") for (int mi = 0; mi < 2; mi++)                           \
    _Pragma("unroll") for (int nj = 0; nj < 16; nj++)                          \
    _Pragma("unroll") for (int q = 0; q < 4; q++) acc[mi][nj][q] = 0.f;        \
    const int nchunks = K / BK;                                                \
    auto load_stage = [&](int s, int k0) {                                     \
        const uint32_t base = sb + s * STB;                                    \
        _Pragma("unroll") for (int i = 0; i < 2; i++) {                        \
            int cid = tid + i * NTH;                                           \
            int row = cid >> 2;                                                \
            int cb = (cid & 3) * 16;                                           \
            int grow = m0 + row;                                               \
            if (grow >= M) grow = M - 1;                                       \
            size_t gb = ((size_t)grow * K + k0) * 2 + cb;                      \
            uint32_t d = base + row * 64 + (cb ^ ((row & 3) << 4));            \
            cp16(d + AH_OFF, (const char*)A + gb);                             \
            if (HAS_AL) cp16(d + AL_OFF, (const char*)AL + gb);                \
        }                                                                      \
        _Pragma("unroll") for (int i = 0; i < 4; i++) {                        \
            int cid = tid + i * NTH;                                           \
            int k = cid >> 5;                                                  \
            int cb = (cid & 31) * 16;                                          \
            size_t gb = (size_t)(k0 + k) * 512 + cb;                           \
            uint32_t d = base + k * 512 + (cb ^ ((k & 7) << 4));               \
            cp16(d + BH_OFF, (const char*)Bz + gb);                            \
        }                                                                      \
        asm volatile("cp.async.commit_group;" ::: "memory");                   \
    };                                                                         \
    auto compute_stage = [&](int s) {                                          \
        const uint32_t base = sb + s * STB;                                    \
        _Pragma("unroll") for (int kk = 0; kk < 2; kk++) {                     \
            uint32_t ah[2][4], al[2][4];                                       \
            _Pragma("unroll") for (int mi = 0; mi < 2; mi++) {                 \
                int row = wm * 32 + mi * 16 + (lane & 15);                     \
                uint32_t cb = kk * 32 + ((lane >> 4) << 4);                    \
                uint32_t ad = base + row * 64 + (cb ^ ((row & 3) << 4));       \
                ldsm4(ah[mi], ad + AH_OFF);                                    \
                if (HAS_AL) ldsm4(al[mi], ad + AL_OFF);                        \
            }                                                                  \
            const int kr = kk * 16 + (lane & 15);                              \
            const uint32_t hi16 = (lane >> 4) << 4;                            \
            uint32_t bhA[4], bhB[4];                                           \
            {                                                                  \
                uint32_t cb = wn * 256 + hi16;                                 \
                uint32_t bd = base + kr * 512 + (cb ^ ((kr & 7) << 4));        \
                ldsm4t(bhA, bd + BH_OFF);                                      \
            }                                                                  \
            _Pragma("unroll") for (int nj2 = 0; nj2 < 8; nj2++) {              \
                uint32_t* ch = (nj2 & 1) ? bhB : bhA;                          \
                if (nj2 < 7) {                                                 \
                    uint32_t* nh = (nj2 & 1) ? bhA : bhB;                      \
                    uint32_t cb = wn * 256 + (nj2 + 1) * 32 + hi16;            \
                    uint32_t bd = base + kr * 512 + (cb ^ ((kr & 7) << 4));    \
                    ldsm4t(nh, bd + BH_OFF);                                   \
                }                                                              \
                _Pragma("unroll") for (int mi = 0; mi < 2; mi++)               \
                _Pragma("unroll") for (int sub = 0; sub < 2; sub++) {          \
                    int nj = nj2 * 2 + sub;                                    \
                    mma16816(acc[mi][nj], ah[mi], &ch[sub * 2]);               \
                    if (HAS_AL) mma16816(acc[mi][nj], al[mi], &ch[sub * 2]);   \
                }                                                              \
            }                                                                  \
        }                                                                      \
    };                                                                         \
    for (int p = 0; p < 3 && p < nchunks; p++) load_stage(p, p * BK);          \
    {                                                                          \
        int cs = 0, ls = 3;                                                    \
        for (int c = 0; c < nchunks; c++) {                                    \
            if (c + 3 < nchunks) load_stage(ls, (c + 3) * BK);                 \
            else asm volatile("cp.async.commit_group;" ::: "memory");          \
            asm volatile("cp.async.wait_group 2;" ::: "memory");               \
            __syncthreads();                                                   \
            compute_stage(cs);                                                 \
            if (++cs == NSTAGE) cs = 0;                                        \
            if (++ls == NSTAGE) ls = 0;                                        \
        }                                                                      \
    }

// scalar epilogue
#define GEMM_EPI_SCALAR(P1, P2, SRC, DST, SBIAS, W2, B2, SOUT)                 \
    {                                                                          \
        float* sred = (float*)smem;                                            \
        _Pragma("unroll") for (int mi = 0; mi < 2; mi++)                       \
        _Pragma("unroll") for (int half = 0; half < 2; half++) {               \
            int rowl = wm * 32 + mi * 16 + half * 8 + (lane >> 2);             \
            int row = m0 + rowl;                                               \
            int cl = (row < M) ? row : (M - 1);                                \
            const __half* p1 = (P1) ? ((P1) + (size_t)(SRC)[cl] * 256) : nullptr;\
            const __half* p2 = (P2) ? ((P2) + (size_t)(DST)[cl] * 256) : nullptr;\
            float part = 0.f;                                                  \
            _Pragma("unroll") for (int nj = 0; nj < 16; nj++) {                \
                int col = wn * 128 + nj * 8 + (lane & 3) * 2;                  \
                float2 bv = *(const float2*)((SBIAS) + col);                   \
                float2 wv = *(const float2*)((W2) + col);                      \
                float2 p1v = make_float2(0.f, 0.f), p2v = make_float2(0.f, 0.f);\
                if (p1) p1v = __half22float2(*(const __half2*)(p1 + col));     \
                if (p2) p2v = __half22float2(*(const __half2*)(p2 + col));     \
                float v0 = fmaxf(acc[mi][nj][half * 2 + 0] + bv.x + p1v.x + p2v.x, 0.f);\
                float v1 = fmaxf(acc[mi][nj][half * 2 + 1] + bv.y + p1v.y + p2v.y, 0.f);\
                part = fmaf(v0, wv.x, part);                                   \
                part = fmaf(v1, wv.y, part);                                   \
            }                                                                  \
            part += __shfl_xor_sync(0xffffffffu, part, 1);                     \
            part += __shfl_xor_sync(0xffffffffu, part, 2);                     \
            if ((lane & 3) == 0) sred[rowl * 2 + wn] = part;                   \
        }                                                                      \
        __syncthreads();                                                       \
        if (tid < 128) {                                                       \
            int row = m0 + tid;                                                \
            if (row < M) (SOUT)[row] = sred[tid * 2] + sred[tid * 2 + 1] + (B2)[0];\
        }                                                                      \
    }

// ---------------- input projection GEMM (2-term exact-A) ----------------------
__global__ void __launch_bounds__(NTH, 1)
proj_gemm(const __half* __restrict__ A, const __half* __restrict__ AL,
          int M, int K, const __half* __restrict__ Bz,
          const float* __restrict__ bias, float* __restrict__ C,
          __half* __restrict__ ohh, __half* __restrict__ ohl)
{
    extern __shared__ char smem[];
    const uint32_t sb = smem_u32(smem);
    const int tid = threadIdx.x;
    const int lane = tid & 31;
    const int wid = tid >> 5;
    const int wm = wid & 3;
    const int wn = wid >> 2;
    const int m0 = blockIdx.x * BM;

    GEMM_MAINLOOP(true)

#pragma unroll
    for (int mi = 0; mi < 2; mi++) {
#pragma unroll
        for (int half = 0; half < 2; half++) {
            int row = m0 + wm * 32 + mi * 16 + half * 8 + (lane >> 2);
            if (row >= M) continue;
#pragma unroll
            for (int nj = 0; nj < 16; nj++) {
                int col = wn * 128 + nj * 8 + (lane & 3) * 2;
                float2 v;
                v.x = acc[mi][nj][half * 2 + 0] + bias[col];
                v.y = acc[mi][nj][half * 2 + 1] + bias[col + 1];
                *(float2*)(C + (size_t)row * 256 + col) = v;
                __half b0 = __float2half(v.x);
                __half b1 = __float2half(v.y);
                *(__half2*)(ohh + (size_t)row * 256 + col) = __half2(b0, b1);
                *(__half2*)(ohl + (size_t)row * 256 + col) =
                    __half2(__float2half(v.x - __half2float(b0)),
                            __float2half(v.y - __half2float(b1)));
            }
        }
    }
}

// ---------------- node GEMM: P1/P2 (1-term, fp16 out) --------------------------
__global__ void __launch_bounds__(NTH, 1)
node_gemm(const __half* __restrict__ A, int M, int K,
          const __half* __restrict__ Bh, __half* __restrict__ PC)
{
    extern __shared__ char smem[];
    const uint32_t sb = smem_u32(smem);
    const int tid = threadIdx.x;
    const int lane = tid & 31;
    const int wid = tid >> 5;
    const int wm = wid & 3;
    const int wn = wid >> 2;
    const int m0 = blockIdx.x * BM;
    const int z = blockIdx.z;
    const __half* AL = nullptr;
    const __half* Bz = Bh + (size_t)z * 65536;

    GEMM_MAINLOOP(false)

    __half* Pz = PC + (size_t)z * N_MAX * H;
#pragma unroll
    for (int mi = 0; mi < 2; mi++) {
#pragma unroll
        for (int half = 0; half < 2; half++) {
            int row = m0 + wm * 32 + mi * 16 + half * 8 + (lane >> 2);
            if (row >= M) continue;
#pragma unroll
            for (int nj = 0; nj < 16; nj++) {
                int col = wn * 128 + nj * 8 + (lane & 3) * 2;
                __half2 hp(__float2half(acc[mi][nj][half * 2 + 0]),
                           __float2half(acc[mi][nj][half * 2 + 1]));
                *(__half2*)(Pz + (size_t)row * 256 + col) = hp;
            }
        }
    }
}

// ---------------- edge + eps GEMM (1-term, flat 1D grid) -----------------------
__global__ void __launch_bounds__(NTH, 1)
edge_eps_gemm(const __half* __restrict__ Aedge, int E,
              const __half* __restrict__ Anode, int Nn, int nblkE,
              const __half* __restrict__ WhL,
              const float* __restrict__ a_b1, const float* __restrict__ a_w2,
              const float* __restrict__ a_b2, float* __restrict__ ae,
              const __half* __restrict__ P1, const __half* __restrict__ P2,
              const float* __restrict__ eps_b1, const float* __restrict__ eps_w2,
              const float* __restrict__ eps_b2, float* __restrict__ epsv)
{
    extern __shared__ char smem[];
    const uint32_t sb = smem_u32(smem);
    const int tid = threadIdx.x;
    const int lane = tid & 31;
    const int wid = tid >> 5;
    const int wm = wid & 3;
    const int wn = wid >> 2;
    const int bid = blockIdx.x;
    const int is_edge = (bid < nblkE);
    const int m0 = (is_edge ? bid : (bid - nblkE)) * BM;
    const int K = H;

    const __half* A = is_edge ? Aedge : Anode;
    const __half* AL = nullptr;
    const int M = is_edge ? E : Nn;
    const __half* Bz = WhL + (size_t)(is_edge ? 768 : 512) * 256;

    GEMM_MAINLOOP(false)

    if (is_edge) {
        GEMM_EPI_SCALAR(P1, P2, g_srcp, g_dstp, a_b1, a_w2, a_b2, ae)
    } else {
        GEMM_EPI_SCALAR((const __half*)nullptr, (const __half*)nullptr,
                        g_srcp, g_dstp, eps_b1, eps_w2, eps_b2, epsv)
    }
}

// ---------------- fused message + softmax + update (warp per node) -----------
// everything indexed in permuted (dst-sorted) order: ae[j], g_srcp[j], ghh row j
__global__ void msg_update(const float* __restrict__ ae,
                           const __half* __restrict__ ghh,
                           const __half* __restrict__ hh_r,
                           const float* __restrict__ h_old,
                           const float* __restrict__ epsv,
                           float* __restrict__ h_new,
                           __half* __restrict__ hh_w, __half* __restrict__ hl_w,
                           int N)
{
    const int w = (blockIdx.x * blockDim.x + threadIdx.x) >> 5;
    const int lane = threadIdx.x & 31;
    if (w >= N) return;
    const int lo = g_off[w], hi = g_off[w + 1];

    float acc8[8];
#pragma unroll
    for (int q = 0; q < 8; q++) acc8[q] = 0.f;
    float s = 0.f;

    if (hi > lo) {
        float mym = -INFINITY;
        for (int j = lo + lane; j < hi; j += 32)
            mym = fmaxf(mym, ae[j]);
#pragma unroll
        for (int o = 16; o; o >>= 1)
            mym = fmaxf(mym, __shfl_xor_sync(0xffffffffu, mym, o));
        const float m = mym;
        for (int base = lo; base < hi; base += 32) {
            const int j = base + lane;
            int sr = 0;
            float c = 0.f;
            if (j < hi) {
                c = __expf(ae[j] - m);
                sr = g_srcp[j];
            }
            s += c;
            const int cnt = min(32, hi - base);
            for (int i = 0; i < cnt; i++) {
                const float ci = __shfl_sync(0xffffffffu, c, i);
                const int si = __shfl_sync(0xffffffffu, sr, i);
                const int ji = base + i;
                const uint4 gv = *(const uint4*)(ghh + (size_t)ji * H + lane * 8);
                const uint4 hv16 = *(const uint4*)(hh_r + (size_t)si * H + lane * 8);
                float2 g0 = __half22float2(*(const __half2*)&gv.x);
                float2 g1 = __half22float2(*(const __half2*)&gv.y);
                float2 g2 = __half22float2(*(const __half2*)&gv.z);
                float2 g3 = __half22float2(*(const __half2*)&gv.w);
                float2 q0 = __half22float2(*(const __half2*)&hv16.x);
                float2 q1 = __half22float2(*(const __half2*)&hv16.y);
                float2 q2 = __half22float2(*(const __half2*)&hv16.z);
                float2 q3 = __half22float2(*(const __half2*)&hv16.w);
                acc8[0] = fmaf(ci * g0.x, q0.x, acc8[0]);
                acc8[1] = fmaf(ci * g0.y, q0.y, acc8[1]);
                acc8[2] = fmaf(ci * g1.x, q1.x, acc8[2]);
                acc8[3] = fmaf(ci * g1.y, q1.y, acc8[3]);
                acc8[4] = fmaf(ci * g2.x, q2.x, acc8[4]);
                acc8[5] = fmaf(ci * g2.y, q2.y, acc8[5]);
                acc8[6] = fmaf(ci * g3.x, q3.x, acc8[6]);
                acc8[7] = fmaf(ci * g3.y, q3.y, acc8[7]);
            }
        }
#pragma unroll
        for (int o = 16; o; o >>= 1)
            s += __shfl_xor_sync(0xffffffffu, s, o);
    }

    const float inv = (s > 0.f) ? (1.f / s) : 0.f;
    const float scale = (1.f + epsv[w]) * inv;

    const float4* hrow = (const float4*)(h_old + (size_t)w * H + lane * 8);
    float4 o0 = hrow[0], o1 = hrow[1];
    float4 r0, r1;
    r0.x = fmaf(acc8[0], scale, o0.x); r0.y = fmaf(acc8[1], scale, o0.y);
    r0.z = fmaf(acc8[2], scale, o0.z); r0.w = fmaf(acc8[3], scale, o0.w);
    r1.x = fmaf(acc8[4], scale, o1.x); r1.y = fmaf(acc8[5], scale, o1.y);
    r1.z = fmaf(acc8[6], scale, o1.z); r1.w = fmaf(acc8[7], scale, o1.w);
    float4* orow = (float4*)(h_new + (size_t)w * H + lane * 8);
    orow[0] = r0;
    orow[1] = r1;

    __half2 hp[4], lp[4];
    float vv[8] = {r0.x, r0.y, r0.z, r0.w, r1.x, r1.y, r1.z, r1.w};
#pragma unroll
    for (int q = 0; q < 4; q++) {
        __half b0 = __float2half(vv[q * 2]);
        __half b1 = __float2half(vv[q * 2 + 1]);
        hp[q] = __half2(b0, b1);
        lp[q] = __half2(__float2half(vv[q * 2] - __half2float(b0)),
                        __float2half(vv[q * 2 + 1] - __half2float(b1)));
    }
    *(uint4*)(hh_w + (size_t)w * H + lane * 8) = *(uint4*)hp;
    *(uint4*)(hl_w + (size_t)w * H + lane * 8) = *(uint4*)lp;
}

// ---------------- launch -------------------------------------------------------
extern "C" void kernel_launch(void* const* d_in, const int* in_sizes, int n_in,
                              void* d_out, int out_size)
{
    (void)n_in; (void)out_size;
    const float* node_feats = (const float*)d_in[0];
    const float* gh         = (const float*)d_in[1];
    const int*   src        = (const int*)d_in[2];
    const int*   dst        = (const int*)d_in[3];
    const float* Wn_w       = (const float*)d_in[4];
    const float* Wn_b       = (const float*)d_in[5];
    const float* eps_w1     = (const float*)d_in[6];
    const float* eps_b1     = (const float*)d_in[7];
    const float* eps_w2     = (const float*)d_in[8];
    const float* eps_b2     = (const float*)d_in[9];
    const float* a_w1       = (const float*)d_in[10];
    const float* a_b1       = (const float*)d_in[11];
    const float* a_w2       = (const float*)d_in[12];
    const float* a_b2       = (const float*)d_in[13];

    const int D_IN = 128;
    const int N = in_sizes[0] / D_IN;
    const int E = in_sizes[2];
    const int L = in_sizes[6] / (H * H);

    float* out = (float*)d_out;

    __half *ghh, *nfh, *nfl, *hh0, *hl0, *Wh, *wnh, *gP;
    float *epsv, *ae;
    cudaGetSymbolAddress((void**)&ghh, g_ghh);
    cudaGetSymbolAddress((void**)&nfh, g_nfh);
    cudaGetSymbolAddress((void**)&nfl, g_nfl);
    cudaGetSymbolAddress((void**)&hh0, g_hh);
    cudaGetSymbolAddress((void**)&hl0, g_hl);
    cudaGetSymbolAddress((void**)&Wh,  g_Wh);
    cudaGetSymbolAddress((void**)&wnh, g_wnh);
    cudaGetSymbolAddress((void**)&gP,   g_P);
    cudaGetSymbolAddress((void**)&epsv, g_eps);
    cudaGetSymbolAddress((void**)&ae,   g_ae);

    constexpr int SMEM2 = NSTAGE * (16384 + 16384);   // 2-term (proj) = 160KB
    constexpr int SMEM1 = NSTAGE * (8192 + 16384);    // 1-term = 120KB
    cudaFuncSetAttribute(proj_gemm, cudaFuncAttributeMaxDynamicSharedMemorySize, SMEM2);
    cudaFuncSetAttribute(node_gemm, cudaFuncAttributeMaxDynamicSharedMemorySize, SMEM1);
    cudaFuncSetAttribute(edge_eps_gemm, cudaFuncAttributeMaxDynamicSharedMemorySize, SMEM1);

    // one-time prep: weights+clear, nf cvt+hist, scan, scatter, gh cvt (permuted)
    {
        int totw = L * 1024 * 256 + 128 * 256;
        prep_w<<<(totw + 255) / 256, 256>>>(a_w1, eps_w1, Wn_w, L, N);
        int n4 = (N * D_IN) / 4;
        int thr = (n4 > E) ? n4 : E;
        cvt_nf_hist<<<(thr + 255) / 256, 256>>>(node_feats, nfh, nfl, n4, dst, E);
        csr_scan<<<1, 1024>>>(N, E);
        csr_scatter<<<(E + 255) / 256, 256>>>(src, dst, E);
        int g4 = (E * H) / 4;
        cvt_gh_perm<<<(g4 + 255) / 256, 256>>>(gh, ghh, g4);
    }

    const int nblkN = (N + BM - 1) / BM;
    const int nblkE = (E + BM - 1) / BM;
    const size_t hbuf = (size_t)N_MAX * H;

    // input projection -> out[0:N*H] fp32 (+ fp16 split into buffer 0)
    proj_gemm<<<dim3(nblkN, 1, 1), NTH, SMEM2>>>(
        nfh, nfl, N, D_IN, wnh, Wn_b, out, hh0, hl0);

    for (int l = 0; l < L; l++) {
        const float* hcur = out + (size_t)l * N * H;
        float*       hnext = out + (size_t)(l + 1) * N * H;
        const __half* WhL = Wh + (size_t)l * 1024 * 256;
        __half* hhr = hh0 + (size_t)(l & 1) * hbuf;
        __half* hhw = hh0 + (size_t)((l + 1) & 1) * hbuf;
        __half* hlw = hl0 + (size_t)((l + 1) & 1) * hbuf;

        // P1/P2 (1-term, fp16 out)
        node_gemm<<<dim3(nblkN, 1, 2), NTH, SMEM1>>>(hhr, N, H, WhL, gP);

        // edge scores (permuted order) + eps in one flat launch
        edge_eps_gemm<<<dim3(nblkE + nblkN, 1, 1), NTH, SMEM1>>>(
            ghh, E, hhr, N, nblkE, WhL,
            a_b1 + (size_t)l * H, a_w2 + (size_t)l * H, a_b2 + l, ae,
            gP, gP + hbuf,
            eps_b1 + (size_t)l * H, eps_w2 + (size_t)l * H, eps_b2 + l, epsv);

        // fused message + softmax + GIN update (+ fp16 split of h_next)
        msg_update<<<(N * 32 + 255) / 256, 256>>>(
            ae, ghh, hhr, hcur, epsv, hnext, hhw, hlw, N);
    }
}